// round 10
// baseline (speedup 1.0000x reference)
#include <cuda_runtime.h>
#include <cuda_bf16.h>
#include <mma.h>
#include <cstdint>
#include <math.h>

using namespace nvcuda;

#define BB 4
#define TT 168
#define BT 672
#define DD 4096
#define HH 4
#define HDIM 1024
#define DFF 16384

#define OFFQ  0ul
#define OFFK  16777216ul
#define OFFV  33554432ul
#define OFFO  50331648ul
#define WTOT  67108864ul

__device__ __nv_bfloat16 g_whi[WTOT];
__device__ __nv_bfloat16 g_wlo[WTOT];
__device__ float g_w1t[67108864];   // W1^T [16384,4096] fp32
__device__ float g_w2t[67108864];   // W2^T [4096,16384] fp32

__device__ float g_To[768], g_Td[768];
__device__ float g_Wos2[4096], g_Wds2[4096], g_bos2[16], g_bds2[16];
__device__ float g_x[BT * DD];
__device__ float g_xm[BT];
__device__ float g_q[BT * DD], g_k[BT * DD], g_v[BT * DD];
__device__ float g_y[BT * DD];
__device__ float g_f[(size_t)BT * DFF];
__device__ int   g_periods[BB * HH];
__device__ __nv_bfloat16 g_xnh[BT * DD], g_xnl[BT * DD];
__device__ __nv_bfloat16 g_aoh[BT * DD], g_aol[BT * DD];

__device__ __forceinline__ float blockReduceSum(float v, float* red) {
    int tid = threadIdx.x;
    #pragma unroll
    for (int o = 16; o > 0; o >>= 1) v += __shfl_xor_sync(0xffffffffu, v, o);
    if ((tid & 31) == 0) red[tid >> 5] = v;
    __syncthreads();
    if (tid < 32) {
        float t = (tid < 8) ? red[tid] : 0.0f;
        #pragma unroll
        for (int o = 4; o > 0; o >>= 1) t += __shfl_xor_sync(0xffffffffu, t, o);
        if (tid == 0) red[0] = t;
    }
    __syncthreads();
    float r = red[0];
    __syncthreads();
    return r;
}

__device__ __forceinline__ void split_bf16(float v, __nv_bfloat16& h, __nv_bfloat16& l) {
    h = __float2bfloat16(v);
    l = __float2bfloat16(v - __bfloat162float(h));
}

__device__ __forceinline__ void cpa16(uint32_t dst, const void* src, int srcsz) {
    asm volatile("cp.async.cg.shared.global [%0], [%1], 16, %2;"
                 :: "r"(dst), "l"(src), "r"(srcsz) : "memory");
}
__device__ __forceinline__ void cpa_commit() { asm volatile("cp.async.commit_group;" ::: "memory"); }
template<int N>
__device__ __forceinline__ void cpa_wait() { asm volatile("cp.async.wait_group %0;" :: "n"(N) : "memory"); }

// ---------------- weight convert ----------------
// QKV/O: bf16 hi/lo [N,K] (fast 128x32 tiles).  W1/W2: fp32 transpose.
__global__ void __launch_bounds__(256) convert_all_kernel(
    const float* __restrict__ Wq, const float* __restrict__ Wk,
    const float* __restrict__ Wv, const float* __restrict__ Wo,
    const float* __restrict__ W1, const float* __restrict__ W2)
{
    int bid = blockIdx.x;
    int tid = threadIdx.x;
    if (bid < 16384) {
        __shared__ float s[128][33];
        int w = bid >> 12, t = bid & 4095;
        const float* W = (w == 0) ? Wq : (w == 1) ? Wk : (w == 2) ? Wv : Wo;
        size_t off = (size_t)w * 16777216ul;
        int bx = t & 127, by = t >> 7;
        int k0 = by * 128, n0 = bx * 32;
        {
            int n = tid & 31, kb = tid >> 5;
            #pragma unroll
            for (int r = 0; r < 16; r++) {
                int k = r * 8 + kb;
                s[k][n] = W[(size_t)(k0 + k) * 4096 + n0 + n];
            }
        }
        __syncthreads();
        {
            int n = tid >> 3;
            int kc = (tid & 7) * 16;
            __nv_bfloat16 hb[16], lb[16];
            #pragma unroll
            for (int j = 0; j < 16; j++) split_bf16(s[kc + j][n], hb[j], lb[j]);
            size_t o = off + (size_t)(n0 + n) * 4096 + k0 + kc;
            #pragma unroll
            for (int u = 0; u < 2; u++) {
                uint4 ph, pl;
                uint32_t* pph = (uint32_t*)&ph;
                uint32_t* ppl = (uint32_t*)&pl;
                #pragma unroll
                for (int c = 0; c < 4; c++) {
                    int j = u * 8 + c * 2;
                    pph[c] = ((uint32_t)__bfloat16_as_ushort(hb[j+1]) << 16) | __bfloat16_as_ushort(hb[j]);
                    ppl[c] = ((uint32_t)__bfloat16_as_ushort(lb[j+1]) << 16) | __bfloat16_as_ushort(lb[j]);
                }
                *(uint4*)(g_whi + o + u * 8) = ph;
                *(uint4*)(g_wlo + o + u * 8) = pl;
            }
        }
    } else {
        __shared__ float s[32][33];
        const float* W; float* Wt; int K, N; int bx, by;
        if (bid < 81920) {
            int t = bid - 16384;
            W = W1; Wt = g_w1t; K = 4096; N = 16384;
            bx = t & 511; by = t >> 9;        // 512 n-blocks, 128 k-blocks
        } else {
            int t = bid - 81920;
            W = W2; Wt = g_w2t; K = 16384; N = 4096;
            bx = t & 127; by = t >> 7;        // 128 n-blocks, 512 k-blocks
        }
        int k0 = by * 32, n0 = bx * 32;
        int r = tid >> 5, c = tid & 31;
        #pragma unroll
        for (int i = 0; i < 4; i++)
            s[r + 8 * i][c] = W[(size_t)(k0 + r + 8 * i) * N + n0 + c];
        __syncthreads();
        #pragma unroll
        for (int i = 0; i < 4; i++) {
            int n = r + 8 * i;
            Wt[(size_t)(n0 + n) * K + k0 + c] = s[c][n];
        }
    }
}

// ---------------- bf16 split GEMM, tile 128x128, 2-stage, 2 CTA/SM (R8 config) ----------------
#define PAD 40
#define ST_AL (128 * PAD)
#define ST_BH (2 * 128 * PAD)
#define ST_BL (3 * 128 * PAD)
#define ST_ELE (4 * 128 * PAD)
#define ST_BYT (ST_ELE * 2)
#define G_SMEM (2 * ST_BYT)

__device__ __forceinline__ void issue_stage(
    uint32_t sb,
    const __nv_bfloat16* __restrict__ Ah, const __nv_bfloat16* __restrict__ Al,
    const __nv_bfloat16* __restrict__ Bh, const __nv_bfloat16* __restrict__ Bl,
    int bm, int bn, int k0, int K, int Mr, int tid)
{
    #pragma unroll
    for (int t = 0; t < 2; t++) {
        int u = tid + t * 256;
        int row = u >> 2, q = u & 3;
        int m = bm + row;
        int ok = (m < Mr) ? 16 : 0;
        size_t g = (size_t)(m < Mr ? m : 0) * K + k0 + q * 8;
        cpa16(sb + (0     + row * PAD + q * 8) * 2, Ah + g, ok);
        cpa16(sb + (ST_AL + row * PAD + q * 8) * 2, Al + g, ok);
        size_t gb = (size_t)(bn + row) * K + k0 + q * 8;
        cpa16(sb + (ST_BH + row * PAD + q * 8) * 2, Bh + gb, 16);
        cpa16(sb + (ST_BL + row * PAD + q * 8) * 2, Bl + gb, 16);
    }
}

__device__ __forceinline__ void gemm_body(
    const __nv_bfloat16* __restrict__ Ah, const __nv_bfloat16* __restrict__ Al,
    const __nv_bfloat16* __restrict__ Bh, const __nv_bfloat16* __restrict__ Bl,
    const float* __restrict__ bias, const float* __restrict__ res,
    float* __restrict__ C, int Mr, int Nc, int K, int EPI)
{
    extern __shared__ char dsm[];
    uint32_t sbase = (uint32_t)__cvta_generic_to_shared(dsm);
    __nv_bfloat16* sm = (__nv_bfloat16*)dsm;

    int tid = threadIdx.x, wid = tid >> 5, lane = tid & 31;
    int bm = blockIdx.x * 128, bn = blockIdx.y * 128;
    int wm = (wid >> 2) * 64, wn = (wid & 3) * 32;

    wmma::fragment<wmma::accumulator, 16, 16, 16, float> acc[4][2];
    #pragma unroll
    for (int i = 0; i < 4; i++)
        #pragma unroll
        for (int j = 0; j < 2; j++) wmma::fill_fragment(acc[i][j], 0.0f);

    int KC = K >> 5;
    issue_stage(sbase, Ah, Al, Bh, Bl, bm, bn, 0, K, Mr, tid);
    cpa_commit();

    for (int kc = 0; kc < KC; kc++) {
        int cur = kc & 1;
        if (kc + 1 < KC) {
            issue_stage(sbase + ((kc + 1) & 1) * ST_BYT, Ah, Al, Bh, Bl,
                        bm, bn, (kc + 1) * 32, K, Mr, tid);
            cpa_commit();
            cpa_wait<1>();
        } else {
            cpa_wait<0>();
        }
        __syncthreads();
        const __nv_bfloat16* S = sm + cur * ST_ELE;
        #pragma unroll
        for (int kk = 0; kk < 32; kk += 16) {
            wmma::fragment<wmma::matrix_b, 16, 16, 16, __nv_bfloat16, wmma::col_major> fbh[2], fbl[2];
            #pragma unroll
            for (int j = 0; j < 2; j++) {
                wmma::load_matrix_sync(fbh[j], S + ST_BH + (wn + 16 * j) * PAD + kk, PAD);
                wmma::load_matrix_sync(fbl[j], S + ST_BL + (wn + 16 * j) * PAD + kk, PAD);
            }
            #pragma unroll
            for (int i = 0; i < 4; i++) {
                wmma::fragment<wmma::matrix_a, 16, 16, 16, __nv_bfloat16, wmma::row_major> fah, fal;
                wmma::load_matrix_sync(fah, S + 0     + (wm + 16 * i) * PAD + kk, PAD);
                wmma::load_matrix_sync(fal, S + ST_AL + (wm + 16 * i) * PAD + kk, PAD);
                #pragma unroll
                for (int j = 0; j < 2; j++) {
                    wmma::mma_sync(acc[i][j], fah, fbh[j], acc[i][j]);
                    wmma::mma_sync(acc[i][j], fah, fbl[j], acc[i][j]);
                    wmma::mma_sync(acc[i][j], fal, fbh[j], acc[i][j]);
                }
            }
        }
        __syncthreads();
    }

    float* fst = (float*)dsm + wid * 256;
    int r = lane >> 1, cs = (lane & 1) * 8;
    #pragma unroll
    for (int i = 0; i < 4; i++)
        #pragma unroll
        for (int j = 0; j < 2; j++) {
            wmma::store_matrix_sync(fst, acc[i][j], 16, wmma::mem_row_major);
            __syncwarp();
            int m = bm + wm + 16 * i + r;
            int col0 = bn + wn + 16 * j + cs;
            if (m < Mr) {
                float v[8];
                #pragma unroll
                for (int c = 0; c < 8; c++) v[c] = fst[r * 16 + cs + c] + bias[col0 + c];
                if (EPI == 1) {
                    const float* rp = res + (size_t)m * Nc + col0;
                    #pragma unroll
                    for (int c = 0; c < 8; c++) v[c] += rp[c];
                }
                float4 o0, o1;
                o0.x = v[0]; o0.y = v[1]; o0.z = v[2]; o0.w = v[3];
                o1.x = v[4]; o1.y = v[5]; o1.z = v[6]; o1.w = v[7];
                *(float4*)(C + (size_t)m * Nc + col0) = o0;
                *(float4*)(C + (size_t)m * Nc + col0 + 4) = o1;
            }
            __syncwarp();
        }
}

__global__ void __launch_bounds__(256, 2) gemm_wmma(
    const __nv_bfloat16* Ah, const __nv_bfloat16* Al,
    const __nv_bfloat16* Bh, const __nv_bfloat16* Bl,
    const float* bias, const float* res, float* C,
    int Mr, int Nc, int K, int EPI)
{
    gemm_body(Ah, Al, Bh, Bl, bias, res, C, Mr, Nc, K, EPI);
}

__global__ void __launch_bounds__(256, 2) gemm_wmma_qkv(
    const __nv_bfloat16* Ah, const __nv_bfloat16* Al,
    const __nv_bfloat16* whi, const __nv_bfloat16* wlo,
    const float* bq, const float* bk, const float* bv,
    float* q, float* k, float* v)
{
    int z = blockIdx.z;
    size_t off = (size_t)z * 16777216ul;
    const float* bias = (z == 0) ? bq : (z == 1) ? bk : bv;
    float* C = (z == 0) ? q : (z == 1) ? k : v;
    gemm_body(Ah, Al, whi + off, wlo + off, bias, (const float*)0, C, BT, DD, DD, 0);
}

// ---------------- tf32 single-pass GEMM (FFN), tile 128x128, k-chunk 32 ----------------
#define PADF 36
#define TF_A (128 * PADF)
#define TF_ELE (2 * 128 * PADF)
#define TF_BYT (TF_ELE * 4)
#define TF_SMEM (2 * TF_BYT)

__device__ __forceinline__ void issue_stage_tf(
    uint32_t sb, const float* __restrict__ A, const float* __restrict__ B,
    int bm, int bn, int k0, int K, int Mr, int tid)
{
    #pragma unroll
    for (int t = 0; t < 4; t++) {
        int u = tid + t * 256;
        int row = u >> 3, q = u & 7;
        int m = bm + row;
        int ok = (m < Mr) ? 16 : 0;
        size_t g = (size_t)(m < Mr ? m : 0) * K + k0 + q * 4;
        cpa16(sb + (row * PADF + q * 4) * 4, A + g, ok);
        size_t gb = (size_t)(bn + row) * K + k0 + q * 4;
        cpa16(sb + (TF_A + row * PADF + q * 4) * 4, B + gb, 16);
    }
}

// EPI: 1 = bias+res, 2 = gelu(bias)
__global__ void __launch_bounds__(256, 2) gemm_tf32(
    const float* __restrict__ A, const float* __restrict__ B,
    const float* __restrict__ bias, const float* __restrict__ res,
    float* __restrict__ C, int Mr, int Nc, int K, int EPI)
{
    extern __shared__ char dsm[];
    uint32_t sbase = (uint32_t)__cvta_generic_to_shared(dsm);
    float* sm = (float*)dsm;

    int tid = threadIdx.x, wid = tid >> 5, lane = tid & 31;
    int bm = blockIdx.x * 128, bn = blockIdx.y * 128;
    int wm = (wid >> 2) * 64, wn = (wid & 3) * 32;

    wmma::fragment<wmma::accumulator, 16, 16, 8, float> acc[4][2];
    #pragma unroll
    for (int i = 0; i < 4; i++)
        #pragma unroll
        for (int j = 0; j < 2; j++) wmma::fill_fragment(acc[i][j], 0.0f);

    int KC = K >> 5;
    issue_stage_tf(sbase, A, B, bm, bn, 0, K, Mr, tid);
    cpa_commit();

    for (int kc = 0; kc < KC; kc++) {
        int cur = kc & 1;
        if (kc + 1 < KC) {
            issue_stage_tf(sbase + ((kc + 1) & 1) * TF_BYT, A, B, bm, bn, (kc + 1) * 32, K, Mr, tid);
            cpa_commit();
            cpa_wait<1>();
        } else {
            cpa_wait<0>();
        }
        __syncthreads();
        const float* S = sm + cur * TF_ELE;
        #pragma unroll
        for (int kk = 0; kk < 32; kk += 8) {
            wmma::fragment<wmma::matrix_b, 16, 16, 8, wmma::precision::tf32, wmma::col_major> fb[2];
            #pragma unroll
            for (int j = 0; j < 2; j++) {
                wmma::load_matrix_sync(fb[j], S + TF_A + (wn + 16 * j) * PADF + kk, PADF);
                #pragma unroll
                for (int t = 0; t < fb[j].num_elements; t++)
                    fb[j].x[t] = wmma::__float_to_tf32(fb[j].x[t]);
            }
            #pragma unroll
            for (int i = 0; i < 4; i++) {
                wmma::fragment<wmma::matrix_a, 16, 16, 8, wmma::precision::tf32, wmma::row_major> fa;
                wmma::load_matrix_sync(fa, S + (wm + 16 * i) * PADF + kk, PADF);
                #pragma unroll
                for (int t = 0; t < fa.num_elements; t++)
                    fa.x[t] = wmma::__float_to_tf32(fa.x[t]);
                #pragma unroll
                for (int j = 0; j < 2; j++)
                    wmma::mma_sync(acc[i][j], fa, fb[j], acc[i][j]);
            }
        }
        __syncthreads();
    }

    float* fst = (float*)dsm + wid * 256;
    int r = lane >> 1, cs = (lane & 1) * 8;
    #pragma unroll
    for (int i = 0; i < 4; i++)
        #pragma unroll
        for (int j = 0; j < 2; j++) {
            wmma::store_matrix_sync(fst, acc[i][j], 16, wmma::mem_row_major);
            __syncwarp();
            int m = bm + wm + 16 * i + r;
            int col0 = bn + wn + 16 * j + cs;
            if (m < Mr) {
                float v[8];
                #pragma unroll
                for (int c = 0; c < 8; c++) v[c] = fst[r * 16 + cs + c] + bias[col0 + c];
                if (EPI == 1) {
                    const float* rp = res + (size_t)m * Nc + col0;
                    #pragma unroll
                    for (int c = 0; c < 8; c++) v[c] += rp[c];
                }
                if (EPI == 2) {
                    #pragma unroll
                    for (int c = 0; c < 8; c++)
                        v[c] = 0.5f * v[c] * (1.0f + erff(v[c] * 0.7071067811865475f));
                }
                float4 o0, o1;
                o0.x = v[0]; o0.y = v[1]; o0.z = v[2]; o0.w = v[3];
                o1.x = v[4]; o1.y = v[5]; o1.z = v[6]; o1.w = v[7];
                *(float4*)(C + (size_t)m * Nc + col0) = o0;
                *(float4*)(C + (size_t)m * Nc + col0 + 4) = o1;
            }
            __syncwarp();
        }
}

// ---------------- merged prep ----------------
__global__ void prep_kernel(const float* __restrict__ Lo, const float* __restrict__ Ld,
                            const float* __restrict__ Wop, const float* __restrict__ bop,
                            const float* __restrict__ Wos, const float* __restrict__ bos,
                            const float* __restrict__ Wdp, const float* __restrict__ bdp,
                            const float* __restrict__ Wds, const float* __restrict__ bds) {
    int tid = threadIdx.x;
    if (blockIdx.x == 0) {
        int i = tid >> 4, j = tid & 15;
        float id = (i == j) ? 1.0f : 0.0f;
        float a = 0.f, b = 0.f;
        for (int k = 0; k < 16; k++) { a += Lo[i*16+k]*Lo[k*16+j]; b += Ld[i*16+k]*Ld[k*16+j]; }
        g_To[tid] = id; g_To[256+tid] = Lo[tid]; g_To[512+tid] = 2.f*a - id;
        g_Td[tid] = id; g_Td[256+tid] = Ld[tid]; g_Td[512+tid] = 2.f*b - id;
    }
    int idx = blockIdx.x * 256 + tid;
    int kf = idx >> 4, n = idx & 15;
    float a = 0.f, b = 0.f;
    for (int h = 0; h < 512; h++) {
        a += Wop[kf*512+h] * Wos[h*16+n];
        b += Wdp[kf*512+h] * Wds[h*16+n];
    }
    g_Wos2[idx] = a; g_Wds2[idx] = b;
    if (idx < 16) {
        float c = bos[idx], d = bds[idx];
        for (int h = 0; h < 512; h++) { c += bop[h]*Wos[h*16+idx]; d += bdp[h]*Wds[h*16+idx]; }
        g_bos2[idx] = c; g_bds2[idx] = d;
    }
}

// ---------------- GCN + OD + combine + fused LayerNorm1 ----------------
__global__ void __launch_bounds__(256) gcnod_kernel(const float* __restrict__ M,
                                                    const float* __restrict__ theta,
                                                    const float* __restrict__ g1,
                                                    const float* __restrict__ be1) {
    __shared__ float sM[4096], sR[4096], sTh[2304];
    __shared__ float sScore[256], sPo[256], sPd[256], st2[512];
    __shared__ float sEnt[16], sRed[8];
    __shared__ int   sSel[4];
    int bt = blockIdx.x, tid = threadIdx.x;
    const float* Mp = M + (size_t)bt * 4096;
    for (int o = tid; o < 4096; o += 256) sM[o] = Mp[o];
    for (int o = tid; o < 2304; o += 256) sTh[o] = theta[o];
    __syncthreads();
    {
        int i = tid >> 4, n = tid & 15;
        const float* xr = sM + i * 256;
        float a = g_bos2[n];
        for (int kf = 0; kf < 256; kf++) a += xr[kf] * g_Wos2[kf*16+n];
        sScore[tid] = a;
    }
    __syncthreads();
    if (tid < 16) {
        float mx = -1e30f;
        #pragma unroll
        for (int n = 0; n < 16; n++) mx = fmaxf(mx, sScore[tid*16+n]);
        float e[16], s = 0.f;
        #pragma unroll
        for (int n = 0; n < 16; n++) { e[n] = expf(sScore[tid*16+n]-mx); s += e[n]; }
        float inv = 1.f/s, ent = 0.f;
        #pragma unroll
        for (int n = 0; n < 16; n++) { float p = e[n]*inv; sPo[tid*16+n]=p; ent -= p*logf(p+1e-9f); }
        sEnt[tid] = ent;
    }
    __syncthreads();
    if (tid == 0) {
        int i0 = 0;
        for (int t = 1; t < 16; t++) if (sEnt[t] < sEnt[i0]) i0 = t;
        int i1 = (i0 == 0) ? 1 : 0;
        for (int t = 0; t < 16; t++) { if (t == i0) continue; if (sEnt[t] < sEnt[i1]) i1 = t; }
        sSel[0] = i0; sSel[1] = i1;
    }
    {
        int k = tid >> 4, n = tid & 15;
        float a = g_bds2[n];
        for (int jf = 0; jf < 256; jf++)
            a += sM[(jf>>4)*256 + k*16 + (jf&15)] * g_Wds2[jf*16+n];
        __syncthreads();
        sScore[tid] = a;
    }
    __syncthreads();
    if (tid < 16) {
        float mx = -1e30f;
        #pragma unroll
        for (int n = 0; n < 16; n++) mx = fmaxf(mx, sScore[tid*16+n]);
        float e[16], s = 0.f;
        #pragma unroll
        for (int n = 0; n < 16; n++) { e[n] = expf(sScore[tid*16+n]-mx); s += e[n]; }
        float inv = 1.f/s, ent = 0.f;
        #pragma unroll
        for (int n = 0; n < 16; n++) { float p = e[n]*inv; sPd[tid*16+n]=p; ent -= p*logf(p+1e-9f); }
        sEnt[tid] = ent;
    }
    __syncthreads();
    if (tid == 0) {
        int i0 = 0;
        for (int t = 1; t < 16; t++) if (sEnt[t] < sEnt[i0]) i0 = t;
        int i1 = (i0 == 0) ? 1 : 0;
        for (int t = 0; t < 16; t++) { if (t == i0) continue; if (sEnt[t] < sEnt[i1]) i1 = t; }
        sSel[2] = i0; sSel[3] = i1;
    }
    __syncthreads();
    {
        #pragma unroll
        for (int s = 0; s < 2; s++) {
            int ii = sSel[s];
            float a = 0.f;
            for (int j = 0; j < 16; j++) a += sPo[ii*16+j] * sM[j*256 + tid];
            st2[s*256 + tid] = a;
        }
    }
    __syncthreads();
    int gi = tid & 15, gl = tid >> 4;
    float MG[16];
    #pragma unroll
    for (int g = 0; g < 16; g++) MG[g] = 0.f;
    for (int c = 0; c < 3; c++) {
        for (int r = 0; r < 16; r++) {
            int ll = tid >> 4, f = tid & 15;
            float a = 0.f;
            #pragma unroll
            for (int k = 0; k < 16; k++)
                a += sM[(r<<8)+(k<<4)+f] * g_Td[c*256 + (k<<4) + ll];
            sR[(r<<8) + tid] = a;
        }
        __syncthreads();
        for (int a_ = 0; a_ < 3; a_++) {
            float S[16];
            #pragma unroll
            for (int f = 0; f < 16; f++) S[f] = 0.f;
            for (int j = 0; j < 16; j++) {
                float t_ = g_To[a_*256 + (gi<<4) + j];
                const float* rp = sR + (j<<8) + (gl<<4);
                #pragma unroll
                for (int f = 0; f < 16; f++) S[f] += t_ * rp[f];
            }
            const float* th = sTh + (a_*3 + c) * 256;
            #pragma unroll
            for (int f = 0; f < 16; f++) {
                float sv = S[f];
                #pragma unroll
                for (int g = 0; g < 16; g++) MG[g] += sv * th[f*16+g];
            }
        }
        __syncthreads();
    }
    int so = (gi == sSel[0]) ? 0 : ((gi == sSel[1]) ? 1 : -1);
    int sd = (gl == sSel[2]) ? 0 : ((gl == sSel[3]) ? 1 : -1);
    float v[16];
    float lsum = 0.f, lsq = 0.f;
    #pragma unroll
    for (int g = 0; g < 16; g++) {
        float w = 0.5f * MG[g];
        if (so >= 0 && sd >= 0) {
            float ma = 0.f;
            #pragma unroll
            for (int ll = 0; ll < 16; ll++)
                ma += st2[so*256 + g*16 + ll] * sPd[gl*16 + ll];
            w += 0.5f * ma;
        }
        v[g] = w;
        lsum += w;
        lsq += w * w;
    }
    float tot = blockReduceSum(lsum, sRed);
    float sqt = blockReduceSum(lsq, sRed);
    float mu = tot * (1.0f/4096.0f);
    float var = sqt * (1.0f/4096.0f) - mu * mu;
    float rstd = rsqrtf(var + 1e-5f);
    size_t base = (size_t)bt*4096 + gi*256 + gl*16;
    float* xp = g_x + base;
    __nv_bfloat16* xh = g_xnh + base;
    __nv_bfloat16* xl = g_xnl + base;
    #pragma unroll
    for (int g = 0; g < 16; g++) {
        xp[g] = v[g];
        float xn = (v[g] - mu) * rstd * g1[gi*256 + gl*16 + g] + be1[gi*256 + gl*16 + g];
        __nv_bfloat16 h, l; split_bf16(xn, h, l);
        xh[g] = h; xl[g] = l;
    }
    if (tid == 0) g_xm[bt] = mu;
}

__global__ void period_kernel() {
    __shared__ float sx[168], sd[168], sac[168];
    __shared__ float smean;
    int b = blockIdx.x, tid = threadIdx.x;
    if (tid < 168) sx[tid] = g_xm[b*168 + tid];
    __syncthreads();
    if (tid < 168) {
        float s = 0.f;
        #pragma unroll
        for (int o = -12; o <= 12; o++) {
            int u = tid + o; u = u < 0 ? 0 : (u > 167 ? 167 : u);
            s += sx[u];
        }
        sd[tid] = sx[tid] - s * (1.0f/25.0f);
    }
    __syncthreads();
    if (tid == 0) {
        float s = 0.f;
        for (int t = 0; t < 168; t++) s += sd[t];
        smean = s / 168.0f;
    }
    __syncthreads();
    if (tid < 168) sd[tid] -= smean;
    __syncthreads();
    if (tid < 168) {
        float a = 0.f;
        for (int t = 0; t + tid < 168; t++) a += sd[t] * sd[t + tid];
        sac[tid] = (tid < 2) ? -1e9f : a;
    }
    __syncthreads();
    if (tid == 0) {
        bool used[168];
        for (int t = 0; t < 168; t++) used[t] = false;
        for (int r = 0; r < 4; r++) {
            int bi = 0; float bv = -1e30f;
            for (int t = 0; t < 168; t++)
                if (!used[t] && sac[t] > bv) { bv = sac[t]; bi = t; }
            used[bi] = true;
            g_periods[b*4 + r] = bi;
        }
    }
}

// LayerNorm2: fp32 in -> fp32 out
__global__ void __launch_bounds__(256) ln_kernel(const float* __restrict__ x,
                                                 const float* __restrict__ gw,
                                                 const float* __restrict__ bw,
                                                 float* __restrict__ out) {
    __shared__ float srow[DD];
    __shared__ float red[8];
    int row = blockIdx.x, tid = threadIdx.x;
    const float* xp = x + (size_t)row * DD;
    float s = 0.f;
    for (int o = tid; o < DD; o += 256) { float v = xp[o]; srow[o] = v; s += v; }
    s = blockReduceSum(s, red);
    float mu = s * (1.0f/DD);
    float vs = 0.f;
    for (int o = tid; o < DD; o += 256) { float d = srow[o]-mu; vs += d*d; }
    vs = blockReduceSum(vs, red);
    float rstd = rsqrtf(vs * (1.0f/DD) + 1e-5f);
    float* op = out + (size_t)row * DD;
    for (int o = tid; o < DD; o += 256)
        op[o] = (srow[o]-mu) * rstd * gw[o] + bw[o];
}

// ---------------- period-sparse attention, float4 vectorized ----------------
__global__ void __launch_bounds__(256) attn_kernel() {
    __shared__ float4 sq4[256];
    __shared__ float sc[168];
    __shared__ float red[8];
    int i = blockIdx.x, h = blockIdx.y, b = blockIdx.z;
    int tid = threadIdx.x;
    int p = g_periods[b*4 + h]; if (p < 1) p = 1;
    int nm = i/p + 1;
    size_t qb = ((size_t)(b*TT + i))*DD + h*HDIM;
    sq4[tid] = ((const float4*)(g_q + qb))[tid];
    __syncthreads();
    int w = tid >> 5, lane = tid & 31;
    for (int m = w; m < nm; m += 8) {
        int j = i - m*p;
        const float4* kp4 = (const float4*)(g_k + ((size_t)(b*TT + j))*DD + h*HDIM);
        float s = 0.f;
        for (int d = lane; d < 256; d += 32) {
            float4 a = sq4[d], bb = kp4[d];
            s += a.x*bb.x + a.y*bb.y + a.z*bb.z + a.w*bb.w;
        }
        #pragma unroll
        for (int o = 16; o > 0; o >>= 1) s += __shfl_xor_sync(0xffffffffu, s, o);
        if (lane == 0) sc[m] = s * 0.03125f;
    }
    __syncthreads();
    float mx = -1e30f;
    for (int m = tid; m < nm; m += 256) mx = fmaxf(mx, sc[m]);
    #pragma unroll
    for (int o = 16; o > 0; o >>= 1) mx = fmaxf(mx, __shfl_xor_sync(0xffffffffu, mx, o));
    if (lane == 0) red[w] = mx;
    __syncthreads();
    if (tid < 32) {
        float t = (tid < 8) ? red[tid] : -1e30f;
        #pragma unroll
        for (int o = 4; o > 0; o >>= 1) t = fmaxf(t, __shfl_xor_sync(0xffffffffu, t, o));
        if (tid == 0) red[0] = t;
    }
    __syncthreads();
    mx = red[0];
    __syncthreads();
    float sum = 0.f;
    for (int m = tid; m < nm; m += 256) { float e = expf(sc[m]-mx); sc[m] = e; sum += e; }
    sum = blockReduceSum(sum, red);
    float inv = 1.0f/sum;
    float4 av = make_float4(0.f, 0.f, 0.f, 0.f);
    for (int m = 0; m < nm; m++) {
        int j = i - m*p;
        float4 vv = ((const float4*)(g_v + ((size_t)(b*TT + j))*DD + h*HDIM))[tid];
        float wgt = sc[m];
        av.x += wgt*vv.x; av.y += wgt*vv.y; av.z += wgt*vv.z; av.w += wgt*vv.w;
    }
    av.x *= inv; av.y *= inv; av.z *= inv; av.w *= inv;
    __nv_bfloat16 h0, l0, h1, l1, h2, l2, h3, l3;
    split_bf16(av.x, h0, l0); split_bf16(av.y, h1, l1);
    split_bf16(av.z, h2, l2); split_bf16(av.w, h3, l3);
    uint2 uh, ul;
    uh.x = ((uint32_t)__bfloat16_as_ushort(h1) << 16) | __bfloat16_as_ushort(h0);
    uh.y = ((uint32_t)__bfloat16_as_ushort(h3) << 16) | __bfloat16_as_ushort(h2);
    ul.x = ((uint32_t)__bfloat16_as_ushort(l1) << 16) | __bfloat16_as_ushort(l0);
    ul.y = ((uint32_t)__bfloat16_as_ushort(l3) << 16) | __bfloat16_as_ushort(l2);
    size_t ob = qb + (size_t)tid * 4;
    *(uint2*)(g_aoh + ob) = uh;
    *(uint2*)(g_aol + ob) = ul;
}

__global__ void periods_out_kernel(float* dst) {
    int t = threadIdx.x;
    if (t < 16) dst[t] = (float)g_periods[t];
}

// ---------------- launch ----------------
extern "C" void kernel_launch(void* const* d_in, const int* in_sizes, int n_in,
                              void* d_out, int out_size) {
    const float* M     = (const float*)d_in[0];
    const float* L_o   = (const float*)d_in[1];
    const float* L_d   = (const float*)d_in[2];
    const float* theta = (const float*)d_in[3];
    const float* Wop   = (const float*)d_in[4];
    const float* bop   = (const float*)d_in[5];
    const float* Wdp   = (const float*)d_in[6];
    const float* bdp   = (const float*)d_in[7];
    const float* Wos   = (const float*)d_in[8];
    const float* bos   = (const float*)d_in[9];
    const float* Wds   = (const float*)d_in[10];
    const float* bds   = (const float*)d_in[11];
    const float* Wq    = (const float*)d_in[12];
    const float* bq    = (const float*)d_in[13];
    const float* Wk    = (const float*)d_in[14];
    const float* bk    = (const float*)d_in[15];
    const float* Wv    = (const float*)d_in[16];
    const float* bv    = (const float*)d_in[17];
    const float* Wo    = (const float*)d_in[18];
    const float* bo    = (const float*)d_in[19];
    const float* W1    = (const float*)d_in[20];
    const float* b1    = (const float*)d_in[21];
    const float* W2    = (const float*)d_in[22];
    const float* b2    = (const float*)d_in[23];
    const float* g1    = (const float*)d_in[24];
    const float* be1   = (const float*)d_in[25];
    const float* g2    = (const float*)d_in[26];
    const float* be2   = (const float*)d_in[27];
    float* out = (float*)d_out;

    float *p_x, *p_q, *p_k, *p_v, *p_y, *p_f, *p_w1t, *p_w2t;
    __nv_bfloat16 *p_whi, *p_wlo, *p_aoh, *p_aol, *p_xnh, *p_xnl;
    cudaGetSymbolAddress((void**)&p_x,  g_x);
    cudaGetSymbolAddress((void**)&p_q,  g_q);
    cudaGetSymbolAddress((void**)&p_k,  g_k);
    cudaGetSymbolAddress((void**)&p_v,  g_v);
    cudaGetSymbolAddress((void**)&p_y,  g_y);
    cudaGetSymbolAddress((void**)&p_f,  g_f);
    cudaGetSymbolAddress((void**)&p_w1t,g_w1t);
    cudaGetSymbolAddress((void**)&p_w2t,g_w2t);
    cudaGetSymbolAddress((void**)&p_whi,g_whi);
    cudaGetSymbolAddress((void**)&p_wlo,g_wlo);
    cudaGetSymbolAddress((void**)&p_xnh,g_xnh);
    cudaGetSymbolAddress((void**)&p_xnl,g_xnl);
    cudaGetSymbolAddress((void**)&p_aoh,g_aoh);
    cudaGetSymbolAddress((void**)&p_aol,g_aol);

    cudaFuncSetAttribute(gemm_wmma,     cudaFuncAttributeMaxDynamicSharedMemorySize, G_SMEM);
    cudaFuncSetAttribute(gemm_wmma_qkv, cudaFuncAttributeMaxDynamicSharedMemorySize, G_SMEM);
    cudaFuncSetAttribute(gemm_tf32,     cudaFuncAttributeMaxDynamicSharedMemorySize, TF_SMEM);

    convert_all_kernel<<<147456, 256>>>(Wq, Wk, Wv, Wo, W1, W2);                 // 1
    prep_kernel<<<16, 256>>>(L_o, L_d, Wop, bop, Wos, bos, Wdp, bdp, Wds, bds);  // 2
    gcnod_kernel<<<BT, 256>>>(M, theta, g1, be1);                                // 3
    gemm_wmma_qkv<<<dim3(6, 32, 3), 256, G_SMEM>>>(p_xnh, p_xnl, p_whi, p_wlo,
                                                   bq, bk, bv, p_q, p_k, p_v);   // 4 <- ncu slot
    period_kernel<<<BB, 192>>>();                                                // 5
    dim3 gA(TT, HH, BB);
    attn_kernel<<<gA, 256>>>();                                                  // 6

    gemm_wmma<<<dim3(6, 32), 256, G_SMEM>>>(p_aoh, p_aol, p_whi + OFFO, p_wlo + OFFO,
                                            bo, p_x, p_x, BT, DD, DD, 1);
    ln_kernel<<<BT, 256>>>(p_x, g2, be2, p_y);
    gemm_tf32<<<dim3(6, 128), 256, TF_SMEM>>>(p_y, p_w1t, b1, (const float*)0,
                                              p_f, BT, DFF, DD, 2);
    gemm_tf32<<<dim3(6, 32), 256, TF_SMEM>>>(p_f, p_w2t, b2, p_x,
                                             out, BT, DD, DFF, 1);

    if (out_size >= BT*DD + 16) {
        periods_out_kernel<<<1, 32>>>(out + (size_t)BT*DD);
    }
}

// round 11
// speedup vs baseline: 1.3169x; 1.3169x over previous
#include <cuda_runtime.h>
#include <cuda_bf16.h>
#include <mma.h>
#include <cstdint>
#include <math.h>

using namespace nvcuda;

#define BB 4
#define TT 168
#define BT 672
#define DD 4096
#define HH 4
#define HDIM 1024
#define DFF 16384

#define OFFQ  0ul
#define OFFK  16777216ul
#define OFFV  33554432ul
#define OFFO  50331648ul
#define OFFW1 67108864ul
#define OFFW2 134217728ul
#define WTOT  201326592ul

__device__ __nv_bfloat16 g_whi[WTOT];
__device__ __nv_bfloat16 g_wlo[WTOT];

__device__ float g_To[768], g_Td[768];
__device__ float g_Wos2[4096], g_Wds2[4096], g_bos2[16], g_bds2[16];
__device__ float g_x[BT * DD];
__device__ float g_xm[BT];
__device__ float g_q[BT * DD], g_k[BT * DD], g_v[BT * DD];
__device__ int   g_periods[BB * HH];
__device__ __nv_bfloat16 g_xnh[BT * DD], g_xnl[BT * DD];
__device__ __nv_bfloat16 g_aoh[BT * DD], g_aol[BT * DD];
__device__ __nv_bfloat16 g_yh [BT * DD], g_yl [BT * DD];
__device__ __nv_bfloat16 g_fh [(size_t)BT * DFF], g_fl[(size_t)BT * DFF];

__device__ __forceinline__ float blockReduceSum(float v, float* red) {
    int tid = threadIdx.x;
    #pragma unroll
    for (int o = 16; o > 0; o >>= 1) v += __shfl_xor_sync(0xffffffffu, v, o);
    if ((tid & 31) == 0) red[tid >> 5] = v;
    __syncthreads();
    if (tid < 32) {
        float t = (tid < 8) ? red[tid] : 0.0f;
        #pragma unroll
        for (int o = 4; o > 0; o >>= 1) t += __shfl_xor_sync(0xffffffffu, t, o);
        if (tid == 0) red[0] = t;
    }
    __syncthreads();
    float r = red[0];
    __syncthreads();
    return r;
}

__device__ __forceinline__ void split_bf16(float v, __nv_bfloat16& h, __nv_bfloat16& l) {
    h = __float2bfloat16(v);
    l = __float2bfloat16(v - __bfloat162float(h));
}

__device__ __forceinline__ void cpa16(uint32_t dst, const void* src, int srcsz) {
    asm volatile("cp.async.cg.shared.global [%0], [%1], 16, %2;"
                 :: "r"(dst), "l"(src), "r"(srcsz) : "memory");
}
__device__ __forceinline__ void cpa_commit() { asm volatile("cp.async.commit_group;" ::: "memory"); }
template<int N>
__device__ __forceinline__ void cpa_wait() { asm volatile("cp.async.wait_group %0;" :: "n"(N) : "memory"); }

// ---------------- weight convert: 128(K) x 32(N) tiles, coalesced 256B stores (R9) ----------------
__global__ void __launch_bounds__(256) convert_all_kernel(
    const float* __restrict__ Wq, const float* __restrict__ Wk,
    const float* __restrict__ Wv, const float* __restrict__ Wo,
    const float* __restrict__ W1, const float* __restrict__ W2)
{
    __shared__ float s[128][33];
    int bid = blockIdx.x;
    const float* W; int K, N; size_t off; int bx, by;
    if (bid < 16384) {
        int w = bid >> 12, t = bid & 4095;
        W = (w == 0) ? Wq : (w == 1) ? Wk : (w == 2) ? Wv : Wo;
        K = 4096; N = 4096; off = (size_t)w * 16777216ul;
        bx = t & 127; by = t >> 7;
    } else if (bid < 32768) {
        int t = bid - 16384;
        W = W1; K = 4096; N = 16384; off = OFFW1;
        bx = t & 511; by = t >> 9;
    } else {
        int t = bid - 32768;
        W = W2; K = 16384; N = 4096; off = OFFW2;
        bx = t & 127; by = t >> 7;
    }
    int k0 = by * 128, n0 = bx * 32;
    int tid = threadIdx.x;
    {
        int n = tid & 31, kb = tid >> 5;
        #pragma unroll
        for (int r = 0; r < 16; r++) {
            int k = r * 8 + kb;
            s[k][n] = W[(size_t)(k0 + k) * N + n0 + n];
        }
    }
    __syncthreads();
    {
        int n = tid >> 3;
        int kc = (tid & 7) * 16;
        __nv_bfloat16 hb[16], lb[16];
        #pragma unroll
        for (int j = 0; j < 16; j++) split_bf16(s[kc + j][n], hb[j], lb[j]);
        size_t o = off + (size_t)(n0 + n) * K + k0 + kc;
        #pragma unroll
        for (int u = 0; u < 2; u++) {
            uint4 ph, pl;
            uint32_t* pph = (uint32_t*)&ph;
            uint32_t* ppl = (uint32_t*)&pl;
            #pragma unroll
            for (int c = 0; c < 4; c++) {
                int j = u * 8 + c * 2;
                pph[c] = ((uint32_t)__bfloat16_as_ushort(hb[j+1]) << 16) | __bfloat16_as_ushort(hb[j]);
                ppl[c] = ((uint32_t)__bfloat16_as_ushort(lb[j+1]) << 16) | __bfloat16_as_ushort(lb[j]);
            }
            *(uint4*)(g_whi + o + u * 8) = ph;
            *(uint4*)(g_wlo + o + u * 8) = pl;
        }
    }
}

// ---------------- bf16 split GEMM, tile 128x128, 2-stage, 2 CTA/SM (R8) ----------------
#define PAD 40
#define ST_AL (128 * PAD)
#define ST_BH (2 * 128 * PAD)
#define ST_BL (3 * 128 * PAD)
#define ST_ELE (4 * 128 * PAD)
#define ST_BYT (ST_ELE * 2)
#define G_SMEM (2 * ST_BYT)

__device__ __forceinline__ void issue_stage(
    uint32_t sb,
    const __nv_bfloat16* __restrict__ Ah, const __nv_bfloat16* __restrict__ Al,
    const __nv_bfloat16* __restrict__ Bh, const __nv_bfloat16* __restrict__ Bl,
    int bm, int bn, int k0, int K, int Mr, int tid)
{
    #pragma unroll
    for (int t = 0; t < 2; t++) {
        int u = tid + t * 256;
        int row = u >> 2, q = u & 3;
        int m = bm + row;
        int ok = (m < Mr) ? 16 : 0;
        size_t g = (size_t)(m < Mr ? m : 0) * K + k0 + q * 8;
        cpa16(sb + (0     + row * PAD + q * 8) * 2, Ah + g, ok);
        cpa16(sb + (ST_AL + row * PAD + q * 8) * 2, Al + g, ok);
        size_t gb = (size_t)(bn + row) * K + k0 + q * 8;
        cpa16(sb + (ST_BH + row * PAD + q * 8) * 2, Bh + gb, 16);
        cpa16(sb + (ST_BL + row * PAD + q * 8) * 2, Bl + gb, 16);
    }
}

__device__ __forceinline__ void gemm_body(
    const __nv_bfloat16* __restrict__ Ah, const __nv_bfloat16* __restrict__ Al,
    const __nv_bfloat16* __restrict__ Bh, const __nv_bfloat16* __restrict__ Bl,
    const float* __restrict__ bias, const float* __restrict__ res,
    float* __restrict__ C, __nv_bfloat16* __restrict__ Ch, __nv_bfloat16* __restrict__ Cl,
    int Mr, int Nc, int K, int EPI)
{
    extern __shared__ char dsm[];
    uint32_t sbase = (uint32_t)__cvta_generic_to_shared(dsm);
    __nv_bfloat16* sm = (__nv_bfloat16*)dsm;

    int tid = threadIdx.x, wid = tid >> 5, lane = tid & 31;
    int bm = blockIdx.x * 128, bn = blockIdx.y * 128;
    int wm = (wid >> 2) * 64, wn = (wid & 3) * 32;

    wmma::fragment<wmma::accumulator, 16, 16, 16, float> acc[4][2];
    #pragma unroll
    for (int i = 0; i < 4; i++)
        #pragma unroll
        for (int j = 0; j < 2; j++) wmma::fill_fragment(acc[i][j], 0.0f);

    int KC = K >> 5;
    issue_stage(sbase, Ah, Al, Bh, Bl, bm, bn, 0, K, Mr, tid);
    cpa_commit();

    for (int kc = 0; kc < KC; kc++) {
        int cur = kc & 1;
        if (kc + 1 < KC) {
            issue_stage(sbase + ((kc + 1) & 1) * ST_BYT, Ah, Al, Bh, Bl,
                        bm, bn, (kc + 1) * 32, K, Mr, tid);
            cpa_commit();
            cpa_wait<1>();
        } else {
            cpa_wait<0>();
        }
        __syncthreads();
        const __nv_bfloat16* S = sm + cur * ST_ELE;
        #pragma unroll
        for (int kk = 0; kk < 32; kk += 16) {
            wmma::fragment<wmma::matrix_b, 16, 16, 16, __nv_bfloat16, wmma::col_major> fbh[2], fbl[2];
            #pragma unroll
            for (int j = 0; j < 2; j++) {
                wmma::load_matrix_sync(fbh[j], S + ST_BH + (wn + 16 * j) * PAD + kk, PAD);
                wmma::load_matrix_sync(fbl[j], S + ST_BL + (wn + 16 * j) * PAD + kk, PAD);
            }
            #pragma unroll
            for (int i = 0; i < 4; i++) {
                wmma::fragment<wmma::matrix_a, 16, 16, 16, __nv_bfloat16, wmma::row_major> fah, fal;
                wmma::load_matrix_sync(fah, S + 0     + (wm + 16 * i) * PAD + kk, PAD);
                wmma::load_matrix_sync(fal, S + ST_AL + (wm + 16 * i) * PAD + kk, PAD);
                #pragma unroll
                for (int j = 0; j < 2; j++) {
                    wmma::mma_sync(acc[i][j], fah, fbh[j], acc[i][j]);
                    wmma::mma_sync(acc[i][j], fah, fbl[j], acc[i][j]);
                    wmma::mma_sync(acc[i][j], fal, fbh[j], acc[i][j]);
                }
            }
        }
        __syncthreads();
    }

    float* fst = (float*)dsm + wid * 256;
    int r = lane >> 1, cs = (lane & 1) * 8;
    #pragma unroll
    for (int i = 0; i < 4; i++)
        #pragma unroll
        for (int j = 0; j < 2; j++) {
            wmma::store_matrix_sync(fst, acc[i][j], 16, wmma::mem_row_major);
            __syncwarp();
            int m = bm + wm + 16 * i + r;
            int col0 = bn + wn + 16 * j + cs;
            if (m < Mr) {
                float v[8];
                #pragma unroll
                for (int c = 0; c < 8; c++) v[c] = fst[r * 16 + cs + c] + bias[col0 + c];
                if (EPI == 1) {
                    const float* rp = res + (size_t)m * Nc + col0;
                    #pragma unroll
                    for (int c = 0; c < 8; c++) v[c] += rp[c];
                }
                if (EPI == 2) {
                    #pragma unroll
                    for (int c = 0; c < 8; c++)
                        v[c] = 0.5f * v[c] * (1.0f + erff(v[c] * 0.7071067811865475f));
                    uint4 uh, ul;
                    uint32_t ph[4], pl[4];
                    #pragma unroll
                    for (int c = 0; c < 4; c++) {
                        __nv_bfloat16 h0, l0, h1, l1;
                        split_bf16(v[2 * c], h0, l0);
                        split_bf16(v[2 * c + 1], h1, l1);
                        ph[c] = ((uint32_t)__bfloat16_as_ushort(h1) << 16) | __bfloat16_as_ushort(h0);
                        pl[c] = ((uint32_t)__bfloat16_as_ushort(l1) << 16) | __bfloat16_as_ushort(l0);
                    }
                    uh.x = ph[0]; uh.y = ph[1]; uh.z = ph[2]; uh.w = ph[3];
                    ul.x = pl[0]; ul.y = pl[1]; ul.z = pl[2]; ul.w = pl[3];
                    *(uint4*)(Ch + (size_t)m * Nc + col0) = uh;
                    *(uint4*)(Cl + (size_t)m * Nc + col0) = ul;
                } else {
                    float4 o0, o1;
                    o0.x = v[0]; o0.y = v[1]; o0.z = v[2]; o0.w = v[3];
                    o1.x = v[4]; o1.y = v[5]; o1.z = v[6]; o1.w = v[7];
                    *(float4*)(C + (size_t)m * Nc + col0) = o0;
                    *(float4*)(C + (size_t)m * Nc + col0 + 4) = o1;
                }
            }
            __syncwarp();
        }
}

__global__ void __launch_bounds__(256, 2) gemm_wmma(
    const __nv_bfloat16* Ah, const __nv_bfloat16* Al,
    const __nv_bfloat16* Bh, const __nv_bfloat16* Bl,
    const float* bias, const float* res,
    float* C, __nv_bfloat16* Ch, __nv_bfloat16* Cl,
    int Mr, int Nc, int K, int EPI)
{
    gemm_body(Ah, Al, Bh, Bl, bias, res, C, Ch, Cl, Mr, Nc, K, EPI);
}

__global__ void __launch_bounds__(256, 2) gemm_wmma_qkv(
    const __nv_bfloat16* Ah, const __nv_bfloat16* Al,
    const __nv_bfloat16* whi, const __nv_bfloat16* wlo,
    const float* bq, const float* bk, const float* bv,
    float* q, float* k, float* v)
{
    int z = blockIdx.z;
    size_t off = (size_t)z * 16777216ul;
    const float* bias = (z == 0) ? bq : (z == 1) ? bk : bv;
    float* C = (z == 0) ? q : (z == 1) ? k : v;
    gemm_body(Ah, Al, whi + off, wlo + off, bias, (const float*)0, C,
              (__nv_bfloat16*)0, (__nv_bfloat16*)0, BT, DD, DD, 0);
}

// ---------------- merged prep ----------------
__global__ void prep_kernel(const float* __restrict__ Lo, const float* __restrict__ Ld,
                            const float* __restrict__ Wop, const float* __restrict__ bop,
                            const float* __restrict__ Wos, const float* __restrict__ bos,
                            const float* __restrict__ Wdp, const float* __restrict__ bdp,
                            const float* __restrict__ Wds, const float* __restrict__ bds) {
    int tid = threadIdx.x;
    if (blockIdx.x == 0) {
        int i = tid >> 4, j = tid & 15;
        float id = (i == j) ? 1.0f : 0.0f;
        float a = 0.f, b = 0.f;
        for (int k = 0; k < 16; k++) { a += Lo[i*16+k]*Lo[k*16+j]; b += Ld[i*16+k]*Ld[k*16+j]; }
        g_To[tid] = id; g_To[256+tid] = Lo[tid]; g_To[512+tid] = 2.f*a - id;
        g_Td[tid] = id; g_Td[256+tid] = Ld[tid]; g_Td[512+tid] = 2.f*b - id;
    }
    int idx = blockIdx.x * 256 + tid;
    int kf = idx >> 4, n = idx & 15;
    float a = 0.f, b = 0.f;
    for (int h = 0; h < 512; h++) {
        a += Wop[kf*512+h] * Wos[h*16+n];
        b += Wdp[kf*512+h] * Wds[h*16+n];
    }
    g_Wos2[idx] = a; g_Wds2[idx] = b;
    if (idx < 16) {
        float c = bos[idx], d = bds[idx];
        for (int h = 0; h < 512; h++) { c += bop[h]*Wos[h*16+idx]; d += bdp[h]*Wds[h*16+idx]; }
        g_bos2[idx] = c; g_bds2[idx] = d;
    }
}

// ---------------- GCN + OD + combine + fused LayerNorm1 ----------------
__global__ void __launch_bounds__(256) gcnod_kernel(const float* __restrict__ M,
                                                    const float* __restrict__ theta,
                                                    const float* __restrict__ g1,
                                                    const float* __restrict__ be1) {
    __shared__ float sM[4096], sR[4096], sTh[2304];
    __shared__ float sScore[256], sPo[256], sPd[256], st2[512];
    __shared__ float sEnt[16], sRed[8];
    __shared__ int   sSel[4];
    int bt = blockIdx.x, tid = threadIdx.x;
    const float* Mp = M + (size_t)bt * 4096;
    for (int o = tid; o < 4096; o += 256) sM[o] = Mp[o];
    for (int o = tid; o < 2304; o += 256) sTh[o] = theta[o];
    __syncthreads();
    {
        int i = tid >> 4, n = tid & 15;
        const float* xr = sM + i * 256;
        float a = g_bos2[n];
        for (int kf = 0; kf < 256; kf++) a += xr[kf] * g_Wos2[kf*16+n];
        sScore[tid] = a;
    }
    __syncthreads();
    if (tid < 16) {
        float mx = -1e30f;
        #pragma unroll
        for (int n = 0; n < 16; n++) mx = fmaxf(mx, sScore[tid*16+n]);
        float e[16], s = 0.f;
        #pragma unroll
        for (int n = 0; n < 16; n++) { e[n] = expf(sScore[tid*16+n]-mx); s += e[n]; }
        float inv = 1.f/s, ent = 0.f;
        #pragma unroll
        for (int n = 0; n < 16; n++) { float p = e[n]*inv; sPo[tid*16+n]=p; ent -= p*logf(p+1e-9f); }
        sEnt[tid] = ent;
    }
    __syncthreads();
    if (tid == 0) {
        int i0 = 0;
        for (int t = 1; t < 16; t++) if (sEnt[t] < sEnt[i0]) i0 = t;
        int i1 = (i0 == 0) ? 1 : 0;
        for (int t = 0; t < 16; t++) { if (t == i0) continue; if (sEnt[t] < sEnt[i1]) i1 = t; }
        sSel[0] = i0; sSel[1] = i1;
    }
    {
        int k = tid >> 4, n = tid & 15;
        float a = g_bds2[n];
        for (int jf = 0; jf < 256; jf++)
            a += sM[(jf>>4)*256 + k*16 + (jf&15)] * g_Wds2[jf*16+n];
        __syncthreads();
        sScore[tid] = a;
    }
    __syncthreads();
    if (tid < 16) {
        float mx = -1e30f;
        #pragma unroll
        for (int n = 0; n < 16; n++) mx = fmaxf(mx, sScore[tid*16+n]);
        float e[16], s = 0.f;
        #pragma unroll
        for (int n = 0; n < 16; n++) { e[n] = expf(sScore[tid*16+n]-mx); s += e[n]; }
        float inv = 1.f/s, ent = 0.f;
        #pragma unroll
        for (int n = 0; n < 16; n++) { float p = e[n]*inv; sPd[tid*16+n]=p; ent -= p*logf(p+1e-9f); }
        sEnt[tid] = ent;
    }
    __syncthreads();
    if (tid == 0) {
        int i0 = 0;
        for (int t = 1; t < 16; t++) if (sEnt[t] < sEnt[i0]) i0 = t;
        int i1 = (i0 == 0) ? 1 : 0;
        for (int t = 0; t < 16; t++) { if (t == i0) continue; if (sEnt[t] < sEnt[i1]) i1 = t; }
        sSel[2] = i0; sSel[3] = i1;
    }
    __syncthreads();
    {
        #pragma unroll
        for (int s = 0; s < 2; s++) {
            int ii = sSel[s];
            float a = 0.f;
            for (int j = 0; j < 16; j++) a += sPo[ii*16+j] * sM[j*256 + tid];
            st2[s*256 + tid] = a;
        }
    }
    __syncthreads();
    int gi = tid & 15, gl = tid >> 4;
    float MG[16];
    #pragma unroll
    for (int g = 0; g < 16; g++) MG[g] = 0.f;
    for (int c = 0; c < 3; c++) {
        for (int r = 0; r < 16; r++) {
            int ll = tid >> 4, f = tid & 15;
            float a = 0.f;
            #pragma unroll
            for (int k = 0; k < 16; k++)
                a += sM[(r<<8)+(k<<4)+f] * g_Td[c*256 + (k<<4) + ll];
            sR[(r<<8) + tid] = a;
        }
        __syncthreads();
        for (int a_ = 0; a_ < 3; a_++) {
            float S[16];
            #pragma unroll
            for (int f = 0; f < 16; f++) S[f] = 0.f;
            for (int j = 0; j < 16; j++) {
                float t_ = g_To[a_*256 + (gi<<4) + j];
                const float* rp = sR + (j<<8) + (gl<<4);
                #pragma unroll
                for (int f = 0; f < 16; f++) S[f] += t_ * rp[f];
            }
            const float* th = sTh + (a_*3 + c) * 256;
            #pragma unroll
            for (int f = 0; f < 16; f++) {
                float sv = S[f];
                #pragma unroll
                for (int g = 0; g < 16; g++) MG[g] += sv * th[f*16+g];
            }
        }
        __syncthreads();
    }
    int so = (gi == sSel[0]) ? 0 : ((gi == sSel[1]) ? 1 : -1);
    int sd = (gl == sSel[2]) ? 0 : ((gl == sSel[3]) ? 1 : -1);
    float v[16];
    float lsum = 0.f, lsq = 0.f;
    #pragma unroll
    for (int g = 0; g < 16; g++) {
        float w = 0.5f * MG[g];
        if (so >= 0 && sd >= 0) {
            float ma = 0.f;
            #pragma unroll
            for (int ll = 0; ll < 16; ll++)
                ma += st2[so*256 + g*16 + ll] * sPd[gl*16 + ll];
            w += 0.5f * ma;
        }
        v[g] = w;
        lsum += w;
        lsq += w * w;
    }
    float tot = blockReduceSum(lsum, sRed);
    float sqt = blockReduceSum(lsq, sRed);
    float mu = tot * (1.0f/4096.0f);
    float var = sqt * (1.0f/4096.0f) - mu * mu;
    float rstd = rsqrtf(var + 1e-5f);
    size_t base = (size_t)bt*4096 + gi*256 + gl*16;
    float* xp = g_x + base;
    __nv_bfloat16* xh = g_xnh + base;
    __nv_bfloat16* xl = g_xnl + base;
    #pragma unroll
    for (int g = 0; g < 16; g++) {
        xp[g] = v[g];
        float xn = (v[g] - mu) * rstd * g1[gi*256 + gl*16 + g] + be1[gi*256 + gl*16 + g];
        __nv_bfloat16 h, l; split_bf16(xn, h, l);
        xh[g] = h; xl[g] = l;
    }
    if (tid == 0) g_xm[bt] = mu;
}

__global__ void period_kernel() {
    __shared__ float sx[168], sd[168], sac[168];
    __shared__ float smean;
    int b = blockIdx.x, tid = threadIdx.x;
    if (tid < 168) sx[tid] = g_xm[b*168 + tid];
    __syncthreads();
    if (tid < 168) {
        float s = 0.f;
        #pragma unroll
        for (int o = -12; o <= 12; o++) {
            int u = tid + o; u = u < 0 ? 0 : (u > 167 ? 167 : u);
            s += sx[u];
        }
        sd[tid] = sx[tid] - s * (1.0f/25.0f);
    }
    __syncthreads();
    if (tid == 0) {
        float s = 0.f;
        for (int t = 0; t < 168; t++) s += sd[t];
        smean = s / 168.0f;
    }
    __syncthreads();
    if (tid < 168) sd[tid] -= smean;
    __syncthreads();
    if (tid < 168) {
        float a = 0.f;
        for (int t = 0; t + tid < 168; t++) a += sd[t] * sd[t + tid];
        sac[tid] = (tid < 2) ? -1e9f : a;
    }
    __syncthreads();
    if (tid == 0) {
        bool used[168];
        for (int t = 0; t < 168; t++) used[t] = false;
        for (int r = 0; r < 4; r++) {
            int bi = 0; float bv = -1e30f;
            for (int t = 0; t < 168; t++)
                if (!used[t] && sac[t] > bv) { bv = sac[t]; bi = t; }
            used[bi] = true;
            g_periods[b*4 + r] = bi;
        }
    }
}

__global__ void __launch_bounds__(256) ln_kernel(const float* __restrict__ x,
                                                 const float* __restrict__ gw,
                                                 const float* __restrict__ bw,
                                                 __nv_bfloat16* __restrict__ oh,
                                                 __nv_bfloat16* __restrict__ ol) {
    __shared__ float srow[DD];
    __shared__ float red[8];
    int row = blockIdx.x, tid = threadIdx.x;
    const float* xp = x + (size_t)row * DD;
    float s = 0.f;
    for (int o = tid; o < DD; o += 256) { float v = xp[o]; srow[o] = v; s += v; }
    s = blockReduceSum(s, red);
    float mu = s * (1.0f/DD);
    float vs = 0.f;
    for (int o = tid; o < DD; o += 256) { float d = srow[o]-mu; vs += d*d; }
    vs = blockReduceSum(vs, red);
    float rstd = rsqrtf(vs * (1.0f/DD) + 1e-5f);
    __nv_bfloat16* oph = oh + (size_t)row * DD;
    __nv_bfloat16* opl = ol + (size_t)row * DD;
    for (int o = tid; o < DD; o += 256) {
        float v = (srow[o]-mu) * rstd * gw[o] + bw[o];
        __nv_bfloat16 h, l; split_bf16(v, h, l);
        oph[o] = h; opl[o] = l;
    }
}

// ---------------- period-sparse attention, float4 vectorized (R9) ----------------
__global__ void __launch_bounds__(256) attn_kernel() {
    __shared__ float4 sq4[256];
    __shared__ float sc[168];
    __shared__ float red[8];
    int i = blockIdx.x, h = blockIdx.y, b = blockIdx.z;
    int tid = threadIdx.x;
    int p = g_periods[b*4 + h]; if (p < 1) p = 1;
    int nm = i/p + 1;
    size_t qb = ((size_t)(b*TT + i))*DD + h*HDIM;
    sq4[tid] = ((const float4*)(g_q + qb))[tid];
    __syncthreads();
    int w = tid >> 5, lane = tid & 31;
    for (int m = w; m < nm; m += 8) {
        int j = i - m*p;
        const float4* kp4 = (const float4*)(g_k + ((size_t)(b*TT + j))*DD + h*HDIM);
        float s = 0.f;
        for (int d = lane; d < 256; d += 32) {
            float4 a = sq4[d], bb = kp4[d];
            s += a.x*bb.x + a.y*bb.y + a.z*bb.z + a.w*bb.w;
        }
        #pragma unroll
        for (int o = 16; o > 0; o >>= 1) s += __shfl_xor_sync(0xffffffffu, s, o);
        if (lane == 0) sc[m] = s * 0.03125f;
    }
    __syncthreads();
    float mx = -1e30f;
    for (int m = tid; m < nm; m += 256) mx = fmaxf(mx, sc[m]);
    #pragma unroll
    for (int o = 16; o > 0; o >>= 1) mx = fmaxf(mx, __shfl_xor_sync(0xffffffffu, mx, o));
    if (lane == 0) red[w] = mx;
    __syncthreads();
    if (tid < 32) {
        float t = (tid < 8) ? red[tid] : -1e30f;
        #pragma unroll
        for (int o = 4; o > 0; o >>= 1) t = fmaxf(t, __shfl_xor_sync(0xffffffffu, t, o));
        if (tid == 0) red[0] = t;
    }
    __syncthreads();
    mx = red[0];
    __syncthreads();
    float sum = 0.f;
    for (int m = tid; m < nm; m += 256) { float e = expf(sc[m]-mx); sc[m] = e; sum += e; }
    sum = blockReduceSum(sum, red);
    float inv = 1.0f/sum;
    float4 av = make_float4(0.f, 0.f, 0.f, 0.f);
    for (int m = 0; m < nm; m++) {
        int j = i - m*p;
        float4 vv = ((const float4*)(g_v + ((size_t)(b*TT + j))*DD + h*HDIM))[tid];
        float wgt = sc[m];
        av.x += wgt*vv.x; av.y += wgt*vv.y; av.z += wgt*vv.z; av.w += wgt*vv.w;
    }
    av.x *= inv; av.y *= inv; av.z *= inv; av.w *= inv;
    __nv_bfloat16 h0, l0, h1, l1, h2, l2, h3, l3;
    split_bf16(av.x, h0, l0); split_bf16(av.y, h1, l1);
    split_bf16(av.z, h2, l2); split_bf16(av.w, h3, l3);
    uint2 uh, ul;
    uh.x = ((uint32_t)__bfloat16_as_ushort(h1) << 16) | __bfloat16_as_ushort(h0);
    uh.y = ((uint32_t)__bfloat16_as_ushort(h3) << 16) | __bfloat16_as_ushort(h2);
    ul.x = ((uint32_t)__bfloat16_as_ushort(l1) << 16) | __bfloat16_as_ushort(l0);
    ul.y = ((uint32_t)__bfloat16_as_ushort(l3) << 16) | __bfloat16_as_ushort(l2);
    size_t ob = qb + (size_t)tid * 4;
    *(uint2*)(g_aoh + ob) = uh;
    *(uint2*)(g_aol + ob) = ul;
}

__global__ void periods_out_kernel(float* dst) {
    int t = threadIdx.x;
    if (t < 16) dst[t] = (float)g_periods[t];
}

// ---------------- launch ----------------
extern "C" void kernel_launch(void* const* d_in, const int* in_sizes, int n_in,
                              void* d_out, int out_size) {
    const float* M     = (const float*)d_in[0];
    const float* L_o   = (const float*)d_in[1];
    const float* L_d   = (const float*)d_in[2];
    const float* theta = (const float*)d_in[3];
    const float* Wop   = (const float*)d_in[4];
    const float* bop   = (const float*)d_in[5];
    const float* Wdp   = (const float*)d_in[6];
    const float* bdp   = (const float*)d_in[7];
    const float* Wos   = (const float*)d_in[8];
    const float* bos   = (const float*)d_in[9];
    const float* Wds   = (const float*)d_in[10];
    const float* bds   = (const float*)d_in[11];
    const float* Wq    = (const float*)d_in[12];
    const float* bq    = (const float*)d_in[13];
    const float* Wk    = (const float*)d_in[14];
    const float* bk    = (const float*)d_in[15];
    const float* Wv    = (const float*)d_in[16];
    const float* bv    = (const float*)d_in[17];
    const float* Wo    = (const float*)d_in[18];
    const float* bo    = (const float*)d_in[19];
    const float* W1    = (const float*)d_in[20];
    const float* b1    = (const float*)d_in[21];
    const float* W2    = (const float*)d_in[22];
    const float* b2    = (const float*)d_in[23];
    const float* g1    = (const float*)d_in[24];
    const float* be1   = (const float*)d_in[25];
    const float* g2    = (const float*)d_in[26];
    const float* be2   = (const float*)d_in[27];
    float* out = (float*)d_out;

    float *p_x, *p_q, *p_k, *p_v;
    __nv_bfloat16 *p_whi, *p_wlo, *p_aoh, *p_aol, *p_yh, *p_yl, *p_fh, *p_fl, *p_xnh, *p_xnl;
    cudaGetSymbolAddress((void**)&p_x,  g_x);
    cudaGetSymbolAddress((void**)&p_q,  g_q);
    cudaGetSymbolAddress((void**)&p_k,  g_k);
    cudaGetSymbolAddress((void**)&p_v,  g_v);
    cudaGetSymbolAddress((void**)&p_whi,g_whi);
    cudaGetSymbolAddress((void**)&p_wlo,g_wlo);
    cudaGetSymbolAddress((void**)&p_xnh,g_xnh);
    cudaGetSymbolAddress((void**)&p_xnl,g_xnl);
    cudaGetSymbolAddress((void**)&p_aoh,g_aoh);
    cudaGetSymbolAddress((void**)&p_aol,g_aol);
    cudaGetSymbolAddress((void**)&p_yh, g_yh);
    cudaGetSymbolAddress((void**)&p_yl, g_yl);
    cudaGetSymbolAddress((void**)&p_fh, g_fh);
    cudaGetSymbolAddress((void**)&p_fl, g_fl);

    cudaFuncSetAttribute(gemm_wmma,     cudaFuncAttributeMaxDynamicSharedMemorySize, G_SMEM);
    cudaFuncSetAttribute(gemm_wmma_qkv, cudaFuncAttributeMaxDynamicSharedMemorySize, G_SMEM);

    convert_all_kernel<<<49152, 256>>>(Wq, Wk, Wv, Wo, W1, W2);                  // 1
    prep_kernel<<<16, 256>>>(L_o, L_d, Wop, bop, Wos, bos, Wdp, bdp, Wds, bds);  // 2
    gcnod_kernel<<<BT, 256>>>(M, theta, g1, be1);                                // 3
    gemm_wmma_qkv<<<dim3(6, 32, 3), 256, G_SMEM>>>(p_xnh, p_xnl, p_whi, p_wlo,
                                                   bq, bk, bv, p_q, p_k, p_v);   // 4 <- ncu slot
    period_kernel<<<BB, 192>>>();                                                // 5
    dim3 gA(TT, HH, BB);
    attn_kernel<<<gA, 256>>>();                                                  // 6

    gemm_wmma<<<dim3(6, 32), 256, G_SMEM>>>(p_aoh, p_aol, p_whi + OFFO, p_wlo + OFFO, bo, p_x,
                                            p_x, (__nv_bfloat16*)0, (__nv_bfloat16*)0, BT, DD, DD, 1);
    ln_kernel<<<BT, 256>>>(p_x, g2, be2, p_yh, p_yl);
    gemm_wmma<<<dim3(6, 128), 256, G_SMEM>>>(p_yh, p_yl, p_whi + OFFW1, p_wlo + OFFW1, b1, (const float*)0,
                                             (float*)0, p_fh, p_fl, BT, DFF, DD, 2);
    gemm_wmma<<<dim3(6, 32), 256, G_SMEM>>>(p_fh, p_fl, p_whi + OFFW2, p_wlo + OFFW2, b2, p_x,
                                            out, (__nv_bfloat16*)0, (__nv_bfloat16*)0, BT, DD, DFF, 1);

    if (out_size >= BT*DD + 16) {
        periods_out_kernel<<<1, 32>>>(out + (size_t)BT*DD);
    }
}

// round 12
// speedup vs baseline: 2.1245x; 1.6133x over previous
#include <cuda_runtime.h>
#include <cuda_bf16.h>
#include <cuda_fp16.h>
#include <mma.h>
#include <cstdint>
#include <math.h>

using namespace nvcuda;

#define BB 4
#define TT 168
#define BT 672
#define DD 4096
#define HH 4
#define HDIM 1024
#define DFF 16384

#define OFFQ  0ul
#define OFFK  16777216ul
#define OFFV  33554432ul
#define OFFO  50331648ul
#define WTOT  67108864ul
#define OFFH1 0ul
#define OFFH2 67108864ul

__device__ __nv_bfloat16 g_whi[WTOT];
__device__ __nv_bfloat16 g_wlo[WTOT];
__device__ __half g_w16[134217728];   // W1^T [16384,4096] + W2^T [4096,16384]

__device__ float g_To[768], g_Td[768];
__device__ float g_Wos2[4096], g_Wds2[4096], g_bos2[16], g_bds2[16];
__device__ float g_x[BT * DD];
__device__ float g_xm[BT];
__device__ float g_q[BT * DD], g_k[BT * DD], g_v[BT * DD];
__device__ int   g_periods[BB * HH];
__device__ __nv_bfloat16 g_xnh[BT * DD], g_xnl[BT * DD];
__device__ __nv_bfloat16 g_aoh[BT * DD], g_aol[BT * DD];
__device__ __half g_y16[BT * DD];
__device__ __half g_f16[(size_t)BT * DFF];

__device__ __forceinline__ float blockReduceSum(float v, float* red) {
    int tid = threadIdx.x;
    #pragma unroll
    for (int o = 16; o > 0; o >>= 1) v += __shfl_xor_sync(0xffffffffu, v, o);
    if ((tid & 31) == 0) red[tid >> 5] = v;
    __syncthreads();
    if (tid < 32) {
        float t = (tid < 8) ? red[tid] : 0.0f;
        #pragma unroll
        for (int o = 4; o > 0; o >>= 1) t += __shfl_xor_sync(0xffffffffu, t, o);
        if (tid == 0) red[0] = t;
    }
    __syncthreads();
    float r = red[0];
    __syncthreads();
    return r;
}

__device__ __forceinline__ void split_bf16(float v, __nv_bfloat16& h, __nv_bfloat16& l) {
    h = __float2bfloat16(v);
    l = __float2bfloat16(v - __bfloat162float(h));
}

__device__ __forceinline__ void cpa16(uint32_t dst, const void* src, int srcsz) {
    asm volatile("cp.async.cg.shared.global [%0], [%1], 16, %2;"
                 :: "r"(dst), "l"(src), "r"(srcsz) : "memory");
}
__device__ __forceinline__ void cpa_commit() { asm volatile("cp.async.commit_group;" ::: "memory"); }
template<int N>
__device__ __forceinline__ void cpa_wait() { asm volatile("cp.async.wait_group %0;" :: "n"(N) : "memory"); }

// ---------------- weight convert ----------------
// QKV/O -> bf16 hi/lo [N,K].  W1/W2 -> fp16 [N,K].
__global__ void __launch_bounds__(256) convert_all_kernel(
    const float* __restrict__ Wq, const float* __restrict__ Wk,
    const float* __restrict__ Wv, const float* __restrict__ Wo,
    const float* __restrict__ W1, const float* __restrict__ W2)
{
    __shared__ float s[128][33];
    int bid = blockIdx.x;
    int tid = threadIdx.x;
    if (bid < 16384) {
        int w = bid >> 12, t = bid & 4095;
        const float* W = (w == 0) ? Wq : (w == 1) ? Wk : (w == 2) ? Wv : Wo;
        size_t off = (size_t)w * 16777216ul;
        int bx = t & 127, by = t >> 7;
        int k0 = by * 128, n0 = bx * 32;
        {
            int n = tid & 31, kb = tid >> 5;
            #pragma unroll
            for (int r = 0; r < 16; r++) {
                int k = r * 8 + kb;
                s[k][n] = W[(size_t)(k0 + k) * 4096 + n0 + n];
            }
        }
        __syncthreads();
        {
            int n = tid >> 3;
            int kc = (tid & 7) * 16;
            __nv_bfloat16 hb[16], lb[16];
            #pragma unroll
            for (int j = 0; j < 16; j++) split_bf16(s[kc + j][n], hb[j], lb[j]);
            size_t o = off + (size_t)(n0 + n) * 4096 + k0 + kc;
            #pragma unroll
            for (int u = 0; u < 2; u++) {
                uint4 ph, pl;
                uint32_t* pph = (uint32_t*)&ph;
                uint32_t* ppl = (uint32_t*)&pl;
                #pragma unroll
                for (int c = 0; c < 4; c++) {
                    int j = u * 8 + c * 2;
                    pph[c] = ((uint32_t)__bfloat16_as_ushort(hb[j+1]) << 16) | __bfloat16_as_ushort(hb[j]);
                    ppl[c] = ((uint32_t)__bfloat16_as_ushort(lb[j+1]) << 16) | __bfloat16_as_ushort(lb[j]);
                }
                *(uint4*)(g_whi + o + u * 8) = ph;
                *(uint4*)(g_wlo + o + u * 8) = pl;
            }
        }
    } else {
        const float* W; size_t off; int K, N; int bx, by;
        if (bid < 32768) {
            int t = bid - 16384;
            W = W1; off = OFFH1; K = 4096; N = 16384;
            bx = t & 511; by = t >> 9;
        } else {
            int t = bid - 32768;
            W = W2; off = OFFH2; K = 16384; N = 4096;
            bx = t & 127; by = t >> 7;
        }
        int k0 = by * 128, n0 = bx * 32;
        {
            int n = tid & 31, kb = tid >> 5;
            #pragma unroll
            for (int r = 0; r < 16; r++) {
                int k = r * 8 + kb;
                s[k][n] = W[(size_t)(k0 + k) * N + n0 + n];
            }
        }
        __syncthreads();
        {
            int n = tid >> 3;
            int kc = (tid & 7) * 16;
            __half hv[16];
            #pragma unroll
            for (int j = 0; j < 16; j++) hv[j] = __float2half(s[kc + j][n]);
            size_t o = off + (size_t)(n0 + n) * K + k0 + kc;
            #pragma unroll
            for (int u = 0; u < 2; u++) {
                uint4 p;
                uint32_t* pp = (uint32_t*)&p;
                #pragma unroll
                for (int c = 0; c < 4; c++) {
                    int j = u * 8 + c * 2;
                    pp[c] = ((uint32_t)__half_as_ushort(hv[j+1]) << 16) | __half_as_ushort(hv[j]);
                }
                *(uint4*)(g_w16 + o + u * 8) = p;
            }
        }
    }
}

// ---------------- bf16 split GEMM, tile 128x128, 2-stage, 2 CTA/SM ----------------
#define PAD 40
#define ST_AL (128 * PAD)
#define ST_BH (2 * 128 * PAD)
#define ST_BL (3 * 128 * PAD)
#define ST_ELE (4 * 128 * PAD)
#define ST_BYT (ST_ELE * 2)
#define G_SMEM (2 * ST_BYT)

__device__ __forceinline__ void issue_stage(
    uint32_t sb,
    const __nv_bfloat16* __restrict__ Ah, const __nv_bfloat16* __restrict__ Al,
    const __nv_bfloat16* __restrict__ Bh, const __nv_bfloat16* __restrict__ Bl,
    int bm, int bn, int k0, int K, int Mr, int tid)
{
    #pragma unroll
    for (int t = 0; t < 2; t++) {
        int u = tid + t * 256;
        int row = u >> 2, q = u & 3;
        int m = bm + row;
        int ok = (m < Mr) ? 16 : 0;
        size_t g = (size_t)(m < Mr ? m : 0) * K + k0 + q * 8;
        cpa16(sb + (0     + row * PAD + q * 8) * 2, Ah + g, ok);
        cpa16(sb + (ST_AL + row * PAD + q * 8) * 2, Al + g, ok);
        size_t gb = (size_t)(bn + row) * K + k0 + q * 8;
        cpa16(sb + (ST_BH + row * PAD + q * 8) * 2, Bh + gb, 16);
        cpa16(sb + (ST_BL + row * PAD + q * 8) * 2, Bl + gb, 16);
    }
}

__device__ __forceinline__ void gemm_body(
    const __nv_bfloat16* __restrict__ Ah, const __nv_bfloat16* __restrict__ Al,
    const __nv_bfloat16* __restrict__ Bh, const __nv_bfloat16* __restrict__ Bl,
    const float* __restrict__ bias, const float* __restrict__ res,
    float* __restrict__ C, int Mr, int Nc, int K, int EPI)
{
    extern __shared__ char dsm[];
    uint32_t sbase = (uint32_t)__cvta_generic_to_shared(dsm);
    __nv_bfloat16* sm = (__nv_bfloat16*)dsm;

    int tid = threadIdx.x, wid = tid >> 5, lane = tid & 31;
    int bm = blockIdx.x * 128, bn = blockIdx.y * 128;
    int wm = (wid >> 2) * 64, wn = (wid & 3) * 32;

    wmma::fragment<wmma::accumulator, 16, 16, 16, float> acc[4][2];
    #pragma unroll
    for (int i = 0; i < 4; i++)
        #pragma unroll
        for (int j = 0; j < 2; j++) wmma::fill_fragment(acc[i][j], 0.0f);

    int KC = K >> 5;
    issue_stage(sbase, Ah, Al, Bh, Bl, bm, bn, 0, K, Mr, tid);
    cpa_commit();

    for (int kc = 0; kc < KC; kc++) {
        int cur = kc & 1;
        if (kc + 1 < KC) {
            issue_stage(sbase + ((kc + 1) & 1) * ST_BYT, Ah, Al, Bh, Bl,
                        bm, bn, (kc + 1) * 32, K, Mr, tid);
            cpa_commit();
            cpa_wait<1>();
        } else {
            cpa_wait<0>();
        }
        __syncthreads();
        const __nv_bfloat16* S = sm + cur * ST_ELE;
        #pragma unroll
        for (int kk = 0; kk < 32; kk += 16) {
            wmma::fragment<wmma::matrix_b, 16, 16, 16, __nv_bfloat16, wmma::col_major> fbh[2], fbl[2];
            #pragma unroll
            for (int j = 0; j < 2; j++) {
                wmma::load_matrix_sync(fbh[j], S + ST_BH + (wn + 16 * j) * PAD + kk, PAD);
                wmma::load_matrix_sync(fbl[j], S + ST_BL + (wn + 16 * j) * PAD + kk, PAD);
            }
            #pragma unroll
            for (int i = 0; i < 4; i++) {
                wmma::fragment<wmma::matrix_a, 16, 16, 16, __nv_bfloat16, wmma::row_major> fah, fal;
                wmma::load_matrix_sync(fah, S + 0     + (wm + 16 * i) * PAD + kk, PAD);
                wmma::load_matrix_sync(fal, S + ST_AL + (wm + 16 * i) * PAD + kk, PAD);
                #pragma unroll
                for (int j = 0; j < 2; j++) {
                    wmma::mma_sync(acc[i][j], fah, fbh[j], acc[i][j]);
                    wmma::mma_sync(acc[i][j], fah, fbl[j], acc[i][j]);
                    wmma::mma_sync(acc[i][j], fal, fbh[j], acc[i][j]);
                }
            }
        }
        __syncthreads();
    }

    float* fst = (float*)dsm + wid * 256;
    int r = lane >> 1, cs = (lane & 1) * 8;
    #pragma unroll
    for (int i = 0; i < 4; i++)
        #pragma unroll
        for (int j = 0; j < 2; j++) {
            wmma::store_matrix_sync(fst, acc[i][j], 16, wmma::mem_row_major);
            __syncwarp();
            int m = bm + wm + 16 * i + r;
            int col0 = bn + wn + 16 * j + cs;
            if (m < Mr) {
                float v[8];
                #pragma unroll
                for (int c = 0; c < 8; c++) v[c] = fst[r * 16 + cs + c] + bias[col0 + c];
                if (EPI == 1) {
                    const float* rp = res + (size_t)m * Nc + col0;
                    #pragma unroll
                    for (int c = 0; c < 8; c++) v[c] += rp[c];
                }
                float4 o0, o1;
                o0.x = v[0]; o0.y = v[1]; o0.z = v[2]; o0.w = v[3];
                o1.x = v[4]; o1.y = v[5]; o1.z = v[6]; o1.w = v[7];
                *(float4*)(C + (size_t)m * Nc + col0) = o0;
                *(float4*)(C + (size_t)m * Nc + col0 + 4) = o1;
            }
            __syncwarp();
        }
}

__global__ void __launch_bounds__(256, 2) gemm_wmma(
    const __nv_bfloat16* Ah, const __nv_bfloat16* Al,
    const __nv_bfloat16* Bh, const __nv_bfloat16* Bl,
    const float* bias, const float* res, float* C,
    int Mr, int Nc, int K, int EPI)
{
    gemm_body(Ah, Al, Bh, Bl, bias, res, C, Mr, Nc, K, EPI);
}

__global__ void __launch_bounds__(256, 2) gemm_wmma_qkv(
    const __nv_bfloat16* Ah, const __nv_bfloat16* Al,
    const __nv_bfloat16* whi, const __nv_bfloat16* wlo,
    const float* bq, const float* bk, const float* bv,
    float* q, float* k, float* v)
{
    int z = blockIdx.z;
    size_t off = (size_t)z * 16777216ul;
    const float* bias = (z == 0) ? bq : (z == 1) ? bk : bv;
    float* C = (z == 0) ? q : (z == 1) ? k : v;
    gemm_body(Ah, Al, whi + off, wlo + off, bias, (const float*)0, C, BT, DD, DD, 0);
}

// ---------------- fp16 single-pass GEMM (FFN), tile 128x128, 2-stage ----------------
#define PADH 40
#define H_B (128 * PADH)
#define H_ELE (2 * 128 * PADH)
#define H_BYT (H_ELE * 2)
#define H_SMEM (2 * H_BYT)

__device__ __forceinline__ void issue_stage_h(
    uint32_t sb, const __half* __restrict__ A, const __half* __restrict__ B,
    int bm, int bn, int k0, int K, int Mr, int tid)
{
    #pragma unroll
    for (int t = 0; t < 2; t++) {
        int u = tid + t * 256;
        int row = u >> 2, q = u & 3;
        int m = bm + row;
        int ok = (m < Mr) ? 16 : 0;
        size_t g = (size_t)(m < Mr ? m : 0) * K + k0 + q * 8;
        cpa16(sb + (row * PADH + q * 8) * 2, A + g, ok);
        size_t gb = (size_t)(bn + row) * K + k0 + q * 8;
        cpa16(sb + (H_B + row * PADH + q * 8) * 2, B + gb, 16);
    }
}

// EPI: 1 = bias+res -> fp32 C ; 2 = gelu(bias) -> fp16 Ch
__global__ void __launch_bounds__(256, 2) gemm_fp16(
    const __half* __restrict__ A, const __half* __restrict__ B,
    const float* __restrict__ bias, const float* __restrict__ res,
    float* __restrict__ C, __half* __restrict__ Ch,
    int Mr, int Nc, int K, int EPI)
{
    extern __shared__ char dsm[];
    uint32_t sbase = (uint32_t)__cvta_generic_to_shared(dsm);
    __half* sm = (__half*)dsm;

    int tid = threadIdx.x, wid = tid >> 5, lane = tid & 31;
    int bm = blockIdx.x * 128, bn = blockIdx.y * 128;
    int wm = (wid >> 2) * 64, wn = (wid & 3) * 32;

    wmma::fragment<wmma::accumulator, 16, 16, 16, float> acc[4][2];
    #pragma unroll
    for (int i = 0; i < 4; i++)
        #pragma unroll
        for (int j = 0; j < 2; j++) wmma::fill_fragment(acc[i][j], 0.0f);

    int KC = K >> 5;
    issue_stage_h(sbase, A, B, bm, bn, 0, K, Mr, tid);
    cpa_commit();

    for (int kc = 0; kc < KC; kc++) {
        int cur = kc & 1;
        if (kc + 1 < KC) {
            issue_stage_h(sbase + ((kc + 1) & 1) * H_BYT, A, B, bm, bn, (kc + 1) * 32, K, Mr, tid);
            cpa_commit();
            cpa_wait<1>();
        } else {
            cpa_wait<0>();
        }
        __syncthreads();
        const __half* S = sm + cur * H_ELE;
        #pragma unroll
        for (int kk = 0; kk < 32; kk += 16) {
            wmma::fragment<wmma::matrix_b, 16, 16, 16, __half, wmma::col_major> fb[2];
            #pragma unroll
            for (int j = 0; j < 2; j++)
                wmma::load_matrix_sync(fb[j], S + H_B + (wn + 16 * j) * PADH + kk, PADH);
            #pragma unroll
            for (int i = 0; i < 4; i++) {
                wmma::fragment<wmma::matrix_a, 16, 16, 16, __half, wmma::row_major> fa;
                wmma::load_matrix_sync(fa, S + (wm + 16 * i) * PADH + kk, PADH);
                #pragma unroll
                for (int j = 0; j < 2; j++)
                    wmma::mma_sync(acc[i][j], fa, fb[j], acc[i][j]);
            }
        }
        __syncthreads();
    }

    float* fst = (float*)dsm + wid * 256;
    int r = lane >> 1, cs = (lane & 1) * 8;
    #pragma unroll
    for (int i = 0; i < 4; i++)
        #pragma unroll
        for (int j = 0; j < 2; j++) {
            wmma::store_matrix_sync(fst, acc[i][j], 16, wmma::mem_row_major);
            __syncwarp();
            int m = bm + wm + 16 * i + r;
            int col0 = bn + wn + 16 * j + cs;
            if (m < Mr) {
                float v[8];
                #pragma unroll
                for (int c = 0; c < 8; c++) v[c] = fst[r * 16 + cs + c] + bias[col0 + c];
                if (EPI == 1) {
                    const float* rp = res + (size_t)m * Nc + col0;
                    #pragma unroll
                    for (int c = 0; c < 8; c++) v[c] += rp[c];
                    float4 o0, o1;
                    o0.x = v[0]; o0.y = v[1]; o0.z = v[2]; o0.w = v[3];
                    o1.x = v[4]; o1.y = v[5]; o1.z = v[6]; o1.w = v[7];
                    *(float4*)(C + (size_t)m * Nc + col0) = o0;
                    *(float4*)(C + (size_t)m * Nc + col0 + 4) = o1;
                } else {
                    uint4 p;
                    uint32_t* pp = (uint32_t*)&p;
                    #pragma unroll
                    for (int c = 0; c < 4; c++) {
                        float a0 = v[2*c],   g0 = 0.5f * a0 * (1.0f + erff(a0 * 0.7071067811865475f));
                        float a1 = v[2*c+1], g1 = 0.5f * a1 * (1.0f + erff(a1 * 0.7071067811865475f));
                        __half h0 = __float2half(g0), h1 = __float2half(g1);
                        pp[c] = ((uint32_t)__half_as_ushort(h1) << 16) | __half_as_ushort(h0);
                    }
                    *(uint4*)(Ch + (size_t)m * Nc + col0) = p;
                }
            }
            __syncwarp();
        }
}

// ---------------- merged prep ----------------
__global__ void prep_kernel(const float* __restrict__ Lo, const float* __restrict__ Ld,
                            const float* __restrict__ Wop, const float* __restrict__ bop,
                            const float* __restrict__ Wos, const float* __restrict__ bos,
                            const float* __restrict__ Wdp, const float* __restrict__ bdp,
                            const float* __restrict__ Wds, const float* __restrict__ bds) {
    int tid = threadIdx.x;
    if (blockIdx.x == 0) {
        int i = tid >> 4, j = tid & 15;
        float id = (i == j) ? 1.0f : 0.0f;
        float a = 0.f, b = 0.f;
        for (int k = 0; k < 16; k++) { a += Lo[i*16+k]*Lo[k*16+j]; b += Ld[i*16+k]*Ld[k*16+j]; }
        g_To[tid] = id; g_To[256+tid] = Lo[tid]; g_To[512+tid] = 2.f*a - id;
        g_Td[tid] = id; g_Td[256+tid] = Ld[tid]; g_Td[512+tid] = 2.f*b - id;
    }
    int idx = blockIdx.x * 256 + tid;
    int kf = idx >> 4, n = idx & 15;
    float a = 0.f, b = 0.f;
    for (int h = 0; h < 512; h++) {
        a += Wop[kf*512+h] * Wos[h*16+n];
        b += Wdp[kf*512+h] * Wds[h*16+n];
    }
    g_Wos2[idx] = a; g_Wds2[idx] = b;
    if (idx < 16) {
        float c = bos[idx], d = bds[idx];
        for (int h = 0; h < 512; h++) { c += bop[h]*Wos[h*16+idx]; d += bdp[h]*Wds[h*16+idx]; }
        g_bos2[idx] = c; g_bds2[idx] = d;
    }
}

// ---------------- GCN + OD + combine + fused LayerNorm1 ----------------
__global__ void __launch_bounds__(256) gcnod_kernel(const float* __restrict__ M,
                                                    const float* __restrict__ theta,
                                                    const float* __restrict__ g1,
                                                    const float* __restrict__ be1) {
    __shared__ float sM[4096], sR[4096], sTh[2304];
    __shared__ float sScore[256], sPo[256], sPd[256], st2[512];
    __shared__ float sEnt[16], sRed[8];
    __shared__ int   sSel[4];
    int bt = blockIdx.x, tid = threadIdx.x;
    const float* Mp = M + (size_t)bt * 4096;
    for (int o = tid; o < 4096; o += 256) sM[o] = Mp[o];
    for (int o = tid; o < 2304; o += 256) sTh[o] = theta[o];
    __syncthreads();
    {
        int i = tid >> 4, n = tid & 15;
        const float* xr = sM + i * 256;
        float a = g_bos2[n];
        for (int kf = 0; kf < 256; kf++) a += xr[kf] * g_Wos2[kf*16+n];
        sScore[tid] = a;
    }
    __syncthreads();
    if (tid < 16) {
        float mx = -1e30f;
        #pragma unroll
        for (int n = 0; n < 16; n++) mx = fmaxf(mx, sScore[tid*16+n]);
        float e[16], s = 0.f;
        #pragma unroll
        for (int n = 0; n < 16; n++) { e[n] = expf(sScore[tid*16+n]-mx); s += e[n]; }
        float inv = 1.f/s, ent = 0.f;
        #pragma unroll
        for (int n = 0; n < 16; n++) { float p = e[n]*inv; sPo[tid*16+n]=p; ent -= p*logf(p+1e-9f); }
        sEnt[tid] = ent;
    }
    __syncthreads();
    if (tid == 0) {
        int i0 = 0;
        for (int t = 1; t < 16; t++) if (sEnt[t] < sEnt[i0]) i0 = t;
        int i1 = (i0 == 0) ? 1 : 0;
        for (int t = 0; t < 16; t++) { if (t == i0) continue; if (sEnt[t] < sEnt[i1]) i1 = t; }
        sSel[0] = i0; sSel[1] = i1;
    }
    {
        int k = tid >> 4, n = tid & 15;
        float a = g_bds2[n];
        for (int jf = 0; jf < 256; jf++)
            a += sM[(jf>>4)*256 + k*16 + (jf&15)] * g_Wds2[jf*16+n];
        __syncthreads();
        sScore[tid] = a;
    }
    __syncthreads();
    if (tid < 16) {
        float mx = -1e30f;
        #pragma unroll
        for (int n = 0; n < 16; n++) mx = fmaxf(mx, sScore[tid*16+n]);
        float e[16], s = 0.f;
        #pragma unroll
        for (int n = 0; n < 16; n++) { e[n] = expf(sScore[tid*16+n]-mx); s += e[n]; }
        float inv = 1.f/s, ent = 0.f;
        #pragma unroll
        for (int n = 0; n < 16; n++) { float p = e[n]*inv; sPd[tid*16+n]=p; ent -= p*logf(p+1e-9f); }
        sEnt[tid] = ent;
    }
    __syncthreads();
    if (tid == 0) {
        int i0 = 0;
        for (int t = 1; t < 16; t++) if (sEnt[t] < sEnt[i0]) i0 = t;
        int i1 = (i0 == 0) ? 1 : 0;
        for (int t = 0; t < 16; t++) { if (t == i0) continue; if (sEnt[t] < sEnt[i1]) i1 = t; }
        sSel[2] = i0; sSel[3] = i1;
    }
    __syncthreads();
    {
        #pragma unroll
        for (int s = 0; s < 2; s++) {
            int ii = sSel[s];
            float a = 0.f;
            for (int j = 0; j < 16; j++) a += sPo[ii*16+j] * sM[j*256 + tid];
            st2[s*256 + tid] = a;
        }
    }
    __syncthreads();
    int gi = tid & 15, gl = tid >> 4;
    float MG[16];
    #pragma unroll
    for (int g = 0; g < 16; g++) MG[g] = 0.f;
    for (int c = 0; c < 3; c++) {
        for (int r = 0; r < 16; r++) {
            int ll = tid >> 4, f = tid & 15;
            float a = 0.f;
            #pragma unroll
            for (int k = 0; k < 16; k++)
                a += sM[(r<<8)+(k<<4)+f] * g_Td[c*256 + (k<<4) + ll];
            sR[(r<<8) + tid] = a;
        }
        __syncthreads();
        for (int a_ = 0; a_ < 3; a_++) {
            float S[16];
            #pragma unroll
            for (int f = 0; f < 16; f++) S[f] = 0.f;
            for (int j = 0; j < 16; j++) {
                float t_ = g_To[a_*256 + (gi<<4) + j];
                const float* rp = sR + (j<<8) + (gl<<4);
                #pragma unroll
                for (int f = 0; f < 16; f++) S[f] += t_ * rp[f];
            }
            const float* th = sTh + (a_*3 + c) * 256;
            #pragma unroll
            for (int f = 0; f < 16; f++) {
                float sv = S[f];
                #pragma unroll
                for (int g = 0; g < 16; g++) MG[g] += sv * th[f*16+g];
            }
        }
        __syncthreads();
    }
    int so = (gi == sSel[0]) ? 0 : ((gi == sSel[1]) ? 1 : -1);
    int sd = (gl == sSel[2]) ? 0 : ((gl == sSel[3]) ? 1 : -1);
    float v[16];
    float lsum = 0.f, lsq = 0.f;
    #pragma unroll
    for (int g = 0; g < 16; g++) {
        float w = 0.5f * MG[g];
        if (so >= 0 && sd >= 0) {
            float ma = 0.f;
            #pragma unroll
            for (int ll = 0; ll < 16; ll++)
                ma += st2[so*256 + g*16 + ll] * sPd[gl*16 + ll];
            w += 0.5f * ma;
        }
        v[g] = w;
        lsum += w;
        lsq += w * w;
    }
    float tot = blockReduceSum(lsum, sRed);
    float sqt = blockReduceSum(lsq, sRed);
    float mu = tot * (1.0f/4096.0f);
    float var = sqt * (1.0f/4096.0f) - mu * mu;
    float rstd = rsqrtf(var + 1e-5f);
    size_t base = (size_t)bt*4096 + gi*256 + gl*16;
    float* xp = g_x + base;
    __nv_bfloat16* xh = g_xnh + base;
    __nv_bfloat16* xl = g_xnl + base;
    #pragma unroll
    for (int g = 0; g < 16; g++) {
        xp[g] = v[g];
        float xn = (v[g] - mu) * rstd * g1[gi*256 + gl*16 + g] + be1[gi*256 + gl*16 + g];
        __nv_bfloat16 h, l; split_bf16(xn, h, l);
        xh[g] = h; xl[g] = l;
    }
    if (tid == 0) g_xm[bt] = mu;
}

__global__ void period_kernel() {
    __shared__ float sx[168], sd[168], sac[168];
    __shared__ float smean;
    int b = blockIdx.x, tid = threadIdx.x;
    if (tid < 168) sx[tid] = g_xm[b*168 + tid];
    __syncthreads();
    if (tid < 168) {
        float s = 0.f;
        #pragma unroll
        for (int o = -12; o <= 12; o++) {
            int u = tid + o; u = u < 0 ? 0 : (u > 167 ? 167 : u);
            s += sx[u];
        }
        sd[tid] = sx[tid] - s * (1.0f/25.0f);
    }
    __syncthreads();
    if (tid == 0) {
        float s = 0.f;
        for (int t = 0; t < 168; t++) s += sd[t];
        smean = s / 168.0f;
    }
    __syncthreads();
    if (tid < 168) sd[tid] -= smean;
    __syncthreads();
    if (tid < 168) {
        float a = 0.f;
        for (int t = 0; t + tid < 168; t++) a += sd[t] * sd[t + tid];
        sac[tid] = (tid < 2) ? -1e9f : a;
    }
    __syncthreads();
    if (tid == 0) {
        bool used[168];
        for (int t = 0; t < 168; t++) used[t] = false;
        for (int r = 0; r < 4; r++) {
            int bi = 0; float bv = -1e30f;
            for (int t = 0; t < 168; t++)
                if (!used[t] && sac[t] > bv) { bv = sac[t]; bi = t; }
            used[bi] = true;
            g_periods[b*4 + r] = bi;
        }
    }
}

// LayerNorm2: fp32 in -> fp16 out
__global__ void __launch_bounds__(256) ln_kernel(const float* __restrict__ x,
                                                 const float* __restrict__ gw,
                                                 const float* __restrict__ bw,
                                                 __half* __restrict__ o16) {
    __shared__ float srow[DD];
    __shared__ float red[8];
    int row = blockIdx.x, tid = threadIdx.x;
    const float* xp = x + (size_t)row * DD;
    float s = 0.f;
    for (int o = tid; o < DD; o += 256) { float v = xp[o]; srow[o] = v; s += v; }
    s = blockReduceSum(s, red);
    float mu = s * (1.0f/DD);
    float vs = 0.f;
    for (int o = tid; o < DD; o += 256) { float d = srow[o]-mu; vs += d*d; }
    vs = blockReduceSum(vs, red);
    float rstd = rsqrtf(vs * (1.0f/DD) + 1e-5f);
    __half* op = o16 + (size_t)row * DD;
    for (int o = tid; o < DD; o += 256)
        op[o] = __float2half((srow[o]-mu) * rstd * gw[o] + bw[o]);
}

// ---------------- period-sparse attention, float4 vectorized ----------------
__global__ void __launch_bounds__(256) attn_kernel() {
    __shared__ float4 sq4[256];
    __shared__ float sc[168];
    __shared__ float red[8];
    int i = blockIdx.x, h = blockIdx.y, b = blockIdx.z;
    int tid = threadIdx.x;
    int p = g_periods[b*4 + h]; if (p < 1) p = 1;
    int nm = i/p + 1;
    size_t qb = ((size_t)(b*TT + i))*DD + h*HDIM;
    sq4[tid] = ((const float4*)(g_q + qb))[tid];
    __syncthreads();
    int w = tid >> 5, lane = tid & 31;
    for (int m = w; m < nm; m += 8) {
        int j = i - m*p;
        const float4* kp4 = (const float4*)(g_k + ((size_t)(b*TT + j))*DD + h*HDIM);
        float s = 0.f;
        for (int d = lane; d < 256; d += 32) {
            float4 a = sq4[d], bb = kp4[d];
            s += a.x*bb.x + a.y*bb.y + a.z*bb.z + a.w*bb.w;
        }
        #pragma unroll
        for (int o = 16; o > 0; o >>= 1) s += __shfl_xor_sync(0xffffffffu, s, o);
        if (lane == 0) sc[m] = s * 0.03125f;
    }
    __syncthreads();
    float mx = -1e30f;
    for (int m = tid; m < nm; m += 256) mx = fmaxf(mx, sc[m]);
    #pragma unroll
    for (int o = 16; o > 0; o >>= 1) mx = fmaxf(mx, __shfl_xor_sync(0xffffffffu, mx, o));
    if (lane == 0) red[w] = mx;
    __syncthreads();
    if (tid < 32) {
        float t = (tid < 8) ? red[tid] : -1e30f;
        #pragma unroll
        for (int o = 4; o > 0; o >>= 1) t = fmaxf(t, __shfl_xor_sync(0xffffffffu, t, o));
        if (tid == 0) red[0] = t;
    }
    __syncthreads();
    mx = red[0];
    __syncthreads();
    float sum = 0.f;
    for (int m = tid; m < nm; m += 256) { float e = expf(sc[m]-mx); sc[m] = e; sum += e; }
    sum = blockReduceSum(sum, red);
    float inv = 1.0f/sum;
    float4 av = make_float4(0.f, 0.f, 0.f, 0.f);
    for (int m = 0; m < nm; m++) {
        int j = i - m*p;
        float4 vv = ((const float4*)(g_v + ((size_t)(b*TT + j))*DD + h*HDIM))[tid];
        float wgt = sc[m];
        av.x += wgt*vv.x; av.y += wgt*vv.y; av.z += wgt*vv.z; av.w += wgt*vv.w;
    }
    av.x *= inv; av.y *= inv; av.z *= inv; av.w *= inv;
    __nv_bfloat16 h0, l0, h1, l1, h2, l2, h3, l3;
    split_bf16(av.x, h0, l0); split_bf16(av.y, h1, l1);
    split_bf16(av.z, h2, l2); split_bf16(av.w, h3, l3);
    uint2 uh, ul;
    uh.x = ((uint32_t)__bfloat16_as_ushort(h1) << 16) | __bfloat16_as_ushort(h0);
    uh.y = ((uint32_t)__bfloat16_as_ushort(h3) << 16) | __bfloat16_as_ushort(h2);
    ul.x = ((uint32_t)__bfloat16_as_ushort(l1) << 16) | __bfloat16_as_ushort(l0);
    ul.y = ((uint32_t)__bfloat16_as_ushort(l3) << 16) | __bfloat16_as_ushort(l2);
    size_t ob = qb + (size_t)tid * 4;
    *(uint2*)(g_aoh + ob) = uh;
    *(uint2*)(g_aol + ob) = ul;
}

__global__ void periods_out_kernel(float* dst) {
    int t = threadIdx.x;
    if (t < 16) dst[t] = (float)g_periods[t];
}

// ---------------- launch ----------------
extern "C" void kernel_launch(void* const* d_in, const int* in_sizes, int n_in,
                              void* d_out, int out_size) {
    const float* M     = (const float*)d_in[0];
    const float* L_o   = (const float*)d_in[1];
    const float* L_d   = (const float*)d_in[2];
    const float* theta = (const float*)d_in[3];
    const float* Wop   = (const float*)d_in[4];
    const float* bop   = (const float*)d_in[5];
    const float* Wdp   = (const float*)d_in[6];
    const float* bdp   = (const float*)d_in[7];
    const float* Wos   = (const float*)d_in[8];
    const float* bos   = (const float*)d_in[9];
    const float* Wds   = (const float*)d_in[10];
    const float* bds   = (const float*)d_in[11];
    const float* Wq    = (const float*)d_in[12];
    const float* bq    = (const float*)d_in[13];
    const float* Wk    = (const float*)d_in[14];
    const float* bk    = (const float*)d_in[15];
    const float* Wv    = (const float*)d_in[16];
    const float* bv    = (const float*)d_in[17];
    const float* Wo    = (const float*)d_in[18];
    const float* bo    = (const float*)d_in[19];
    const float* W1    = (const float*)d_in[20];
    const float* b1    = (const float*)d_in[21];
    const float* W2    = (const float*)d_in[22];
    const float* b2    = (const float*)d_in[23];
    const float* g1    = (const float*)d_in[24];
    const float* be1   = (const float*)d_in[25];
    const float* g2    = (const float*)d_in[26];
    const float* be2   = (const float*)d_in[27];
    float* out = (float*)d_out;

    float *p_x, *p_q, *p_k, *p_v;
    __nv_bfloat16 *p_whi, *p_wlo, *p_aoh, *p_aol, *p_xnh, *p_xnl;
    __half *p_w16, *p_y16, *p_f16;
    cudaGetSymbolAddress((void**)&p_x,  g_x);
    cudaGetSymbolAddress((void**)&p_q,  g_q);
    cudaGetSymbolAddress((void**)&p_k,  g_k);
    cudaGetSymbolAddress((void**)&p_v,  g_v);
    cudaGetSymbolAddress((void**)&p_whi,g_whi);
    cudaGetSymbolAddress((void**)&p_wlo,g_wlo);
    cudaGetSymbolAddress((void**)&p_xnh,g_xnh);
    cudaGetSymbolAddress((void**)&p_xnl,g_xnl);
    cudaGetSymbolAddress((void**)&p_aoh,g_aoh);
    cudaGetSymbolAddress((void**)&p_aol,g_aol);
    cudaGetSymbolAddress((void**)&p_w16,g_w16);
    cudaGetSymbolAddress((void**)&p_y16,g_y16);
    cudaGetSymbolAddress((void**)&p_f16,g_f16);

    cudaFuncSetAttribute(gemm_wmma,     cudaFuncAttributeMaxDynamicSharedMemorySize, G_SMEM);
    cudaFuncSetAttribute(gemm_wmma_qkv, cudaFuncAttributeMaxDynamicSharedMemorySize, G_SMEM);
    cudaFuncSetAttribute(gemm_fp16,     cudaFuncAttributeMaxDynamicSharedMemorySize, H_SMEM);

    convert_all_kernel<<<49152, 256>>>(Wq, Wk, Wv, Wo, W1, W2);                  // 1
    prep_kernel<<<16, 256>>>(L_o, L_d, Wop, bop, Wos, bos, Wdp, bdp, Wds, bds);  // 2
    gcnod_kernel<<<BT, 256>>>(M, theta, g1, be1);                                // 3
    gemm_wmma_qkv<<<dim3(6, 32, 3), 256, G_SMEM>>>(p_xnh, p_xnl, p_whi, p_wlo,
                                                   bq, bk, bv, p_q, p_k, p_v);   // 4 <- ncu slot
    period_kernel<<<BB, 192>>>();                                                // 5
    dim3 gA(TT, HH, BB);
    attn_kernel<<<gA, 256>>>();                                                  // 6

    gemm_wmma<<<dim3(6, 32), 256, G_SMEM>>>(p_aoh, p_aol, p_whi + OFFO, p_wlo + OFFO,
                                            bo, p_x, p_x, BT, DD, DD, 1);
    ln_kernel<<<BT, 256>>>(p_x, g2, be2, p_y16);
    gemm_fp16<<<dim3(6, 128), 256, H_SMEM>>>(p_y16, p_w16 + OFFH1, b1, (const float*)0,
                                             (float*)0, p_f16, BT, DFF, DD, 2);
    gemm_fp16<<<dim3(6, 32), 256, H_SMEM>>>(p_f16, p_w16 + OFFH2, b2, p_x,
                                            out, (__half*)0, BT, DD, DFF, 1);

    if (out_size >= BT*DD + 16) {
        periods_out_kernel<<<1, 32>>>(out + (size_t)BT*DD);
    }
}

// round 13
// speedup vs baseline: 2.9749x; 1.4002x over previous
#include <cuda_runtime.h>
#include <cuda_fp16.h>
#include <mma.h>
#include <cstdint>
#include <math.h>

using namespace nvcuda;

#define BB 4
#define TT 168
#define BT 672
#define DD 4096
#define HH 4
#define HDIM 1024
#define DFF 16384

#define OFFQ  0ul
#define OFFK  16777216ul
#define OFFV  33554432ul
#define OFFO  50331648ul
#define OFFH1 67108864ul
#define OFFH2 134217728ul

__device__ __half g_w16[201326592];

__device__ float g_To[768], g_Td[768];
__device__ float g_Wos2[4096], g_Wds2[4096], g_bos2[16], g_bds2[16];
__device__ float g_x[BT * DD];
__device__ float g_xm[BT];
__device__ float g_q[BT * DD], g_k[BT * DD], g_v[BT * DD];
__device__ int   g_periods[BB * HH];
__device__ __half g_xn16[BT * DD];
__device__ __half g_ao16[BT * DD];
__device__ __half g_y16[BT * DD];
__device__ __half g_f16[(size_t)BT * DFF];

__device__ __forceinline__ float blockReduceSum(float v, float* red) {
    int tid = threadIdx.x;
    #pragma unroll
    for (int o = 16; o > 0; o >>= 1) v += __shfl_xor_sync(0xffffffffu, v, o);
    if ((tid & 31) == 0) red[tid >> 5] = v;
    __syncthreads();
    if (tid < 32) {
        float t = (tid < 8) ? red[tid] : 0.0f;
        #pragma unroll
        for (int o = 4; o > 0; o >>= 1) t += __shfl_xor_sync(0xffffffffu, t, o);
        if (tid == 0) red[0] = t;
    }
    __syncthreads();
    float r = red[0];
    __syncthreads();
    return r;
}

__device__ __forceinline__ void cpa16(uint32_t dst, const void* src, int srcsz) {
    asm volatile("cp.async.cg.shared.global [%0], [%1], 16, %2;"
                 :: "r"(dst), "l"(src), "r"(srcsz) : "memory");
}
__device__ __forceinline__ void cpa_commit() { asm volatile("cp.async.commit_group;" ::: "memory"); }
template<int N>
__device__ __forceinline__ void cpa_wait() { asm volatile("cp.async.wait_group %0;" :: "n"(N) : "memory"); }

// ---------------- weight convert: all six -> fp16 [N,K], 128Kx32N tiles ----------------
__global__ void __launch_bounds__(256) convert_all_kernel(
    const float* __restrict__ Wq, const float* __restrict__ Wk,
    const float* __restrict__ Wv, const float* __restrict__ Wo,
    const float* __restrict__ W1, const float* __restrict__ W2)
{
    __shared__ float s[128][33];
    int bid = blockIdx.x;
    int tid = threadIdx.x;
    const float* W; size_t off; int K, N; int bx, by;
    if (bid < 16384) {
        int w = bid >> 12, t = bid & 4095;
        W = (w == 0) ? Wq : (w == 1) ? Wk : (w == 2) ? Wv : Wo;
        off = (size_t)w * 16777216ul; K = 4096; N = 4096;
        bx = t & 127; by = t >> 7;
    } else if (bid < 32768) {
        int t = bid - 16384;
        W = W1; off = OFFH1; K = 4096; N = 16384;
        bx = t & 511; by = t >> 9;
    } else {
        int t = bid - 32768;
        W = W2; off = OFFH2; K = 16384; N = 4096;
        bx = t & 127; by = t >> 7;
    }
    int k0 = by * 128, n0 = bx * 32;
    {
        int n = tid & 31, kb = tid >> 5;
        #pragma unroll
        for (int r = 0; r < 16; r++) {
            int k = r * 8 + kb;
            s[k][n] = W[(size_t)(k0 + k) * N + n0 + n];
        }
    }
    __syncthreads();
    {
        int n = tid >> 3;
        int kc = (tid & 7) * 16;
        __half hv[16];
        #pragma unroll
        for (int j = 0; j < 16; j++) hv[j] = __float2half(s[kc + j][n]);
        size_t o = off + (size_t)(n0 + n) * K + k0 + kc;
        #pragma unroll
        for (int u = 0; u < 2; u++) {
            uint4 p;
            uint32_t* pp = (uint32_t*)&p;
            #pragma unroll
            for (int c = 0; c < 4; c++) {
                int j = u * 8 + c * 2;
                pp[c] = ((uint32_t)__half_as_ushort(hv[j+1]) << 16) | __half_as_ushort(hv[j]);
            }
            *(uint4*)(g_w16 + o + u * 8) = p;
        }
    }
}

// ---------------- fp16 single-pass GEMM, tile 128x128, 2-stage, 2 CTA/SM ----------------
#define PADH 40
#define H_B (128 * PADH)
#define H_ELE (2 * 128 * PADH)
#define H_BYT (H_ELE * 2)
#define H_SMEM (2 * H_BYT)

__device__ __forceinline__ void issue_stage_h(
    uint32_t sb, const __half* __restrict__ A, const __half* __restrict__ B,
    int bm, int bn, int k0, int K, int Mr, int tid)
{
    #pragma unroll
    for (int t = 0; t < 2; t++) {
        int u = tid + t * 256;
        int row = u >> 2, q = u & 3;
        int m = bm + row;
        int ok = (m < Mr) ? 16 : 0;
        size_t g = (size_t)(m < Mr ? m : 0) * K + k0 + q * 8;
        cpa16(sb + (row * PADH + q * 8) * 2, A + g, ok);
        size_t gb = (size_t)(bn + row) * K + k0 + q * 8;
        cpa16(sb + (H_B + row * PADH + q * 8) * 2, B + gb, 16);
    }
}

// EPI: 0 = bias -> fp32 C ; 1 = bias+res -> fp32 C ; 2 = gelu(bias) -> fp16 Ch
__device__ __forceinline__ void gemm_h_body(
    const __half* __restrict__ A, const __half* __restrict__ B,
    const float* __restrict__ bias, const float* __restrict__ res,
    float* __restrict__ C, __half* __restrict__ Ch,
    int Mr, int Nc, int K, int EPI)
{
    extern __shared__ char dsm[];
    uint32_t sbase = (uint32_t)__cvta_generic_to_shared(dsm);
    __half* sm = (__half*)dsm;

    int tid = threadIdx.x, wid = tid >> 5, lane = tid & 31;
    int bm = blockIdx.x * 128, bn = blockIdx.y * 128;
    int wm = (wid >> 2) * 64, wn = (wid & 3) * 32;

    wmma::fragment<wmma::accumulator, 16, 16, 16, float> acc[4][2];
    #pragma unroll
    for (int i = 0; i < 4; i++)
        #pragma unroll
        for (int j = 0; j < 2; j++) wmma::fill_fragment(acc[i][j], 0.0f);

    int KC = K >> 5;
    issue_stage_h(sbase, A, B, bm, bn, 0, K, Mr, tid);
    cpa_commit();

    for (int kc = 0; kc < KC; kc++) {
        int cur = kc & 1;
        if (kc + 1 < KC) {
            issue_stage_h(sbase + ((kc + 1) & 1) * H_BYT, A, B, bm, bn, (kc + 1) * 32, K, Mr, tid);
            cpa_commit();
            cpa_wait<1>();
        } else {
            cpa_wait<0>();
        }
        __syncthreads();
        const __half* S = sm + cur * H_ELE;
        #pragma unroll
        for (int kk = 0; kk < 32; kk += 16) {
            wmma::fragment<wmma::matrix_b, 16, 16, 16, __half, wmma::col_major> fb[2];
            #pragma unroll
            for (int j = 0; j < 2; j++)
                wmma::load_matrix_sync(fb[j], S + H_B + (wn + 16 * j) * PADH + kk, PADH);
            #pragma unroll
            for (int i = 0; i < 4; i++) {
                wmma::fragment<wmma::matrix_a, 16, 16, 16, __half, wmma::row_major> fa;
                wmma::load_matrix_sync(fa, S + (wm + 16 * i) * PADH + kk, PADH);
                #pragma unroll
                for (int j = 0; j < 2; j++)
                    wmma::mma_sync(acc[i][j], fa, fb[j], acc[i][j]);
            }
        }
        __syncthreads();
    }

    float* fst = (float*)dsm + wid * 256;
    int r = lane >> 1, cs = (lane & 1) * 8;
    #pragma unroll
    for (int i = 0; i < 4; i++)
        #pragma unroll
        for (int j = 0; j < 2; j++) {
            wmma::store_matrix_sync(fst, acc[i][j], 16, wmma::mem_row_major);
            __syncwarp();
            int m = bm + wm + 16 * i + r;
            int col0 = bn + wn + 16 * j + cs;
            if (m < Mr) {
                float v[8];
                #pragma unroll
                for (int c = 0; c < 8; c++) v[c] = fst[r * 16 + cs + c] + bias[col0 + c];
                if (EPI == 2) {
                    uint4 p;
                    uint32_t* pp = (uint32_t*)&p;
                    #pragma unroll
                    for (int c = 0; c < 4; c++) {
                        float a0 = v[2*c],   q0 = 0.5f * a0 * (1.0f + erff(a0 * 0.7071067811865475f));
                        float a1 = v[2*c+1], q1 = 0.5f * a1 * (1.0f + erff(a1 * 0.7071067811865475f));
                        __half h0 = __float2half(q0), h1 = __float2half(q1);
                        pp[c] = ((uint32_t)__half_as_ushort(h1) << 16) | __half_as_ushort(h0);
                    }
                    *(uint4*)(Ch + (size_t)m * Nc + col0) = p;
                } else {
                    if (EPI == 1) {
                        const float* rp = res + (size_t)m * Nc + col0;
                        #pragma unroll
                        for (int c = 0; c < 8; c++) v[c] += rp[c];
                    }
                    float4 o0, o1;
                    o0.x = v[0]; o0.y = v[1]; o0.z = v[2]; o0.w = v[3];
                    o1.x = v[4]; o1.y = v[5]; o1.z = v[6]; o1.w = v[7];
                    *(float4*)(C + (size_t)m * Nc + col0) = o0;
                    *(float4*)(C + (size_t)m * Nc + col0 + 4) = o1;
                }
            }
            __syncwarp();
        }
}

__global__ void __launch_bounds__(256, 2) gemm_fp16(
    const __half* A, const __half* B,
    const float* bias, const float* res,
    float* C, __half* Ch, int Mr, int Nc, int K, int EPI)
{
    gemm_h_body(A, B, bias, res, C, Ch, Mr, Nc, K, EPI);
}

__global__ void __launch_bounds__(256, 2) gemm_fp16_qkv(
    const __half* A, const __half* w16,
    const float* bq, const float* bk, const float* bv,
    float* q, float* k, float* v)
{
    int z = blockIdx.z;
    size_t off = (size_t)z * 16777216ul;
    const float* bias = (z == 0) ? bq : (z == 1) ? bk : bv;
    float* C = (z == 0) ? q : (z == 1) ? k : v;
    gemm_h_body(A, w16 + off, bias, (const float*)0, C, (__half*)0, BT, DD, DD, 0);
}

// ---------------- merged prep ----------------
__global__ void prep_kernel(const float* __restrict__ Lo, const float* __restrict__ Ld,
                            const float* __restrict__ Wop, const float* __restrict__ bop,
                            const float* __restrict__ Wos, const float* __restrict__ bos,
                            const float* __restrict__ Wdp, const float* __restrict__ bdp,
                            const float* __restrict__ Wds, const float* __restrict__ bds) {
    int tid = threadIdx.x;
    if (blockIdx.x == 0) {
        int i = tid >> 4, j = tid & 15;
        float id = (i == j) ? 1.0f : 0.0f;
        float a = 0.f, b = 0.f;
        for (int k = 0; k < 16; k++) { a += Lo[i*16+k]*Lo[k*16+j]; b += Ld[i*16+k]*Ld[k*16+j]; }
        g_To[tid] = id; g_To[256+tid] = Lo[tid]; g_To[512+tid] = 2.f*a - id;
        g_Td[tid] = id; g_Td[256+tid] = Ld[tid]; g_Td[512+tid] = 2.f*b - id;
    }
    int idx = blockIdx.x * 256 + tid;
    int kf = idx >> 4, n = idx & 15;
    float a = 0.f, b = 0.f;
    for (int h = 0; h < 512; h++) {
        a += Wop[kf*512+h] * Wos[h*16+n];
        b += Wdp[kf*512+h] * Wds[h*16+n];
    }
    g_Wos2[idx] = a; g_Wds2[idx] = b;
    if (idx < 16) {
        float c = bos[idx], d = bds[idx];
        for (int h = 0; h < 512; h++) { c += bop[h]*Wos[h*16+idx]; d += bdp[h]*Wds[h*16+idx]; }
        g_bos2[idx] = c; g_bds2[idx] = d;
    }
}

// ---------------- GCN + OD + combine + fused LayerNorm1 (fp16 xn out) ----------------
__global__ void __launch_bounds__(256) gcnod_kernel(const float* __restrict__ M,
                                                    const float* __restrict__ theta,
                                                    const float* __restrict__ g1,
                                                    const float* __restrict__ be1) {
    __shared__ float sM[4096], sR[4096], sTh[2304];
    __shared__ float sScore[256], sPo[256], sPd[256], st2[512];
    __shared__ float sEnt[16], sRed[8];
    __shared__ int   sSel[4];
    int bt = blockIdx.x, tid = threadIdx.x;
    const float* Mp = M + (size_t)bt * 4096;
    for (int o = tid; o < 4096; o += 256) sM[o] = Mp[o];
    for (int o = tid; o < 2304; o += 256) sTh[o] = theta[o];
    __syncthreads();
    {
        int i = tid >> 4, n = tid & 15;
        const float* xr = sM + i * 256;
        float a = g_bos2[n];
        for (int kf = 0; kf < 256; kf++) a += xr[kf] * g_Wos2[kf*16+n];
        sScore[tid] = a;
    }
    __syncthreads();
    if (tid < 16) {
        float mx = -1e30f;
        #pragma unroll
        for (int n = 0; n < 16; n++) mx = fmaxf(mx, sScore[tid*16+n]);
        float e[16], s = 0.f;
        #pragma unroll
        for (int n = 0; n < 16; n++) { e[n] = expf(sScore[tid*16+n]-mx); s += e[n]; }
        float inv = 1.f/s, ent = 0.f;
        #pragma unroll
        for (int n = 0; n < 16; n++) { float p = e[n]*inv; sPo[tid*16+n]=p; ent -= p*logf(p+1e-9f); }
        sEnt[tid] = ent;
    }
    __syncthreads();
    if (tid == 0) {
        int i0 = 0;
        for (int t = 1; t < 16; t++) if (sEnt[t] < sEnt[i0]) i0 = t;
        int i1 = (i0 == 0) ? 1 : 0;
        for (int t = 0; t < 16; t++) { if (t == i0) continue; if (sEnt[t] < sEnt[i1]) i1 = t; }
        sSel[0] = i0; sSel[1] = i1;
    }
    {
        int k = tid >> 4, n = tid & 15;
        float a = g_bds2[n];
        for (int jf = 0; jf < 256; jf++)
            a += sM[(jf>>4)*256 + k*16 + (jf&15)] * g_Wds2[jf*16+n];
        __syncthreads();
        sScore[tid] = a;
    }
    __syncthreads();
    if (tid < 16) {
        float mx = -1e30f;
        #pragma unroll
        for (int n = 0; n < 16; n++) mx = fmaxf(mx, sScore[tid*16+n]);
        float e[16], s = 0.f;
        #pragma unroll
        for (int n = 0; n < 16; n++) { e[n] = expf(sScore[tid*16+n]-mx); s += e[n]; }
        float inv = 1.f/s, ent = 0.f;
        #pragma unroll
        for (int n = 0; n < 16; n++) { float p = e[n]*inv; sPd[tid*16+n]=p; ent -= p*logf(p+1e-9f); }
        sEnt[tid] = ent;
    }
    __syncthreads();
    if (tid == 0) {
        int i0 = 0;
        for (int t = 1; t < 16; t++) if (sEnt[t] < sEnt[i0]) i0 = t;
        int i1 = (i0 == 0) ? 1 : 0;
        for (int t = 0; t < 16; t++) { if (t == i0) continue; if (sEnt[t] < sEnt[i1]) i1 = t; }
        sSel[2] = i0; sSel[3] = i1;
    }
    __syncthreads();
    {
        #pragma unroll
        for (int s = 0; s < 2; s++) {
            int ii = sSel[s];
            float a = 0.f;
            for (int j = 0; j < 16; j++) a += sPo[ii*16+j] * sM[j*256 + tid];
            st2[s*256 + tid] = a;
        }
    }
    __syncthreads();
    int gi = tid & 15, gl = tid >> 4;
    float MG[16];
    #pragma unroll
    for (int g = 0; g < 16; g++) MG[g] = 0.f;
    for (int c = 0; c < 3; c++) {
        for (int r = 0; r < 16; r++) {
            int ll = tid >> 4, f = tid & 15;
            float a = 0.f;
            #pragma unroll
            for (int k = 0; k < 16; k++)
                a += sM[(r<<8)+(k<<4)+f] * g_Td[c*256 + (k<<4) + ll];
            sR[(r<<8) + tid] = a;
        }
        __syncthreads();
        for (int a_ = 0; a_ < 3; a_++) {
            float S[16];
            #pragma unroll
            for (int f = 0; f < 16; f++) S[f] = 0.f;
            for (int j = 0; j < 16; j++) {
                float t_ = g_To[a_*256 + (gi<<4) + j];
                const float* rp = sR + (j<<8) + (gl<<4);
                #pragma unroll
                for (int f = 0; f < 16; f++) S[f] += t_ * rp[f];
            }
            const float* th = sTh + (a_*3 + c) * 256;
            #pragma unroll
            for (int f = 0; f < 16; f++) {
                float sv = S[f];
                #pragma unroll
                for (int g = 0; g < 16; g++) MG[g] += sv * th[f*16+g];
            }
        }
        __syncthreads();
    }
    int so = (gi == sSel[0]) ? 0 : ((gi == sSel[1]) ? 1 : -1);
    int sd = (gl == sSel[2]) ? 0 : ((gl == sSel[3]) ? 1 : -1);
    float v[16];
    float lsum = 0.f, lsq = 0.f;
    #pragma unroll
    for (int g = 0; g < 16; g++) {
        float w = 0.5f * MG[g];
        if (so >= 0 && sd >= 0) {
            float ma = 0.f;
            #pragma unroll
            for (int ll = 0; ll < 16; ll++)
                ma += st2[so*256 + g*16 + ll] * sPd[gl*16 + ll];
            w += 0.5f * ma;
        }
        v[g] = w;
        lsum += w;
        lsq += w * w;
    }
    float tot = blockReduceSum(lsum, sRed);
    float sqt = blockReduceSum(lsq, sRed);
    float mu = tot * (1.0f/4096.0f);
    float var = sqt * (1.0f/4096.0f) - mu * mu;
    float rstd = rsqrtf(var + 1e-5f);
    size_t base = (size_t)bt*4096 + gi*256 + gl*16;
    float* xp = g_x + base;
    __half* xh = g_xn16 + base;
    #pragma unroll
    for (int g = 0; g < 16; g++) {
        xp[g] = v[g];
        float xn = (v[g] - mu) * rstd * g1[gi*256 + gl*16 + g] + be1[gi*256 + gl*16 + g];
        xh[g] = __float2half(xn);
    }
    if (tid == 0) g_xm[bt] = mu;
}

__global__ void period_kernel() {
    __shared__ float sx[168], sd[168], sac[168];
    __shared__ float smean;
    int b = blockIdx.x, tid = threadIdx.x;
    if (tid < 168) sx[tid] = g_xm[b*168 + tid];
    __syncthreads();
    if (tid < 168) {
        float s = 0.f;
        #pragma unroll
        for (int o = -12; o <= 12; o++) {
            int u = tid + o; u = u < 0 ? 0 : (u > 167 ? 167 : u);
            s += sx[u];
        }
        sd[tid] = sx[tid] - s * (1.0f/25.0f);
    }
    __syncthreads();
    if (tid == 0) {
        float s = 0.f;
        for (int t = 0; t < 168; t++) s += sd[t];
        smean = s / 168.0f;
    }
    __syncthreads();
    if (tid < 168) sd[tid] -= smean;
    __syncthreads();
    if (tid < 168) {
        float a = 0.f;
        for (int t = 0; t + tid < 168; t++) a += sd[t] * sd[t + tid];
        sac[tid] = (tid < 2) ? -1e9f : a;
    }
    __syncthreads();
    if (tid == 0) {
        bool used[168];
        for (int t = 0; t < 168; t++) used[t] = false;
        for (int r = 0; r < 4; r++) {
            int bi = 0; float bv = -1e30f;
            for (int t = 0; t < 168; t++)
                if (!used[t] && sac[t] > bv) { bv = sac[t]; bi = t; }
            used[bi] = true;
            g_periods[b*4 + r] = bi;
        }
    }
}

// LayerNorm2: fp32 in -> fp16 out
__global__ void __launch_bounds__(256) ln_kernel(const float* __restrict__ x,
                                                 const float* __restrict__ gw,
                                                 const float* __restrict__ bw,
                                                 __half* __restrict__ o16) {
    __shared__ float srow[DD];
    __shared__ float red[8];
    int row = blockIdx.x, tid = threadIdx.x;
    const float* xp = x + (size_t)row * DD;
    float s = 0.f;
    for (int o = tid; o < DD; o += 256) { float v = xp[o]; srow[o] = v; s += v; }
    s = blockReduceSum(s, red);
    float mu = s * (1.0f/DD);
    float vs = 0.f;
    for (int o = tid; o < DD; o += 256) { float d = srow[o]-mu; vs += d*d; }
    vs = blockReduceSum(vs, red);
    float rstd = rsqrtf(vs * (1.0f/DD) + 1e-5f);
    __half* op = o16 + (size_t)row * DD;
    for (int o = tid; o < DD; o += 256)
        op[o] = __float2half((srow[o]-mu) * rstd * gw[o] + bw[o]);
}

// ---------------- period-sparse attention, float4, fp16 out ----------------
__global__ void __launch_bounds__(256) attn_kernel() {
    __shared__ float4 sq4[256];
    __shared__ float sc[168];
    __shared__ float red[8];
    int i = blockIdx.x, h = blockIdx.y, b = blockIdx.z;
    int tid = threadIdx.x;
    int p = g_periods[b*4 + h]; if (p < 1) p = 1;
    int nm = i/p + 1;
    size_t qb = ((size_t)(b*TT + i))*DD + h*HDIM;
    sq4[tid] = ((const float4*)(g_q + qb))[tid];
    __syncthreads();
    int w = tid >> 5, lane = tid & 31;
    for (int m = w; m < nm; m += 8) {
        int j = i - m*p;
        const float4* kp4 = (const float4*)(g_k + ((size_t)(b*TT + j))*DD + h*HDIM);
        float s = 0.f;
        for (int d = lane; d < 256; d += 32) {
            float4 a = sq4[d], bb = kp4[d];
            s += a.x*bb.x + a.y*bb.y + a.z*bb.z + a.w*bb.w;
        }
        #pragma unroll
        for (int o = 16; o > 0; o >>= 1) s += __shfl_xor_sync(0xffffffffu, s, o);
        if (lane == 0) sc[m] = s * 0.03125f;
    }
    __syncthreads();
    float mx = -1e30f;
    for (int m = tid; m < nm; m += 256) mx = fmaxf(mx, sc[m]);
    #pragma unroll
    for (int o = 16; o > 0; o >>= 1) mx = fmaxf(mx, __shfl_xor_sync(0xffffffffu, mx, o));
    if (lane == 0) red[w] = mx;
    __syncthreads();
    if (tid < 32) {
        float t = (tid < 8) ? red[tid] : -1e30f;
        #pragma unroll
        for (int o = 4; o > 0; o >>= 1) t = fmaxf(t, __shfl_xor_sync(0xffffffffu, t, o));
        if (tid == 0) red[0] = t;
    }
    __syncthreads();
    mx = red[0];
    __syncthreads();
    float sum = 0.f;
    for (int m = tid; m < nm; m += 256) { float e = expf(sc[m]-mx); sc[m] = e; sum += e; }
    sum = blockReduceSum(sum, red);
    float inv = 1.0f/sum;
    float4 av = make_float4(0.f, 0.f, 0.f, 0.f);
    for (int m = 0; m < nm; m++) {
        int j = i - m*p;
        float4 vv = ((const float4*)(g_v + ((size_t)(b*TT + j))*DD + h*HDIM))[tid];
        float wgt = sc[m];
        av.x += wgt*vv.x; av.y += wgt*vv.y; av.z += wgt*vv.z; av.w += wgt*vv.w;
    }
    av.x *= inv; av.y *= inv; av.z *= inv; av.w *= inv;
    __half h0 = __float2half(av.x), h1 = __float2half(av.y);
    __half h2 = __float2half(av.z), h3 = __float2half(av.w);
    uint2 u2;
    u2.x = ((uint32_t)__half_as_ushort(h1) << 16) | __half_as_ushort(h0);
    u2.y = ((uint32_t)__half_as_ushort(h3) << 16) | __half_as_ushort(h2);
    *(uint2*)(g_ao16 + qb + (size_t)tid * 4) = u2;
}

__global__ void periods_out_kernel(float* dst) {
    int t = threadIdx.x;
    if (t < 16) dst[t] = (float)g_periods[t];
}

// ---------------- launch ----------------
extern "C" void kernel_launch(void* const* d_in, const int* in_sizes, int n_in,
                              void* d_out, int out_size) {
    const float* M     = (const float*)d_in[0];
    const float* L_o   = (const float*)d_in[1];
    const float* L_d   = (const float*)d_in[2];
    const float* theta = (const float*)d_in[3];
    const float* Wop   = (const float*)d_in[4];
    const float* bop   = (const float*)d_in[5];
    const float* Wdp   = (const float*)d_in[6];
    const float* bdp   = (const float*)d_in[7];
    const float* Wos   = (const float*)d_in[8];
    const float* bos   = (const float*)d_in[9];
    const float* Wds   = (const float*)d_in[10];
    const float* bds   = (const float*)d_in[11];
    const float* Wq    = (const float*)d_in[12];
    const float* bq    = (const float*)d_in[13];
    const float* Wk    = (const float*)d_in[14];
    const float* bk    = (const float*)d_in[15];
    const float* Wv    = (const float*)d_in[16];
    const float* bv    = (const float*)d_in[17];
    const float* Wo    = (const float*)d_in[18];
    const float* bo    = (const float*)d_in[19];
    const float* W1    = (const float*)d_in[20];
    const float* b1    = (const float*)d_in[21];
    const float* W2    = (const float*)d_in[22];
    const float* b2    = (const float*)d_in[23];
    const float* g1    = (const float*)d_in[24];
    const float* be1   = (const float*)d_in[25];
    const float* g2    = (const float*)d_in[26];
    const float* be2   = (const float*)d_in[27];
    float* out = (float*)d_out;

    float *p_x, *p_q, *p_k, *p_v;
    __half *p_w16, *p_xn16, *p_ao16, *p_y16, *p_f16;
    cudaGetSymbolAddress((void**)&p_x,   g_x);
    cudaGetSymbolAddress((void**)&p_q,   g_q);
    cudaGetSymbolAddress((void**)&p_k,   g_k);
    cudaGetSymbolAddress((void**)&p_v,   g_v);
    cudaGetSymbolAddress((void**)&p_w16, g_w16);
    cudaGetSymbolAddress((void**)&p_xn16,g_xn16);
    cudaGetSymbolAddress((void**)&p_ao16,g_ao16);
    cudaGetSymbolAddress((void**)&p_y16, g_y16);
    cudaGetSymbolAddress((void**)&p_f16, g_f16);

    cudaFuncSetAttribute(gemm_fp16,     cudaFuncAttributeMaxDynamicSharedMemorySize, H_SMEM);
    cudaFuncSetAttribute(gemm_fp16_qkv, cudaFuncAttributeMaxDynamicSharedMemorySize, H_SMEM);

    convert_all_kernel<<<49152, 256>>>(Wq, Wk, Wv, Wo, W1, W2);                  // 1
    prep_kernel<<<16, 256>>>(L_o, L_d, Wop, bop, Wos, bos, Wdp, bdp, Wds, bds);  // 2
    gcnod_kernel<<<BT, 256>>>(M, theta, g1, be1);                                // 3
    gemm_fp16_qkv<<<dim3(6, 32, 3), 256, H_SMEM>>>(p_xn16, p_w16,
                                                   bq, bk, bv, p_q, p_k, p_v);   // 4 <- ncu slot
    period_kernel<<<BB, 192>>>();                                                // 5
    dim3 gA(TT, HH, BB);
    attn_kernel<<<gA, 256>>>();                                                  // 6

    gemm_fp16<<<dim3(6, 32), 256, H_SMEM>>>(p_ao16, p_w16 + OFFO, bo, p_x,
                                            p_x, (__half*)0, BT, DD, DD, 1);
    ln_kernel<<<BT, 256>>>(p_x, g2, be2, p_y16);
    gemm_fp16<<<dim3(6, 128), 256, H_SMEM>>>(p_y16, p_w16 + OFFH1, b1, (const float*)0,
                                             (float*)0, p_f16, BT, DFF, DD, 2);
    gemm_fp16<<<dim3(6, 32), 256, H_SMEM>>>(p_f16, p_w16 + OFFH2, b2, p_x,
                                            out, (__half*)0, BT, DD, DFF, 1);

    if (out_size >= BT*DD + 16) {
        periods_out_kernel<<<1, 32>>>(out + (size_t)BT*DD);
    }
}

// round 14
// speedup vs baseline: 3.3018x; 1.1099x over previous
#include <cuda_runtime.h>
#include <cuda_fp16.h>
#include <mma.h>
#include <cstdint>
#include <math.h>

using namespace nvcuda;

#define BB 4
#define TT 168
#define BT 672
#define DD 4096
#define HH 4
#define HDIM 1024
#define DFF 16384

// weights stay [K,N] fp16, concatenated: Wq,Wk,Wv,Wo,W1,W2
#define OFFQ  0ul
#define OFFK  16777216ul
#define OFFV  33554432ul
#define OFFO  50331648ul
#define OFFH1 67108864ul
#define OFFH2 134217728ul
#define WELEM 201326592ul

__device__ __half g_w16[WELEM];

__device__ float g_To[768], g_Td[768];
__device__ float g_Wos2[4096], g_Wds2[4096], g_bos2[16], g_bds2[16];
__device__ float g_x[BT * DD];
__device__ float g_xm[BT];
__device__ float g_q[BT * DD], g_k[BT * DD], g_v[BT * DD];
__device__ int   g_periods[BB * HH];
__device__ __half g_xn16[BT * DD];
__device__ __half g_ao16[BT * DD];
__device__ __half g_y16[BT * DD];
__device__ __half g_f16[(size_t)BT * DFF];

__device__ __forceinline__ float blockReduceSum(float v, float* red) {
    int tid = threadIdx.x;
    #pragma unroll
    for (int o = 16; o > 0; o >>= 1) v += __shfl_xor_sync(0xffffffffu, v, o);
    if ((tid & 31) == 0) red[tid >> 5] = v;
    __syncthreads();
    if (tid < 32) {
        float t = (tid < 8) ? red[tid] : 0.0f;
        #pragma unroll
        for (int o = 4; o > 0; o >>= 1) t += __shfl_xor_sync(0xffffffffu, t, o);
        if (tid == 0) red[0] = t;
    }
    __syncthreads();
    float r = red[0];
    __syncthreads();
    return r;
}

__device__ __forceinline__ void cpa16(uint32_t dst, const void* src, int srcsz) {
    asm volatile("cp.async.cg.shared.global [%0], [%1], 16, %2;"
                 :: "r"(dst), "l"(src), "r"(srcsz) : "memory");
}
__device__ __forceinline__ void cpa_commit() { asm volatile("cp.async.commit_group;" ::: "memory"); }
template<int N>
__device__ __forceinline__ void cpa_wait() { asm volatile("cp.async.wait_group %0;" :: "n"(N) : "memory"); }

// ---------------- weight convert: pure streaming fp32 -> fp16, no transpose ----------------
__global__ void __launch_bounds__(256) convert_all_kernel(
    const float* __restrict__ Wq, const float* __restrict__ Wk,
    const float* __restrict__ Wv, const float* __restrict__ Wo,
    const float* __restrict__ W1, const float* __restrict__ W2)
{
    size_t idx = ((size_t)blockIdx.x * 256 + threadIdx.x) * 8;
    if (idx >= WELEM) return;
    const float* src;
    size_t base;
    if      (idx < OFFK)  { src = Wq; base = OFFQ;  }
    else if (idx < OFFV)  { src = Wk; base = OFFK;  }
    else if (idx < OFFO)  { src = Wv; base = OFFV;  }
    else if (idx < OFFH1) { src = Wo; base = OFFO;  }
    else if (idx < OFFH2) { src = W1; base = OFFH1; }
    else                  { src = W2; base = OFFH2; }
    const float* p = src + (idx - base);
    float4 a = *(const float4*)p;
    float4 b = *(const float4*)(p + 4);
    uint4 o;
    uint32_t* oo = (uint32_t*)&o;
    __half h0 = __float2half(a.x), h1 = __float2half(a.y);
    __half h2 = __float2half(a.z), h3 = __float2half(a.w);
    __half h4 = __float2half(b.x), h5 = __float2half(b.y);
    __half h6 = __float2half(b.z), h7 = __float2half(b.w);
    oo[0] = ((uint32_t)__half_as_ushort(h1) << 16) | __half_as_ushort(h0);
    oo[1] = ((uint32_t)__half_as_ushort(h3) << 16) | __half_as_ushort(h2);
    oo[2] = ((uint32_t)__half_as_ushort(h5) << 16) | __half_as_ushort(h4);
    oo[3] = ((uint32_t)__half_as_ushort(h7) << 16) | __half_as_ushort(h6);
    *(uint4*)(g_w16 + idx) = o;
}

// ---------------- fp16 GEMM, tile 128x128, K-chunk 64, B row-major [K,N] ----------------
#define PADA 72
#define PADB 136
#define H_A  0
#define H_Bo (128 * PADA)
#define H_STAGE (128 * PADA + 64 * PADB)
#define H_BYT (H_STAGE * 2)
#define H_SMEM (2 * H_BYT)

__device__ __forceinline__ void issue_stage_h(
    uint32_t sb, const __half* __restrict__ A, const __half* __restrict__ B,
    int bm, int bn, int k0, int K, int Nc, int Mr, int tid)
{
    // A: 128 rows x 64 halves = 1024 x 16B
    #pragma unroll
    for (int t = 0; t < 4; t++) {
        int u = tid + t * 256;
        int row = u >> 3, q = u & 7;
        int m = bm + row;
        int ok = (m < Mr) ? 16 : 0;
        size_t g = (size_t)(m < Mr ? m : 0) * K + k0 + q * 8;
        cpa16(sb + (H_A + row * PADA + q * 8) * 2, A + g, ok);
    }
    // B: 64 K-rows x 128 halves = 1024 x 16B, contiguous 256B rows
    #pragma unroll
    for (int t = 0; t < 4; t++) {
        int u = tid + t * 256;
        int row = u >> 4, q = u & 15;
        size_t g = (size_t)(k0 + row) * Nc + bn + q * 8;
        cpa16(sb + (H_Bo + row * PADB + q * 8) * 2, B + g, 16);
    }
}

// EPI: 0 = bias -> fp32 C ; 1 = bias+res -> fp32 C ; 2 = gelu(bias) -> fp16 Ch
__device__ __forceinline__ void gemm_h_body(
    const __half* __restrict__ A, const __half* __restrict__ B,
    const float* __restrict__ bias, const float* __restrict__ res,
    float* __restrict__ C, __half* __restrict__ Ch,
    int Mr, int Nc, int K, int EPI)
{
    extern __shared__ char dsm[];
    uint32_t sbase = (uint32_t)__cvta_generic_to_shared(dsm);
    __half* sm = (__half*)dsm;

    int tid = threadIdx.x, wid = tid >> 5, lane = tid & 31;
    int bm = blockIdx.x * 128, bn = blockIdx.y * 128;
    int wm = (wid >> 2) * 64, wn = (wid & 3) * 32;

    wmma::fragment<wmma::accumulator, 16, 16, 16, float> acc[4][2];
    #pragma unroll
    for (int i = 0; i < 4; i++)
        #pragma unroll
        for (int j = 0; j < 2; j++) wmma::fill_fragment(acc[i][j], 0.0f);

    int KC = K >> 6;
    issue_stage_h(sbase, A, B, bm, bn, 0, K, Nc, Mr, tid);
    cpa_commit();

    for (int kc = 0; kc < KC; kc++) {
        int cur = kc & 1;
        if (kc + 1 < KC) {
            issue_stage_h(sbase + ((kc + 1) & 1) * H_BYT, A, B, bm, bn, (kc + 1) * 64, K, Nc, Mr, tid);
            cpa_commit();
            cpa_wait<1>();
        } else {
            cpa_wait<0>();
        }
        __syncthreads();
        const __half* S = sm + cur * H_STAGE;
        #pragma unroll
        for (int kk = 0; kk < 64; kk += 16) {
            wmma::fragment<wmma::matrix_b, 16, 16, 16, __half, wmma::row_major> fb[2];
            #pragma unroll
            for (int j = 0; j < 2; j++)
                wmma::load_matrix_sync(fb[j], S + H_Bo + kk * PADB + wn + 16 * j, PADB);
            #pragma unroll
            for (int i = 0; i < 4; i++) {
                wmma::fragment<wmma::matrix_a, 16, 16, 16, __half, wmma::row_major> fa;
                wmma::load_matrix_sync(fa, S + H_A + (wm + 16 * i) * PADA + kk, PADA);
                #pragma unroll
                for (int j = 0; j < 2; j++)
                    wmma::mma_sync(acc[i][j], fa, fb[j], acc[i][j]);
            }
        }
        __syncthreads();
    }

    float* fst = (float*)dsm + wid * 256;
    int r = lane >> 1, cs = (lane & 1) * 8;
    #pragma unroll
    for (int i = 0; i < 4; i++)
        #pragma unroll
        for (int j = 0; j < 2; j++) {
            wmma::store_matrix_sync(fst, acc[i][j], 16, wmma::mem_row_major);
            __syncwarp();
            int m = bm + wm + 16 * i + r;
            int col0 = bn + wn + 16 * j + cs;
            if (m < Mr) {
                float v[8];
                #pragma unroll
                for (int c = 0; c < 8; c++) v[c] = fst[r * 16 + cs + c] + bias[col0 + c];
                if (EPI == 2) {
                    uint4 p;
                    uint32_t* pp = (uint32_t*)&p;
                    #pragma unroll
                    for (int c = 0; c < 4; c++) {
                        float a0 = v[2*c],   q0 = 0.5f * a0 * (1.0f + erff(a0 * 0.7071067811865475f));
                        float a1 = v[2*c+1], q1 = 0.5f * a1 * (1.0f + erff(a1 * 0.7071067811865475f));
                        __half h0 = __float2half(q0), h1 = __float2half(q1);
                        pp[c] = ((uint32_t)__half_as_ushort(h1) << 16) | __half_as_ushort(h0);
                    }
                    *(uint4*)(Ch + (size_t)m * Nc + col0) = p;
                } else {
                    if (EPI == 1) {
                        const float* rp = res + (size_t)m * Nc + col0;
                        #pragma unroll
                        for (int c = 0; c < 8; c++) v[c] += rp[c];
                    }
                    float4 o0, o1;
                    o0.x = v[0]; o0.y = v[1]; o0.z = v[2]; o0.w = v[3];
                    o1.x = v[4]; o1.y = v[5]; o1.z = v[6]; o1.w = v[7];
                    *(float4*)(C + (size_t)m * Nc + col0) = o0;
                    *(float4*)(C + (size_t)m * Nc + col0 + 4) = o1;
                }
            }
            __syncwarp();
        }
}

__global__ void __launch_bounds__(256, 2) gemm_fp16(
    const __half* A, const __half* B,
    const float* bias, const float* res,
    float* C, __half* Ch, int Mr, int Nc, int K, int EPI)
{
    gemm_h_body(A, B, bias, res, C, Ch, Mr, Nc, K, EPI);
}

__global__ void __launch_bounds__(256, 2) gemm_fp16_qkv(
    const __half* A, const __half* w16,
    const float* bq, const float* bk, const float* bv,
    float* q, float* k, float* v)
{
    int z = blockIdx.z;
    size_t off = (size_t)z * 16777216ul;
    const float* bias = (z == 0) ? bq : (z == 1) ? bk : bv;
    float* C = (z == 0) ? q : (z == 1) ? k : v;
    gemm_h_body(A, w16 + off, bias, (const float*)0, C, (__half*)0, BT, DD, DD, 0);
}

// ---------------- merged prep ----------------
__global__ void prep_kernel(const float* __restrict__ Lo, const float* __restrict__ Ld,
                            const float* __restrict__ Wop, const float* __restrict__ bop,
                            const float* __restrict__ Wos, const float* __restrict__ bos,
                            const float* __restrict__ Wdp, const float* __restrict__ bdp,
                            const float* __restrict__ Wds, const float* __restrict__ bds) {
    int tid = threadIdx.x;
    if (blockIdx.x == 0) {
        int i = tid >> 4, j = tid & 15;
        float id = (i == j) ? 1.0f : 0.0f;
        float a = 0.f, b = 0.f;
        for (int k = 0; k < 16; k++) { a += Lo[i*16+k]*Lo[k*16+j]; b += Ld[i*16+k]*Ld[k*16+j]; }
        g_To[tid] = id; g_To[256+tid] = Lo[tid]; g_To[512+tid] = 2.f*a - id;
        g_Td[tid] = id; g_Td[256+tid] = Ld[tid]; g_Td[512+tid] = 2.f*b - id;
    }
    int idx = blockIdx.x * 256 + tid;
    int kf = idx >> 4, n = idx & 15;
    float a = 0.f, b = 0.f;
    for (int h = 0; h < 512; h++) {
        a += Wop[kf*512+h] * Wos[h*16+n];
        b += Wdp[kf*512+h] * Wds[h*16+n];
    }
    g_Wos2[idx] = a; g_Wds2[idx] = b;
    if (idx < 16) {
        float c = bos[idx], d = bds[idx];
        for (int h = 0; h < 512; h++) { c += bop[h]*Wos[h*16+idx]; d += bdp[h]*Wds[h*16+idx]; }
        g_bos2[idx] = c; g_bds2[idx] = d;
    }
}

// ---------------- GCN + OD + combine + fused LayerNorm1 (fp16 xn out) ----------------
__global__ void __launch_bounds__(256) gcnod_kernel(const float* __restrict__ M,
                                                    const float* __restrict__ theta,
                                                    const float* __restrict__ g1,
                                                    const float* __restrict__ be1) {
    __shared__ float sM[4096], sR[4096], sTh[2304];
    __shared__ float sScore[256], sPo[256], sPd[256], st2[512];
    __shared__ float sEnt[16], sRed[8];
    __shared__ int   sSel[4];
    int bt = blockIdx.x, tid = threadIdx.x;
    const float* Mp = M + (size_t)bt * 4096;
    for (int o = tid; o < 4096; o += 256) sM[o] = Mp[o];
    for (int o = tid; o < 2304; o += 256) sTh[o] = theta[o];
    __syncthreads();
    {
        int i = tid >> 4, n = tid & 15;
        const float* xr = sM + i * 256;
        float a = g_bos2[n];
        for (int kf = 0; kf < 256; kf++) a += xr[kf] * g_Wos2[kf*16+n];
        sScore[tid] = a;
    }
    __syncthreads();
    if (tid < 16) {
        float mx = -1e30f;
        #pragma unroll
        for (int n = 0; n < 16; n++) mx = fmaxf(mx, sScore[tid*16+n]);
        float e[16], s = 0.f;
        #pragma unroll
        for (int n = 0; n < 16; n++) { e[n] = expf(sScore[tid*16+n]-mx); s += e[n]; }
        float inv = 1.f/s, ent = 0.f;
        #pragma unroll
        for (int n = 0; n < 16; n++) { float p = e[n]*inv; sPo[tid*16+n]=p; ent -= p*logf(p+1e-9f); }
        sEnt[tid] = ent;
    }
    __syncthreads();
    if (tid == 0) {
        int i0 = 0;
        for (int t = 1; t < 16; t++) if (sEnt[t] < sEnt[i0]) i0 = t;
        int i1 = (i0 == 0) ? 1 : 0;
        for (int t = 0; t < 16; t++) { if (t == i0) continue; if (sEnt[t] < sEnt[i1]) i1 = t; }
        sSel[0] = i0; sSel[1] = i1;
    }
    {
        int k = tid >> 4, n = tid & 15;
        float a = g_bds2[n];
        for (int jf = 0; jf < 256; jf++)
            a += sM[(jf>>4)*256 + k*16 + (jf&15)] * g_Wds2[jf*16+n];
        __syncthreads();
        sScore[tid] = a;
    }
    __syncthreads();
    if (tid < 16) {
        float mx = -1e30f;
        #pragma unroll
        for (int n = 0; n < 16; n++) mx = fmaxf(mx, sScore[tid*16+n]);
        float e[16], s = 0.f;
        #pragma unroll
        for (int n = 0; n < 16; n++) { e[n] = expf(sScore[tid*16+n]-mx); s += e[n]; }
        float inv = 1.f/s, ent = 0.f;
        #pragma unroll
        for (int n = 0; n < 16; n++) { float p = e[n]*inv; sPd[tid*16+n]=p; ent -= p*logf(p+1e-9f); }
        sEnt[tid] = ent;
    }
    __syncthreads();
    if (tid == 0) {
        int i0 = 0;
        for (int t = 1; t < 16; t++) if (sEnt[t] < sEnt[i0]) i0 = t;
        int i1 = (i0 == 0) ? 1 : 0;
        for (int t = 0; t < 16; t++) { if (t == i0) continue; if (sEnt[t] < sEnt[i1]) i1 = t; }
        sSel[2] = i0; sSel[3] = i1;
    }
    __syncthreads();
    {
        #pragma unroll
        for (int s = 0; s < 2; s++) {
            int ii = sSel[s];
            float a = 0.f;
            for (int j = 0; j < 16; j++) a += sPo[ii*16+j] * sM[j*256 + tid];
            st2[s*256 + tid] = a;
        }
    }
    __syncthreads();
    int gi = tid & 15, gl = tid >> 4;
    float MG[16];
    #pragma unroll
    for (int g = 0; g < 16; g++) MG[g] = 0.f;
    for (int c = 0; c < 3; c++) {
        for (int r = 0; r < 16; r++) {
            int ll = tid >> 4, f = tid & 15;
            float a = 0.f;
            #pragma unroll
            for (int k = 0; k < 16; k++)
                a += sM[(r<<8)+(k<<4)+f] * g_Td[c*256 + (k<<4) + ll];
            sR[(r<<8) + tid] = a;
        }
        __syncthreads();
        for (int a_ = 0; a_ < 3; a_++) {
            float S[16];
            #pragma unroll
            for (int f = 0; f < 16; f++) S[f] = 0.f;
            for (int j = 0; j < 16; j++) {
                float t_ = g_To[a_*256 + (gi<<4) + j];
                const float* rp = sR + (j<<8) + (gl<<4);
                #pragma unroll
                for (int f = 0; f < 16; f++) S[f] += t_ * rp[f];
            }
            const float* th = sTh + (a_*3 + c) * 256;
            #pragma unroll
            for (int f = 0; f < 16; f++) {
                float sv = S[f];
                #pragma unroll
                for (int g = 0; g < 16; g++) MG[g] += sv * th[f*16+g];
            }
        }
        __syncthreads();
    }
    int so = (gi == sSel[0]) ? 0 : ((gi == sSel[1]) ? 1 : -1);
    int sd = (gl == sSel[2]) ? 0 : ((gl == sSel[3]) ? 1 : -1);
    float v[16];
    float lsum = 0.f, lsq = 0.f;
    #pragma unroll
    for (int g = 0; g < 16; g++) {
        float w = 0.5f * MG[g];
        if (so >= 0 && sd >= 0) {
            float ma = 0.f;
            #pragma unroll
            for (int ll = 0; ll < 16; ll++)
                ma += st2[so*256 + g*16 + ll] * sPd[gl*16 + ll];
            w += 0.5f * ma;
        }
        v[g] = w;
        lsum += w;
        lsq += w * w;
    }
    float tot = blockReduceSum(lsum, sRed);
    float sqt = blockReduceSum(lsq, sRed);
    float mu = tot * (1.0f/4096.0f);
    float var = sqt * (1.0f/4096.0f) - mu * mu;
    float rstd = rsqrtf(var + 1e-5f);
    size_t base = (size_t)bt*4096 + gi*256 + gl*16;
    float* xp = g_x + base;
    __half* xh = g_xn16 + base;
    #pragma unroll
    for (int g = 0; g < 16; g++) {
        xp[g] = v[g];
        float xn = (v[g] - mu) * rstd * g1[gi*256 + gl*16 + g] + be1[gi*256 + gl*16 + g];
        xh[g] = __float2half(xn);
    }
    if (tid == 0) g_xm[bt] = mu;
}

__global__ void period_kernel() {
    __shared__ float sx[168], sd[168], sac[168];
    __shared__ float smean;
    int b = blockIdx.x, tid = threadIdx.x;
    if (tid < 168) sx[tid] = g_xm[b*168 + tid];
    __syncthreads();
    if (tid < 168) {
        float s = 0.f;
        #pragma unroll
        for (int o = -12; o <= 12; o++) {
            int u = tid + o; u = u < 0 ? 0 : (u > 167 ? 167 : u);
            s += sx[u];
        }
        sd[tid] = sx[tid] - s * (1.0f/25.0f);
    }
    __syncthreads();
    if (tid == 0) {
        float s = 0.f;
        for (int t = 0; t < 168; t++) s += sd[t];
        smean = s / 168.0f;
    }
    __syncthreads();
    if (tid < 168) sd[tid] -= smean;
    __syncthreads();
    if (tid < 168) {
        float a = 0.f;
        for (int t = 0; t + tid < 168; t++) a += sd[t] * sd[t + tid];
        sac[tid] = (tid < 2) ? -1e9f : a;
    }
    __syncthreads();
    if (tid == 0) {
        bool used[168];
        for (int t = 0; t < 168; t++) used[t] = false;
        for (int r = 0; r < 4; r++) {
            int bi = 0; float bv = -1e30f;
            for (int t = 0; t < 168; t++)
                if (!used[t] && sac[t] > bv) { bv = sac[t]; bi = t; }
            used[bi] = true;
            g_periods[b*4 + r] = bi;
        }
    }
}

// LayerNorm2: fp32 in -> fp16 out
__global__ void __launch_bounds__(256) ln_kernel(const float* __restrict__ x,
                                                 const float* __restrict__ gw,
                                                 const float* __restrict__ bw,
                                                 __half* __restrict__ o16) {
    __shared__ float srow[DD];
    __shared__ float red[8];
    int row = blockIdx.x, tid = threadIdx.x;
    const float* xp = x + (size_t)row * DD;
    float s = 0.f;
    for (int o = tid; o < DD; o += 256) { float v = xp[o]; srow[o] = v; s += v; }
    s = blockReduceSum(s, red);
    float mu = s * (1.0f/DD);
    float vs = 0.f;
    for (int o = tid; o < DD; o += 256) { float d = srow[o]-mu; vs += d*d; }
    vs = blockReduceSum(vs, red);
    float rstd = rsqrtf(vs * (1.0f/DD) + 1e-5f);
    __half* op = o16 + (size_t)row * DD;
    for (int o = tid; o < DD; o += 256)
        op[o] = __float2half((srow[o]-mu) * rstd * gw[o] + bw[o]);
}

// ---------------- period-sparse attention, float4, fp16 out ----------------
__global__ void __launch_bounds__(256) attn_kernel() {
    __shared__ float4 sq4[256];
    __shared__ float sc[168];
    __shared__ float red[8];
    int i = blockIdx.x, h = blockIdx.y, b = blockIdx.z;
    int tid = threadIdx.x;
    int p = g_periods[b*4 + h]; if (p < 1) p = 1;
    int nm = i/p + 1;
    size_t qb = ((size_t)(b*TT + i))*DD + h*HDIM;
    sq4[tid] = ((const float4*)(g_q + qb))[tid];
    __syncthreads();
    int w = tid >> 5, lane = tid & 31;
    for (int m = w; m < nm; m += 8) {
        int j = i - m*p;
        const float4* kp4 = (const float4*)(g_k + ((size_t)(b*TT + j))*DD + h*HDIM);
        float s = 0.f;
        for (int d = lane; d < 256; d += 32) {
            float4 a = sq4[d], bb = kp4[d];
            s += a.x*bb.x + a.y*bb.y + a.z*bb.z + a.w*bb.w;
        }
        #pragma unroll
        for (int o = 16; o > 0; o >>= 1) s += __shfl_xor_sync(0xffffffffu, s, o);
        if (lane == 0) sc[m] = s * 0.03125f;
    }
    __syncthreads();
    float mx = -1e30f;
    for (int m = tid; m < nm; m += 256) mx = fmaxf(mx, sc[m]);
    #pragma unroll
    for (int o = 16; o > 0; o >>= 1) mx = fmaxf(mx, __shfl_xor_sync(0xffffffffu, mx, o));
    if (lane == 0) red[w] = mx;
    __syncthreads();
    if (tid < 32) {
        float t = (tid < 8) ? red[tid] : -1e30f;
        #pragma unroll
        for (int o = 4; o > 0; o >>= 1) t = fmaxf(t, __shfl_xor_sync(0xffffffffu, t, o));
        if (tid == 0) red[0] = t;
    }
    __syncthreads();
    mx = red[0];
    __syncthreads();
    float sum = 0.f;
    for (int m = tid; m < nm; m += 256) { float e = expf(sc[m]-mx); sc[m] = e; sum += e; }
    sum = blockReduceSum(sum, red);
    float inv = 1.0f/sum;
    float4 av = make_float4(0.f, 0.f, 0.f, 0.f);
    for (int m = 0; m < nm; m++) {
        int j = i - m*p;
        float4 vv = ((const float4*)(g_v + ((size_t)(b*TT + j))*DD + h*HDIM))[tid];
        float wgt = sc[m];
        av.x += wgt*vv.x; av.y += wgt*vv.y; av.z += wgt*vv.z; av.w += wgt*vv.w;
    }
    av.x *= inv; av.y *= inv; av.z *= inv; av.w *= inv;
    __half h0 = __float2half(av.x), h1 = __float2half(av.y);
    __half h2 = __float2half(av.z), h3 = __float2half(av.w);
    uint2 u2;
    u2.x = ((uint32_t)__half_as_ushort(h1) << 16) | __half_as_ushort(h0);
    u2.y = ((uint32_t)__half_as_ushort(h3) << 16) | __half_as_ushort(h2);
    *(uint2*)(g_ao16 + qb + (size_t)tid * 4) = u2;
}

__global__ void periods_out_kernel(float* dst) {
    int t = threadIdx.x;
    if (t < 16) dst[t] = (float)g_periods[t];
}

// ---------------- launch ----------------
extern "C" void kernel_launch(void* const* d_in, const int* in_sizes, int n_in,
                              void* d_out, int out_size) {
    const float* M     = (const float*)d_in[0];
    const float* L_o   = (const float*)d_in[1];
    const float* L_d   = (const float*)d_in[2];
    const float* theta = (const float*)d_in[3];
    const float* Wop   = (const float*)d_in[4];
    const float* bop   = (const float*)d_in[5];
    const float* Wdp   = (const float*)d_in[6];
    const float* bdp   = (const float*)d_in[7];
    const float* Wos   = (const float*)d_in[8];
    const float* bos   = (const float*)d_in[9];
    const float* Wds   = (const float*)d_in[10];
    const float* bds   = (const float*)d_in[11];
    const float* Wq    = (const float*)d_in[12];
    const float* bq    = (const float*)d_in[13];
    const float* Wk    = (const float*)d_in[14];
    const float* bk    = (const float*)d_in[15];
    const float* Wv    = (const float*)d_in[16];
    const float* bv    = (const float*)d_in[17];
    const float* Wo    = (const float*)d_in[18];
    const float* bo    = (const float*)d_in[19];
    const float* W1    = (const float*)d_in[20];
    const float* b1    = (const float*)d_in[21];
    const float* W2    = (const float*)d_in[22];
    const float* b2    = (const float*)d_in[23];
    const float* g1    = (const float*)d_in[24];
    const float* be1   = (const float*)d_in[25];
    const float* g2    = (const float*)d_in[26];
    const float* be2   = (const float*)d_in[27];
    float* out = (float*)d_out;

    float *p_x, *p_q, *p_k, *p_v;
    __half *p_w16, *p_xn16, *p_ao16, *p_y16, *p_f16;
    cudaGetSymbolAddress((void**)&p_x,   g_x);
    cudaGetSymbolAddress((void**)&p_q,   g_q);
    cudaGetSymbolAddress((void**)&p_k,   g_k);
    cudaGetSymbolAddress((void**)&p_v,   g_v);
    cudaGetSymbolAddress((void**)&p_w16, g_w16);
    cudaGetSymbolAddress((void**)&p_xn16,g_xn16);
    cudaGetSymbolAddress((void**)&p_ao16,g_ao16);
    cudaGetSymbolAddress((void**)&p_y16, g_y16);
    cudaGetSymbolAddress((void**)&p_f16, g_f16);

    cudaFuncSetAttribute(gemm_fp16,     cudaFuncAttributeMaxDynamicSharedMemorySize, H_SMEM);
    cudaFuncSetAttribute(gemm_fp16_qkv, cudaFuncAttributeMaxDynamicSharedMemorySize, H_SMEM);

    convert_all_kernel<<<98304, 256>>>(Wq, Wk, Wv, Wo, W1, W2);                  // 1
    prep_kernel<<<16, 256>>>(L_o, L_d, Wop, bop, Wos, bos, Wdp, bdp, Wds, bds);  // 2
    gcnod_kernel<<<BT, 256>>>(M, theta, g1, be1);                                // 3
    gemm_fp16_qkv<<<dim3(6, 32, 3), 256, H_SMEM>>>(p_xn16, p_w16,
                                                   bq, bk, bv, p_q, p_k, p_v);   // 4 <- ncu slot
    period_kernel<<<BB, 192>>>();                                                // 5
    dim3 gA(TT, HH, BB);
    attn_kernel<<<gA, 256>>>();                                                  // 6

    gemm_fp16<<<dim3(6, 32), 256, H_SMEM>>>(p_ao16, p_w16 + OFFO, bo, p_x,
                                            p_x, (__half*)0, BT, DD, DD, 1);
    ln_kernel<<<BT, 256>>>(p_x, g2, be2, p_y16);
    gemm_fp16<<<dim3(6, 128), 256, H_SMEM>>>(p_y16, p_w16 + OFFH1, b1, (const float*)0,
                                             (float*)0, p_f16, BT, DFF, DD, 2);
    gemm_fp16<<<dim3(6, 32), 256, H_SMEM>>>(p_f16, p_w16 + OFFH2, b2, p_x,
                                            out, (__half*)0, BT, DD, DFF, 1);

    if (out_size >= BT*DD + 16) {
        periods_out_kernel<<<1, 32>>>(out + (size_t)BT*DD);
    }
}

// round 16
// speedup vs baseline: 3.4118x; 1.0333x over previous
#include <cuda_runtime.h>
#include <cuda_fp16.h>
#include <mma.h>
#include <cstdint>
#include <math.h>

using namespace nvcuda;

#define BB 4
#define TT 168
#define BT 672
#define DD 4096
#define HH 4
#define HDIM 1024
#define DFF 16384

#define OFFQ  0ul
#define OFFK  16777216ul
#define OFFV  33554432ul
#define OFFO  50331648ul
#define OFFH1 67108864ul
#define OFFH2 134217728ul
#define WELEM 201326592ul

__device__ __half g_w16[WELEM];

__device__ float g_To[768], g_Td[768];
__device__ float g_Wos2[4096], g_Wds2[4096], g_bos2[16], g_bds2[16];
__device__ float g_x[BT * DD];
__device__ float g_xm[BT];
__device__ float g_q[BT * DD], g_k[BT * DD], g_v[BT * DD];
__device__ int   g_periods[BB * HH];
__device__ __half g_xn16[BT * DD];
__device__ __half g_ao16[BT * DD];
__device__ __half g_y16[BT * DD];
__device__ __half g_f16[(size_t)BT * DFF];

__device__ __forceinline__ float blockReduceSum(float v, float* red) {
    int tid = threadIdx.x;
    #pragma unroll
    for (int o = 16; o > 0; o >>= 1) v += __shfl_xor_sync(0xffffffffu, v, o);
    if ((tid & 31) == 0) red[tid >> 5] = v;
    __syncthreads();
    if (tid < 32) {
        float t = (tid < 8) ? red[tid] : 0.0f;
        #pragma unroll
        for (int o = 4; o > 0; o >>= 1) t += __shfl_xor_sync(0xffffffffu, t, o);
        if (tid == 0) red[0] = t;
    }
    __syncthreads();
    float r = red[0];
    __syncthreads();
    return r;
}

__device__ __forceinline__ void cpa16(uint32_t dst, const void* src, int srcsz) {
    asm volatile("cp.async.cg.shared.global [%0], [%1], 16, %2;"
                 :: "r"(dst), "l"(src), "r"(srcsz) : "memory");
}
__device__ __forceinline__ void cpa_commit() { asm volatile("cp.async.commit_group;" ::: "memory"); }
template<int N>
__device__ __forceinline__ void cpa_wait() { asm volatile("cp.async.wait_group %0;" :: "n"(N) : "memory"); }

// ---------------- weight convert: streaming fp32 -> fp16, split into 2 launches ----------------
__global__ void __launch_bounds__(256) convert_all_kernel(
    const float* __restrict__ Wq, const float* __restrict__ Wk,
    const float* __restrict__ Wv, const float* __restrict__ Wo,
    const float* __restrict__ W1, const float* __restrict__ W2,
    int blk0)
{
    size_t idx = ((size_t)(blockIdx.x + blk0) * 256 + threadIdx.x) * 8;
    if (idx >= WELEM) return;
    const float* src;
    size_t base;
    if      (idx < OFFK)  { src = Wq; base = OFFQ;  }
    else if (idx < OFFV)  { src = Wk; base = OFFK;  }
    else if (idx < OFFO)  { src = Wv; base = OFFV;  }
    else if (idx < OFFH1) { src = Wo; base = OFFO;  }
    else if (idx < OFFH2) { src = W1; base = OFFH1; }
    else                  { src = W2; base = OFFH2; }
    const float* p = src + (idx - base);
    float4 a = *(const float4*)p;
    float4 b = *(const float4*)(p + 4);
    uint4 o;
    uint32_t* oo = (uint32_t*)&o;
    __half h0 = __float2half(a.x), h1 = __float2half(a.y);
    __half h2 = __float2half(a.z), h3 = __float2half(a.w);
    __half h4 = __float2half(b.x), h5 = __float2half(b.y);
    __half h6 = __float2half(b.z), h7 = __float2half(b.w);
    oo[0] = ((uint32_t)__half_as_ushort(h1) << 16) | __half_as_ushort(h0);
    oo[1] = ((uint32_t)__half_as_ushort(h3) << 16) | __half_as_ushort(h2);
    oo[2] = ((uint32_t)__half_as_ushort(h5) << 16) | __half_as_ushort(h4);
    oo[3] = ((uint32_t)__half_as_ushort(h7) << 16) | __half_as_ushort(h6);
    *(uint4*)(g_w16 + idx) = o;
}

// ---------------- fp16 GEMM, tile 128x128, K-chunk 64, B row-major [K,N] ----------------
#define PADA 72
#define PADB 136
#define H_A  0
#define H_Bo (128 * PADA)
#define H_STAGE (128 * PADA + 64 * PADB)
#define H_BYT (H_STAGE * 2)
#define H_SMEM (2 * H_BYT)

__device__ __forceinline__ void issue_stage_h(
    uint32_t sb, const __half* __restrict__ A, const __half* __restrict__ B,
    int bm, int bn, int k0, int K, int Nc, int Mr, int tid)
{
    #pragma unroll
    for (int t = 0; t < 4; t++) {
        int u = tid + t * 256;
        int row = u >> 3, q = u & 7;
        int m = bm + row;
        int ok = (m < Mr) ? 16 : 0;
        size_t g = (size_t)(m < Mr ? m : 0) * K + k0 + q * 8;
        cpa16(sb + (H_A + row * PADA + q * 8) * 2, A + g, ok);
    }
    #pragma unroll
    for (int t = 0; t < 4; t++) {
        int u = tid + t * 256;
        int row = u >> 4, q = u & 15;
        size_t g = (size_t)(k0 + row) * Nc + bn + q * 8;
        cpa16(sb + (H_Bo + row * PADB + q * 8) * 2, B + g, 16);
    }
}

// EPI: 0 = bias -> fp32 ; 1 = bias+res -> fp32 ; 2 = gelu(bias) -> fp16
__device__ __forceinline__ void gemm_h_body(
    const __half* __restrict__ A, const __half* __restrict__ B,
    const float* __restrict__ bias, const float* __restrict__ res,
    float* __restrict__ C, __half* __restrict__ Ch,
    int Mr, int Nc, int K, int EPI)
{
    extern __shared__ char dsm[];
    uint32_t sbase = (uint32_t)__cvta_generic_to_shared(dsm);
    __half* sm = (__half*)dsm;

    int tid = threadIdx.x, wid = tid >> 5, lane = tid & 31;
    int bm = blockIdx.x * 128, bn = blockIdx.y * 128;
    int wm = (wid >> 2) * 64, wn = (wid & 3) * 32;

    wmma::fragment<wmma::accumulator, 16, 16, 16, float> acc[4][2];
    #pragma unroll
    for (int i = 0; i < 4; i++)
        #pragma unroll
        for (int j = 0; j < 2; j++) wmma::fill_fragment(acc[i][j], 0.0f);

    int KC = K >> 6;
    issue_stage_h(sbase, A, B, bm, bn, 0, K, Nc, Mr, tid);
    cpa_commit();

    for (int kc = 0; kc < KC; kc++) {
        int cur = kc & 1;
        if (kc + 1 < KC) {
            issue_stage_h(sbase + ((kc + 1) & 1) * H_BYT, A, B, bm, bn, (kc + 1) * 64, K, Nc, Mr, tid);
            cpa_commit();
            cpa_wait<1>();
        } else {
            cpa_wait<0>();
        }
        __syncthreads();
        const __half* S = sm + cur * H_STAGE;
        #pragma unroll
        for (int kk = 0; kk < 64; kk += 16) {
            wmma::fragment<wmma::matrix_b, 16, 16, 16, __half, wmma::row_major> fb[2];
            #pragma unroll
            for (int j = 0; j < 2; j++)
                wmma::load_matrix_sync(fb[j], S + H_Bo + kk * PADB + wn + 16 * j, PADB);
            #pragma unroll
            for (int i = 0; i < 4; i++) {
                wmma::fragment<wmma::matrix_a, 16, 16, 16, __half, wmma::row_major> fa;
                wmma::load_matrix_sync(fa, S + H_A + (wm + 16 * i) * PADA + kk, PADA);
                #pragma unroll
                for (int j = 0; j < 2; j++)
                    wmma::mma_sync(acc[i][j], fa, fb[j], acc[i][j]);
            }
        }
        __syncthreads();
    }

    float* fst = (float*)dsm + wid * 256;
    int r = lane >> 1, cs = (lane & 1) * 8;
    #pragma unroll
    for (int i = 0; i < 4; i++)
        #pragma unroll
        for (int j = 0; j < 2; j++) {
            wmma::store_matrix_sync(fst, acc[i][j], 16, wmma::mem_row_major);
            __syncwarp();
            int m = bm + wm + 16 * i + r;
            int col0 = bn + wn + 16 * j + cs;
            if (m < Mr) {
                float v[8];
                #pragma unroll
                for (int c = 0; c < 8; c++) v[c] = fst[r * 16 + cs + c] + bias[col0 + c];
                if (EPI == 2) {
                    uint4 p;
                    uint32_t* pp = (uint32_t*)&p;
                    #pragma unroll
                    for (int c = 0; c < 4; c++) {
                        float a0 = v[2*c],   q0 = 0.5f * a0 * (1.0f + erff(a0 * 0.7071067811865475f));
                        float a1 = v[2*c+1], q1 = 0.5f * a1 * (1.0f + erff(a1 * 0.7071067811865475f));
                        __half h0 = __float2half(q0), h1 = __float2half(q1);
                        pp[c] = ((uint32_t)__half_as_ushort(h1) << 16) | __half_as_ushort(h0);
                    }
                    *(uint4*)(Ch + (size_t)m * Nc + col0) = p;
                } else {
                    if (EPI == 1) {
                        const float* rp = res + (size_t)m * Nc + col0;
                        #pragma unroll
                        for (int c = 0; c < 8; c++) v[c] += rp[c];
                    }
                    float4 o0, o1;
                    o0.x = v[0]; o0.y = v[1]; o0.z = v[2]; o0.w = v[3];
                    o1.x = v[4]; o1.y = v[5]; o1.z = v[6]; o1.w = v[7];
                    *(float4*)(C + (size_t)m * Nc + col0) = o0;
                    *(float4*)(C + (size_t)m * Nc + col0 + 4) = o1;
                }
            }
            __syncwarp();
        }
}

__global__ void __launch_bounds__(256, 2) gemm_fp16(
    const __half* A, const __half* B,
    const float* bias, const float* res,
    float* C, __half* Ch, int Mr, int Nc, int K, int EPI)
{
    gemm_h_body(A, B, bias, res, C, Ch, Mr, Nc, K, EPI);
}

__global__ void __launch_bounds__(256, 2) gemm_fp16_qkv(
    const __half* A, const __half* w16,
    const float* bq, const float* bk, const float* bv,
    float* q, float* k, float* v)
{
    int z = blockIdx.z;
    size_t off = (size_t)z * 16777216ul;
    const float* bias = (z == 0) ? bq : (z == 1) ? bk : bv;
    float* C = (z == 0) ? q : (z == 1) ? k : v;
    gemm_h_body(A, w16 + off, bias, (const float*)0, C, (__half*)0, BT, DD, DD, 0);
}

// ---------------- prep: full-chip version ----------------
// grid 128: block b owns 32 entries of (Wos2, Wds2); 8 threads per entry over h.
__global__ void __launch_bounds__(256) prep_kernel(
    const float* __restrict__ Lo, const float* __restrict__ Ld,
    const float* __restrict__ Wop, const float* __restrict__ bop,
    const float* __restrict__ Wos, const float* __restrict__ bos,
    const float* __restrict__ Wdp, const float* __restrict__ bdp,
    const float* __restrict__ Wds, const float* __restrict__ bds)
{
    int tid = threadIdx.x;
    if (blockIdx.x == 0 && tid < 256) {
        int i = tid >> 4, j = tid & 15;
        float id = (i == j) ? 1.0f : 0.0f;
        float a = 0.f, b = 0.f;
        for (int k = 0; k < 16; k++) { a += Lo[i*16+k]*Lo[k*16+j]; b += Ld[i*16+k]*Ld[k*16+j]; }
        g_To[tid] = id; g_To[256+tid] = Lo[tid]; g_To[512+tid] = 2.f*a - id;
        g_Td[tid] = id; g_Td[256+tid] = Ld[tid]; g_Td[512+tid] = 2.f*b - id;
    }
    int ent = blockIdx.x * 32 + (tid >> 3);       // 0..4095
    int sub = tid & 7;                            // h-chunk
    int kf = ent >> 4, n = ent & 15;
    float a = 0.f, b = 0.f;
    for (int h = sub * 64; h < sub * 64 + 64; h++) {
        a += Wop[kf*512+h] * Wos[h*16+n];
        b += Wdp[kf*512+h] * Wds[h*16+n];
    }
    #pragma unroll
    for (int o = 4; o > 0; o >>= 1) {
        a += __shfl_down_sync(0xffffffffu, a, o);
        b += __shfl_down_sync(0xffffffffu, b, o);
    }
    if (sub == 0) { g_Wos2[ent] = a; g_Wds2[ent] = b; }
    if (blockIdx.x == 1 && tid < 16) {
        float c = bos[tid], d = bds[tid];
        for (int h = 0; h < 512; h++) { c += bop[h]*Wos[h*16+tid]; d += bdp[h]*Wds[h*16+tid]; }
        g_bos2[tid] = c; g_bds2[tid] = d;
    }
}

// ---------------- GCN + OD + combine + fused LayerNorm1 (fp16 xn out) ----------------
__global__ void __launch_bounds__(256) gcnod_kernel(const float* __restrict__ M,
                                                    const float* __restrict__ theta,
                                                    const float* __restrict__ g1,
                                                    const float* __restrict__ be1) {
    __shared__ float sM[4096], sR[4096], sTh[2304];
    __shared__ float sScore[256], sPo[256], sPd[256], st2[512];
    __shared__ float sEnt[16], sRed[8];
    __shared__ int   sSel[4];
    int bt = blockIdx.x, tid = threadIdx.x;
    const float* Mp = M + (size_t)bt * 4096;
    for (int o = tid; o < 4096; o += 256) sM[o] = Mp[o];
    for (int o = tid; o < 2304; o += 256) sTh[o] = theta[o];
    __syncthreads();
    {
        int i = tid >> 4, n = tid & 15;
        const float* xr = sM + i * 256;
        float a = g_bos2[n];
        for (int kf = 0; kf < 256; kf++) a += xr[kf] * g_Wos2[kf*16+n];
        sScore[tid] = a;
    }
    __syncthreads();
    if (tid < 16) {
        float mx = -1e30f;
        #pragma unroll
        for (int n = 0; n < 16; n++) mx = fmaxf(mx, sScore[tid*16+n]);
        float e[16], s = 0.f;
        #pragma unroll
        for (int n = 0; n < 16; n++) { e[n] = expf(sScore[tid*16+n]-mx); s += e[n]; }
        float inv = 1.f/s, ent = 0.f;
        #pragma unroll
        for (int n = 0; n < 16; n++) { float p = e[n]*inv; sPo[tid*16+n]=p; ent -= p*logf(p+1e-9f); }
        sEnt[tid] = ent;
    }
    __syncthreads();
    if (tid == 0) {
        int i0 = 0;
        for (int t = 1; t < 16; t++) if (sEnt[t] < sEnt[i0]) i0 = t;
        int i1 = (i0 == 0) ? 1 : 0;
        for (int t = 0; t < 16; t++) { if (t == i0) continue; if (sEnt[t] < sEnt[i1]) i1 = t; }
        sSel[0] = i0; sSel[1] = i1;
    }
    {
        int k = tid >> 4, n = tid & 15;
        float a = g_bds2[n];
        for (int jf = 0; jf < 256; jf++)
            a += sM[(jf>>4)*256 + k*16 + (jf&15)] * g_Wds2[jf*16+n];
        __syncthreads();
        sScore[tid] = a;
    }
    __syncthreads();
    if (tid < 16) {
        float mx = -1e30f;
        #pragma unroll
        for (int n = 0; n < 16; n++) mx = fmaxf(mx, sScore[tid*16+n]);
        float e[16], s = 0.f;
        #pragma unroll
        for (int n = 0; n < 16; n++) { e[n] = expf(sScore[tid*16+n]-mx); s += e[n]; }
        float inv = 1.f/s, ent = 0.f;
        #pragma unroll
        for (int n = 0; n < 16; n++) { float p = e[n]*inv; sPd[tid*16+n]=p; ent -= p*logf(p+1e-9f); }
        sEnt[tid] = ent;
    }
    __syncthreads();
    if (tid == 0) {
        int i0 = 0;
        for (int t = 1; t < 16; t++) if (sEnt[t] < sEnt[i0]) i0 = t;
        int i1 = (i0 == 0) ? 1 : 0;
        for (int t = 0; t < 16; t++) { if (t == i0) continue; if (sEnt[t] < sEnt[i1]) i1 = t; }
        sSel[2] = i0; sSel[3] = i1;
    }
    __syncthreads();
    {
        #pragma unroll
        for (int s = 0; s < 2; s++) {
            int ii = sSel[s];
            float a = 0.f;
            for (int j = 0; j < 16; j++) a += sPo[ii*16+j] * sM[j*256 + tid];
            st2[s*256 + tid] = a;
        }
    }
    __syncthreads();
    int gi = tid & 15, gl = tid >> 4;
    float MG[16];
    #pragma unroll
    for (int g = 0; g < 16; g++) MG[g] = 0.f;
    for (int c = 0; c < 3; c++) {
        for (int r = 0; r < 16; r++) {
            int ll = tid >> 4, f = tid & 15;
            float a = 0.f;
            #pragma unroll
            for (int k = 0; k < 16; k++)
                a += sM[(r<<8)+(k<<4)+f] * g_Td[c*256 + (k<<4) + ll];
            sR[(r<<8) + tid] = a;
        }
        __syncthreads();
        for (int a_ = 0; a_ < 3; a_++) {
            float S[16];
            #pragma unroll
            for (int f = 0; f < 16; f++) S[f] = 0.f;
            for (int j = 0; j < 16; j++) {
                float t_ = g_To[a_*256 + (gi<<4) + j];
                const float* rp = sR + (j<<8) + (gl<<4);
                #pragma unroll
                for (int f = 0; f < 16; f++) S[f] += t_ * rp[f];
            }
            const float* th = sTh + (a_*3 + c) * 256;
            #pragma unroll
            for (int f = 0; f < 16; f++) {
                float sv = S[f];
                #pragma unroll
                for (int g = 0; g < 16; g++) MG[g] += sv * th[f*16+g];
            }
        }
        __syncthreads();
    }
    int so = (gi == sSel[0]) ? 0 : ((gi == sSel[1]) ? 1 : -1);
    int sd = (gl == sSel[2]) ? 0 : ((gl == sSel[3]) ? 1 : -1);
    float v[16];
    float lsum = 0.f, lsq = 0.f;
    #pragma unroll
    for (int g = 0; g < 16; g++) {
        float w = 0.5f * MG[g];
        if (so >= 0 && sd >= 0) {
            float ma = 0.f;
            #pragma unroll
            for (int ll = 0; ll < 16; ll++)
                ma += st2[so*256 + g*16 + ll] * sPd[gl*16 + ll];
            w += 0.5f * ma;
        }
        v[g] = w;
        lsum += w;
        lsq += w * w;
    }
    float tot = blockReduceSum(lsum, sRed);
    float sqt = blockReduceSum(lsq, sRed);
    float mu = tot * (1.0f/4096.0f);
    float var = sqt * (1.0f/4096.0f) - mu * mu;
    float rstd = rsqrtf(var + 1e-5f);
    size_t base = (size_t)bt*4096 + gi*256 + gl*16;
    float* xp = g_x + base;
    __half* xh = g_xn16 + base;
    #pragma unroll
    for (int g = 0; g < 16; g++) {
        xp[g] = v[g];
        float xn = (v[g] - mu) * rstd * g1[gi*256 + gl*16 + g] + be1[gi*256 + gl*16 + g];
        xh[g] = __float2half(xn);
    }
    if (tid == 0) g_xm[bt] = mu;
}

__global__ void period_kernel() {
    __shared__ float sx[168], sd[168], sac[168];
    __shared__ float smean;
    int b = blockIdx.x, tid = threadIdx.x;
    if (tid < 168) sx[tid] = g_xm[b*168 + tid];
    __syncthreads();
    if (tid < 168) {
        float s = 0.f;
        #pragma unroll
        for (int o = -12; o <= 12; o++) {
            int u = tid + o; u = u < 0 ? 0 : (u > 167 ? 167 : u);
            s += sx[u];
        }
        sd[tid] = sx[tid] - s * (1.0f/25.0f);
    }
    __syncthreads();
    if (tid == 0) {
        float s = 0.f;
        for (int t = 0; t < 168; t++) s += sd[t];
        smean = s / 168.0f;
    }
    __syncthreads();
    if (tid < 168) sd[tid] -= smean;
    __syncthreads();
    if (tid < 168) {
        float a = 0.f;
        for (int t = 0; t + tid < 168; t++) a += sd[t] * sd[t + tid];
        sac[tid] = (tid < 2) ? -1e9f : a;
    }
    __syncthreads();
    if (tid == 0) {
        bool used[168];
        for (int t = 0; t < 168; t++) used[t] = false;
        for (int r = 0; r < 4; r++) {
            int bi = 0; float bv = -1e30f;
            for (int t = 0; t < 168; t++)
                if (!used[t] && sac[t] > bv) { bv = sac[t]; bi = t; }
            used[bi] = true;
            g_periods[b*4 + r] = bi;
        }
    }
}

// LayerNorm2: fp32 in -> fp16 out
__global__ void __launch_bounds__(256) ln_kernel(const float* __restrict__ x,
                                                 const float* __restrict__ gw,
                                                 const float* __restrict__ bw,
                                                 __half* __restrict__ o16) {
    __shared__ float srow[DD];
    __shared__ float red[8];
    int row = blockIdx.x, tid = threadIdx.x;
    const float* xp = x + (size_t)row * DD;
    float s = 0.f;
    for (int o = tid; o < DD; o += 256) { float v = xp[o]; srow[o] = v; s += v; }
    s = blockReduceSum(s, red);
    float mu = s * (1.0f/DD);
    float vs = 0.f;
    for (int o = tid; o < DD; o += 256) { float d = srow[o]-mu; vs += d*d; }
    vs = blockReduceSum(vs, red);
    float rstd = rsqrtf(vs * (1.0f/DD) + 1e-5f);
    __half* op = o16 + (size_t)row * DD;
    for (int o = tid; o < DD; o += 256)
        op[o] = __float2half((srow[o]-mu) * rstd * gw[o] + bw[o]);
}

// ---------------- period-sparse attention, float4, fp16 out ----------------
__global__ void __launch_bounds__(256) attn_kernel() {
    __shared__ float4 sq4[256];
    __shared__ float sc[168];
    __shared__ float red[8];
    int i = blockIdx.x, h = blockIdx.y, b = blockIdx.z;
    int tid = threadIdx.x;
    int p = g_periods[b*4 + h]; if (p < 1) p = 1;
    int nm = i/p + 1;
    size_t qb = ((size_t)(b*TT + i))*DD + h*HDIM;
    sq4[tid] = ((const float4*)(g_q + qb))[tid];
    __syncthreads();
    int w = tid >> 5, lane = tid & 31;
    for (int m = w; m < nm; m += 8) {
        int j = i - m*p;
        const float4* kp4 = (const float4*)(g_k + ((size_t)(b*TT + j))*DD + h*HDIM);
        float s = 0.f;
        for (int d = lane; d < 256; d += 32) {
            float4 a = sq4[d], bb = kp4[d];
            s += a.x*bb.x + a.y*bb.y + a.z*bb.z + a.w*bb.w;
        }
        #pragma unroll
        for (int o = 16; o > 0; o >>= 1) s += __shfl_xor_sync(0xffffffffu, s, o);
        if (lane == 0) sc[m] = s * 0.03125f;
    }
    __syncthreads();
    float mx = -1e30f;
    for (int m = tid; m < nm; m += 256) mx = fmaxf(mx, sc[m]);
    #pragma unroll
    for (int o = 16; o > 0; o >>= 1) mx = fmaxf(mx, __shfl_xor_sync(0xffffffffu, mx, o));
    if (lane == 0) red[w] = mx;
    __syncthreads();
    if (tid < 32) {
        float t = (tid < 8) ? red[tid] : -1e30f;
        #pragma unroll
        for (int o = 4; o > 0; o >>= 1) t = fmaxf(t, __shfl_xor_sync(0xffffffffu, t, o));
        if (tid == 0) red[0] = t;
    }
    __syncthreads();
    mx = red[0];
    __syncthreads();
    float sum = 0.f;
    for (int m = tid; m < nm; m += 256) { float e = expf(sc[m]-mx); sc[m] = e; sum += e; }
    sum = blockReduceSum(sum, red);
    float inv = 1.0f/sum;
    float4 av = make_float4(0.f, 0.f, 0.f, 0.f);
    for (int m = 0; m < nm; m++) {
        int j = i - m*p;
        float4 vv = ((const float4*)(g_v + ((size_t)(b*TT + j))*DD + h*HDIM))[tid];
        float wgt = sc[m];
        av.x += wgt*vv.x; av.y += wgt*vv.y; av.z += wgt*vv.z; av.w += wgt*vv.w;
    }
    av.x *= inv; av.y *= inv; av.z *= inv; av.w *= inv;
    __half h0 = __float2half(av.x), h1 = __float2half(av.y);
    __half h2 = __float2half(av.z), h3 = __float2half(av.w);
    uint2 u2;
    u2.x = ((uint32_t)__half_as_ushort(h1) << 16) | __half_as_ushort(h0);
    u2.y = ((uint32_t)__half_as_ushort(h3) << 16) | __half_as_ushort(h2);
    *(uint2*)(g_ao16 + qb + (size_t)tid * 4) = u2;
}

__global__ void periods_out_kernel(float* dst) {
    int t = threadIdx.x;
    if (t < 16) dst[t] = (float)g_periods[t];
}

// ---------------- launch ----------------
extern "C" void kernel_launch(void* const* d_in, const int* in_sizes, int n_in,
                              void* d_out, int out_size) {
    const float* M     = (const float*)d_in[0];
    const float* L_o   = (const float*)d_in[1];
    const float* L_d   = (const float*)d_in[2];
    const float* theta = (const float*)d_in[3];
    const float* Wop   = (const float*)d_in[4];
    const float* bop   = (const float*)d_in[5];
    const float* Wdp   = (const float*)d_in[6];
    const float* bdp   = (const float*)d_in[7];
    const float* Wos   = (const float*)d_in[8];
    const float* bos   = (const float*)d_in[9];
    const float* Wds   = (const float*)d_in[10];
    const float* bds   = (const float*)d_in[11];
    const float* Wq    = (const float*)d_in[12];
    const float* bq    = (const float*)d_in[13];
    const float* Wk    = (const float*)d_in[14];
    const float* bk    = (const float*)d_in[15];
    const float* Wv    = (const float*)d_in[16];
    const float* bv    = (const float*)d_in[17];
    const float* Wo    = (const float*)d_in[18];
    const float* bo    = (const float*)d_in[19];
    const float* W1    = (const float*)d_in[20];
    const float* b1    = (const float*)d_in[21];
    const float* W2    = (const float*)d_in[22];
    const float* b2    = (const float*)d_in[23];
    const float* g1    = (const float*)d_in[24];
    const float* be1   = (const float*)d_in[25];
    const float* g2    = (const float*)d_in[26];
    const float* be2   = (const float*)d_in[27];
    float* out = (float*)d_out;

    float *p_x, *p_q, *p_k, *p_v;
    __half *p_w16, *p_xn16, *p_ao16, *p_y16, *p_f16;
    cudaGetSymbolAddress((void**)&p_x,   g_x);
    cudaGetSymbolAddress((void**)&p_q,   g_q);
    cudaGetSymbolAddress((void**)&p_k,   g_k);
    cudaGetSymbolAddress((void**)&p_v,   g_v);
    cudaGetSymbolAddress((void**)&p_w16, g_w16);
    cudaGetSymbolAddress((void**)&p_xn16,g_xn16);
    cudaGetSymbolAddress((void**)&p_ao16,g_ao16);
    cudaGetSymbolAddress((void**)&p_y16, g_y16);
    cudaGetSymbolAddress((void**)&p_f16, g_f16);

    cudaFuncSetAttribute(gemm_fp16,     cudaFuncAttributeMaxDynamicSharedMemorySize, H_SMEM);
    cudaFuncSetAttribute(gemm_fp16_qkv, cudaFuncAttributeMaxDynamicSharedMemorySize, H_SMEM);

    convert_all_kernel<<<49152, 256>>>(Wq, Wk, Wv, Wo, W1, W2, 0);               // 1
    convert_all_kernel<<<49152, 256>>>(Wq, Wk, Wv, Wo, W1, W2, 49152);           // 2
    prep_kernel<<<128, 256>>>(L_o, L_d, Wop, bop, Wos, bos, Wdp, bdp, Wds, bds); // 3
    gcnod_kernel<<<BT, 256>>>(M, theta, g1, be1);                                // 4 <- ncu slot
    gemm_fp16_qkv<<<dim3(6, 32, 3), 256, H_SMEM>>>(p_xn16, p_w16,
                                                   bq, bk, bv, p_q, p_k, p_v);   // 5
    period_kernel<<<BB, 192>>>();                                                // 6
    dim3 gA(TT, HH, BB);
    attn_kernel<<<gA, 256>>>();                                                  // 7

    gemm_fp16<<<dim3(6, 32), 256, H_SMEM>>>(p_ao16, p_w16 + OFFO, bo, p_x,
                                            p_x, (__half*)0, BT, DD, DD, 1);
    ln_kernel<<<BT, 256>>>(p_x, g2, be2, p_y16);
    gemm_fp16<<<dim3(6, 128), 256, H_SMEM>>>(p_y16, p_w16 + OFFH1, b1, (const float*)0,
                                             (float*)0, p_f16, BT, DFF, DD, 2);
    gemm_fp16<<<dim3(6, 32), 256, H_SMEM>>>(p_f16, p_w16 + OFFH2, b2, p_x,
                                            out, (__half*)0, BT, DD, DFF, 1);

    if (out_size >= BT*DD + 16) {
        periods_out_kernel<<<1, 32>>>(out + (size_t)BT*DD);
    }
}

// round 17
// speedup vs baseline: 3.4655x; 1.0157x over previous
#include <cuda_runtime.h>
#include <cuda_fp16.h>
#include <mma.h>
#include <cstdint>
#include <math.h>

using namespace nvcuda;

#define BB 4
#define TT 168
#define BT 672
#define DD 4096
#define HH 4
#define HDIM 1024
#define DFF 16384

#define OFFQ  0ul
#define OFFK  16777216ul
#define OFFV  33554432ul
#define OFFO  50331648ul
#define OFFH1 67108864ul
#define OFFH2 134217728ul
#define WELEM 201326592ul

__device__ __half g_w16[WELEM];

__device__ float g_To[768], g_Td[768];
__device__ float g_Wos2[4096], g_Wds2[4096], g_bos2[16], g_bds2[16];
__device__ float g_x[BT * DD];
__device__ float g_xm[BT];
__device__ int   g_periods[BB * HH];
__device__ __half g_q16[BT * DD], g_k16[BT * DD], g_v16[BT * DD];
__device__ __half g_xn16[BT * DD];
__device__ __half g_ao16[BT * DD];
__device__ __half g_y16[BT * DD];
__device__ __half g_f16[(size_t)BT * DFF];

__device__ __forceinline__ float blockReduceSum(float v, float* red) {
    int tid = threadIdx.x;
    #pragma unroll
    for (int o = 16; o > 0; o >>= 1) v += __shfl_xor_sync(0xffffffffu, v, o);
    if ((tid & 31) == 0) red[tid >> 5] = v;
    __syncthreads();
    if (tid < 32) {
        float t = (tid < 8) ? red[tid] : 0.0f;
        #pragma unroll
        for (int o = 4; o > 0; o >>= 1) t += __shfl_xor_sync(0xffffffffu, t, o);
        if (tid == 0) red[0] = t;
    }
    __syncthreads();
    float r = red[0];
    __syncthreads();
    return r;
}

__device__ __forceinline__ void cpa16(uint32_t dst, const void* src, int srcsz) {
    asm volatile("cp.async.cg.shared.global [%0], [%1], 16, %2;"
                 :: "r"(dst), "l"(src), "r"(srcsz) : "memory");
}
__device__ __forceinline__ void cpa_commit() { asm volatile("cp.async.commit_group;" ::: "memory"); }
template<int N>
__device__ __forceinline__ void cpa_wait() { asm volatile("cp.async.wait_group %0;" :: "n"(N) : "memory"); }

// ---------------- weight convert: streaming fp32 -> fp16, 2 launches ----------------
__global__ void __launch_bounds__(256) convert_all_kernel(
    const float* __restrict__ Wq, const float* __restrict__ Wk,
    const float* __restrict__ Wv, const float* __restrict__ Wo,
    const float* __restrict__ W1, const float* __restrict__ W2,
    int blk0)
{
    size_t idx = ((size_t)(blockIdx.x + blk0) * 256 + threadIdx.x) * 8;
    if (idx >= WELEM) return;
    const float* src;
    size_t base;
    if      (idx < OFFK)  { src = Wq; base = OFFQ;  }
    else if (idx < OFFV)  { src = Wk; base = OFFK;  }
    else if (idx < OFFO)  { src = Wv; base = OFFV;  }
    else if (idx < OFFH1) { src = Wo; base = OFFO;  }
    else if (idx < OFFH2) { src = W1; base = OFFH1; }
    else                  { src = W2; base = OFFH2; }
    const float* p = src + (idx - base);
    float4 a = *(const float4*)p;
    float4 b = *(const float4*)(p + 4);
    uint4 o;
    uint32_t* oo = (uint32_t*)&o;
    __half h0 = __float2half(a.x), h1 = __float2half(a.y);
    __half h2 = __float2half(a.z), h3 = __float2half(a.w);
    __half h4 = __float2half(b.x), h5 = __float2half(b.y);
    __half h6 = __float2half(b.z), h7 = __float2half(b.w);
    oo[0] = ((uint32_t)__half_as_ushort(h1) << 16) | __half_as_ushort(h0);
    oo[1] = ((uint32_t)__half_as_ushort(h3) << 16) | __half_as_ushort(h2);
    oo[2] = ((uint32_t)__half_as_ushort(h5) << 16) | __half_as_ushort(h4);
    oo[3] = ((uint32_t)__half_as_ushort(h7) << 16) | __half_as_ushort(h6);
    *(uint4*)(g_w16 + idx) = o;
}

// ---------------- fp16 GEMM, tile 128x128, K-chunk 64, B row-major [K,N] ----------------
#define PADA 72
#define PADB 136
#define H_A  0
#define H_Bo (128 * PADA)
#define H_STAGE (128 * PADA + 64 * PADB)
#define H_BYT (H_STAGE * 2)
#define H_SMEM (2 * H_BYT)

__device__ __forceinline__ void issue_stage_h(
    uint32_t sb, const __half* __restrict__ A, const __half* __restrict__ B,
    int bm, int bn, int k0, int K, int Nc, int Mr, int tid)
{
    #pragma unroll
    for (int t = 0; t < 4; t++) {
        int u = tid + t * 256;
        int row = u >> 3, q = u & 7;
        int m = bm + row;
        int ok = (m < Mr) ? 16 : 0;
        size_t g = (size_t)(m < Mr ? m : 0) * K + k0 + q * 8;
        cpa16(sb + (H_A + row * PADA + q * 8) * 2, A + g, ok);
    }
    #pragma unroll
    for (int t = 0; t < 4; t++) {
        int u = tid + t * 256;
        int row = u >> 4, q = u & 15;
        size_t g = (size_t)(k0 + row) * Nc + bn + q * 8;
        cpa16(sb + (H_Bo + row * PADB + q * 8) * 2, B + g, 16);
    }
}

// EPI: 0 = bias -> fp32 ; 1 = bias+res -> fp32 ; 2 = gelu(bias) -> fp16 ; 3 = bias -> fp16
__device__ __forceinline__ void gemm_h_body(
    const __half* __restrict__ A, const __half* __restrict__ B,
    const float* __restrict__ bias, const float* __restrict__ res,
    float* __restrict__ C, __half* __restrict__ Ch,
    int Mr, int Nc, int K, int EPI)
{
    extern __shared__ char dsm[];
    uint32_t sbase = (uint32_t)__cvta_generic_to_shared(dsm);
    __half* sm = (__half*)dsm;

    int tid = threadIdx.x, wid = tid >> 5, lane = tid & 31;
    int bm = blockIdx.x * 128, bn = blockIdx.y * 128;
    int wm = (wid >> 2) * 64, wn = (wid & 3) * 32;

    wmma::fragment<wmma::accumulator, 16, 16, 16, float> acc[4][2];
    #pragma unroll
    for (int i = 0; i < 4; i++)
        #pragma unroll
        for (int j = 0; j < 2; j++) wmma::fill_fragment(acc[i][j], 0.0f);

    int KC = K >> 6;
    issue_stage_h(sbase, A, B, bm, bn, 0, K, Nc, Mr, tid);
    cpa_commit();

    for (int kc = 0; kc < KC; kc++) {
        int cur = kc & 1;
        if (kc + 1 < KC) {
            issue_stage_h(sbase + ((kc + 1) & 1) * H_BYT, A, B, bm, bn, (kc + 1) * 64, K, Nc, Mr, tid);
            cpa_commit();
            cpa_wait<1>();
        } else {
            cpa_wait<0>();
        }
        __syncthreads();
        const __half* S = sm + cur * H_STAGE;
        #pragma unroll
        for (int kk = 0; kk < 64; kk += 16) {
            wmma::fragment<wmma::matrix_b, 16, 16, 16, __half, wmma::row_major> fb[2];
            #pragma unroll
            for (int j = 0; j < 2; j++)
                wmma::load_matrix_sync(fb[j], S + H_Bo + kk * PADB + wn + 16 * j, PADB);
            #pragma unroll
            for (int i = 0; i < 4; i++) {
                wmma::fragment<wmma::matrix_a, 16, 16, 16, __half, wmma::row_major> fa;
                wmma::load_matrix_sync(fa, S + H_A + (wm + 16 * i) * PADA + kk, PADA);
                #pragma unroll
                for (int j = 0; j < 2; j++)
                    wmma::mma_sync(acc[i][j], fa, fb[j], acc[i][j]);
            }
        }
        __syncthreads();
    }

    float* fst = (float*)dsm + wid * 256;
    int r = lane >> 1, cs = (lane & 1) * 8;
    #pragma unroll
    for (int i = 0; i < 4; i++)
        #pragma unroll
        for (int j = 0; j < 2; j++) {
            wmma::store_matrix_sync(fst, acc[i][j], 16, wmma::mem_row_major);
            __syncwarp();
            int m = bm + wm + 16 * i + r;
            int col0 = bn + wn + 16 * j + cs;
            if (m < Mr) {
                float v[8];
                #pragma unroll
                for (int c = 0; c < 8; c++) v[c] = fst[r * 16 + cs + c] + bias[col0 + c];
                if (EPI >= 2) {
                    uint4 p;
                    uint32_t* pp = (uint32_t*)&p;
                    #pragma unroll
                    for (int c = 0; c < 4; c++) {
                        float a0 = v[2*c], a1 = v[2*c+1];
                        if (EPI == 2) {
                            a0 = 0.5f * a0 * (1.0f + erff(a0 * 0.7071067811865475f));
                            a1 = 0.5f * a1 * (1.0f + erff(a1 * 0.7071067811865475f));
                        }
                        __half h0 = __float2half(a0), h1 = __float2half(a1);
                        pp[c] = ((uint32_t)__half_as_ushort(h1) << 16) | __half_as_ushort(h0);
                    }
                    *(uint4*)(Ch + (size_t)m * Nc + col0) = p;
                } else {
                    if (EPI == 1) {
                        const float* rp = res + (size_t)m * Nc + col0;
                        #pragma unroll
                        for (int c = 0; c < 8; c++) v[c] += rp[c];
                    }
                    float4 o0, o1;
                    o0.x = v[0]; o0.y = v[1]; o0.z = v[2]; o0.w = v[3];
                    o1.x = v[4]; o1.y = v[5]; o1.z = v[6]; o1.w = v[7];
                    *(float4*)(C + (size_t)m * Nc + col0) = o0;
                    *(float4*)(C + (size_t)m * Nc + col0 + 4) = o1;
                }
            }
            __syncwarp();
        }
}

__global__ void __launch_bounds__(256, 2) gemm_fp16(
    const __half* A, const __half* B,
    const float* bias, const float* res,
    float* C, __half* Ch, int Mr, int Nc, int K, int EPI)
{
    gemm_h_body(A, B, bias, res, C, Ch, Mr, Nc, K, EPI);
}

__global__ void __launch_bounds__(256, 2) gemm_fp16_qkv(
    const __half* A, const __half* w16,
    const float* bq, const float* bk, const float* bv,
    __half* q, __half* k, __half* v)
{
    int z = blockIdx.z;
    size_t off = (size_t)z * 16777216ul;
    const float* bias = (z == 0) ? bq : (z == 1) ? bk : bv;
    __half* C = (z == 0) ? q : (z == 1) ? k : v;
    gemm_h_body(A, w16 + off, bias, (const float*)0, (float*)0, C, BT, DD, DD, 3);
}

// ---------------- prep: full-chip ----------------
__global__ void __launch_bounds__(256) prep_kernel(
    const float* __restrict__ Lo, const float* __restrict__ Ld,
    const float* __restrict__ Wop, const float* __restrict__ bop,
    const float* __restrict__ Wos, const float* __restrict__ bos,
    const float* __restrict__ Wdp, const float* __restrict__ bdp,
    const float* __restrict__ Wds, const float* __restrict__ bds)
{
    int tid = threadIdx.x;
    if (blockIdx.x == 0 && tid < 256) {
        int i = tid >> 4, j = tid & 15;
        float id = (i == j) ? 1.0f : 0.0f;
        float a = 0.f, b = 0.f;
        for (int k = 0; k < 16; k++) { a += Lo[i*16+k]*Lo[k*16+j]; b += Ld[i*16+k]*Ld[k*16+j]; }
        g_To[tid] = id; g_To[256+tid] = Lo[tid]; g_To[512+tid] = 2.f*a - id;
        g_Td[tid] = id; g_Td[256+tid] = Ld[tid]; g_Td[512+tid] = 2.f*b - id;
    }
    int ent = blockIdx.x * 32 + (tid >> 3);
    int sub = tid & 7;
    int kf = ent >> 4, n = ent & 15;
    float a = 0.f, b = 0.f;
    for (int h = sub * 64; h < sub * 64 + 64; h++) {
        a += Wop[kf*512+h] * Wos[h*16+n];
        b += Wdp[kf*512+h] * Wds[h*16+n];
    }
    #pragma unroll
    for (int o = 4; o > 0; o >>= 1) {
        a += __shfl_down_sync(0xffffffffu, a, o);
        b += __shfl_down_sync(0xffffffffu, b, o);
    }
    if (sub == 0) { g_Wos2[ent] = a; g_Wds2[ent] = b; }
    if (blockIdx.x == 1 && tid < 16) {
        float c = bos[tid], d = bds[tid];
        for (int h = 0; h < 512; h++) { c += bop[h]*Wos[h*16+tid]; d += bdp[h]*Wds[h*16+tid]; }
        g_bos2[tid] = c; g_bds2[tid] = d;
    }
}

// ---------------- GCN + OD + combine + fused LN1, LDS-optimized ----------------
__global__ void __launch_bounds__(256) gcnod_kernel(const float* __restrict__ M,
                                                    const float* __restrict__ theta,
                                                    const float* __restrict__ g1,
                                                    const float* __restrict__ be1) {
    __shared__ float sM[4096], sR[4096], sTh[2304];
    __shared__ float sTo[768], sTd[768];
    __shared__ float sScore[256], sPo[256], sPd[256], st2[512];
    __shared__ float sEnt[16], sRed[8];
    __shared__ int   sSel[4];
    int bt = blockIdx.x, tid = threadIdx.x;
    const float* Mp = M + (size_t)bt * 4096;
    for (int o = tid; o < 4096; o += 256) sM[o] = Mp[o];
    for (int o = tid; o < 2304; o += 256) sTh[o] = theta[o];
    for (int o = tid; o < 768; o += 256) { sTo[o] = g_To[o]; sTd[o] = g_Td[o]; }
    __syncthreads();
    { // origin scores (float4 on sM)
        int i = tid >> 4, n = tid & 15;
        const float4* xr4 = (const float4*)(sM + i * 256);
        float a = g_bos2[n];
        for (int k4 = 0; k4 < 64; k4++) {
            float4 x = xr4[k4];
            int kf = k4 * 4;
            a += x.x * g_Wos2[kf*16+n] + x.y * g_Wos2[(kf+1)*16+n]
               + x.z * g_Wos2[(kf+2)*16+n] + x.w * g_Wos2[(kf+3)*16+n];
        }
        sScore[tid] = a;
    }
    __syncthreads();
    if (tid < 16) {
        float mx = -1e30f;
        #pragma unroll
        for (int n = 0; n < 16; n++) mx = fmaxf(mx, sScore[tid*16+n]);
        float e[16], s = 0.f;
        #pragma unroll
        for (int n = 0; n < 16; n++) { e[n] = expf(sScore[tid*16+n]-mx); s += e[n]; }
        float inv = 1.f/s, ent = 0.f;
        #pragma unroll
        for (int n = 0; n < 16; n++) { float p = e[n]*inv; sPo[tid*16+n]=p; ent -= p*logf(p+1e-9f); }
        sEnt[tid] = ent;
    }
    __syncthreads();
    if (tid == 0) {
        int i0 = 0;
        for (int t = 1; t < 16; t++) if (sEnt[t] < sEnt[i0]) i0 = t;
        int i1 = (i0 == 0) ? 1 : 0;
        for (int t = 0; t < 16; t++) { if (t == i0) continue; if (sEnt[t] < sEnt[i1]) i1 = t; }
        sSel[0] = i0; sSel[1] = i1;
    }
    { // dest scores
        int k = tid >> 4, n = tid & 15;
        float a = g_bds2[n];
        for (int jf = 0; jf < 256; jf++)
            a += sM[(jf>>4)*256 + k*16 + (jf&15)] * g_Wds2[jf*16+n];
        __syncthreads();
        sScore[tid] = a;
    }
    __syncthreads();
    if (tid < 16) {
        float mx = -1e30f;
        #pragma unroll
        for (int n = 0; n < 16; n++) mx = fmaxf(mx, sScore[tid*16+n]);
        float e[16], s = 0.f;
        #pragma unroll
        for (int n = 0; n < 16; n++) { e[n] = expf(sScore[tid*16+n]-mx); s += e[n]; }
        float inv = 1.f/s, ent = 0.f;
        #pragma unroll
        for (int n = 0; n < 16; n++) { float p = e[n]*inv; sPd[tid*16+n]=p; ent -= p*logf(p+1e-9f); }
        sEnt[tid] = ent;
    }
    __syncthreads();
    if (tid == 0) {
        int i0 = 0;
        for (int t = 1; t < 16; t++) if (sEnt[t] < sEnt[i0]) i0 = t;
        int i1 = (i0 == 0) ? 1 : 0;
        for (int t = 0; t < 16; t++) { if (t == i0) continue; if (sEnt[t] < sEnt[i1]) i1 = t; }
        sSel[2] = i0; sSel[3] = i1;
    }
    __syncthreads();
    {
        #pragma unroll
        for (int s = 0; s < 2; s++) {
            int ii = sSel[s];
            float a = 0.f;
            for (int j = 0; j < 16; j++) a += sPo[ii*16+j] * sM[j*256 + tid];
            st2[s*256 + tid] = a;
        }
    }
    __syncthreads();
    int gi = tid & 15, gl = tid >> 4;
    float MG[16];
    #pragma unroll
    for (int g = 0; g < 16; g++) MG[g] = 0.f;

    for (int c = 0; c < 3; c++) {
        // R[j][l][f]: thread owns (j = tid>>4, f = tid&15), all l in registers
        {
            int j = tid >> 4, f = tid & 15;
            float Rl[16];
            #pragma unroll
            for (int l = 0; l < 16; l++) Rl[l] = 0.f;
            #pragma unroll
            for (int k = 0; k < 16; k++) {
                float mv = sM[(j<<8) + (k<<4) + f];
                const float4* td4 = (const float4*)(sTd + c*256 + (k<<4));
                #pragma unroll
                for (int l4 = 0; l4 < 4; l4++) {
                    float4 t = td4[l4];
                    Rl[l4*4+0] += mv * t.x;
                    Rl[l4*4+1] += mv * t.y;
                    Rl[l4*4+2] += mv * t.z;
                    Rl[l4*4+3] += mv * t.w;
                }
            }
            #pragma unroll
            for (int l = 0; l < 16; l++)
                sR[(j<<8) + (l<<4) + f] = Rl[l];
        }
        __syncthreads();
        for (int a_ = 0; a_ < 3; a_++) {
            float S[16];
            #pragma unroll
            for (int f = 0; f < 16; f++) S[f] = 0.f;
            for (int j = 0; j < 16; j++) {
                float t_ = sTo[a_*256 + (gi<<4) + j];
                const float4* rp4 = (const float4*)(sR + (j<<8) + (gl<<4));
                #pragma unroll
                for (int f4 = 0; f4 < 4; f4++) {
                    float4 r = rp4[f4];
                    S[f4*4+0] += t_ * r.x;
                    S[f4*4+1] += t_ * r.y;
                    S[f4*4+2] += t_ * r.z;
                    S[f4*4+3] += t_ * r.w;
                }
            }
            const float* th = sTh + (a_*3 + c) * 256;
            #pragma unroll
            for (int f = 0; f < 16; f++) {
                float sv = S[f];
                #pragma unroll
                for (int g = 0; g < 16; g++) MG[g] += sv * th[f*16+g];
            }
        }
        __syncthreads();
    }
    int so = (gi == sSel[0]) ? 0 : ((gi == sSel[1]) ? 1 : -1);
    int sd = (gl == sSel[2]) ? 0 : ((gl == sSel[3]) ? 1 : -1);
    float v[16];
    float lsum = 0.f, lsq = 0.f;
    #pragma unroll
    for (int g = 0; g < 16; g++) {
        float w = 0.5f * MG[g];
        if (so >= 0 && sd >= 0) {
            float ma = 0.f;
            #pragma unroll
            for (int ll = 0; ll < 16; ll++)
                ma += st2[so*256 + g*16 + ll] * sPd[gl*16 + ll];
            w += 0.5f * ma;
        }
        v[g] = w;
        lsum += w;
        lsq += w * w;
    }
    float tot = blockReduceSum(lsum, sRed);
    float sqt = blockReduceSum(lsq, sRed);
    float mu = tot * (1.0f/4096.0f);
    float var = sqt * (1.0f/4096.0f) - mu * mu;
    float rstd = rsqrtf(var + 1e-5f);
    size_t base = (size_t)bt*4096 + gi*256 + gl*16;
    float* xp = g_x + base;
    __half* xh = g_xn16 + base;
    #pragma unroll
    for (int g = 0; g < 16; g++) {
        xp[g] = v[g];
        float xn = (v[g] - mu) * rstd * g1[gi*256 + gl*16 + g] + be1[gi*256 + gl*16 + g];
        xh[g] = __float2half(xn);
    }
    if (tid == 0) g_xm[bt] = mu;
}

__global__ void period_kernel() {
    __shared__ float sx[168], sd[168], sac[168];
    __shared__ float smean;
    int b = blockIdx.x, tid = threadIdx.x;
    if (tid < 168) sx[tid] = g_xm[b*168 + tid];
    __syncthreads();
    if (tid < 168) {
        float s = 0.f;
        #pragma unroll
        for (int o = -12; o <= 12; o++) {
            int u = tid + o; u = u < 0 ? 0 : (u > 167 ? 167 : u);
            s += sx[u];
        }
        sd[tid] = sx[tid] - s * (1.0f/25.0f);
    }
    __syncthreads();
    if (tid == 0) {
        float s = 0.f;
        for (int t = 0; t < 168; t++) s += sd[t];
        smean = s / 168.0f;
    }
    __syncthreads();
    if (tid < 168) sd[tid] -= smean;
    __syncthreads();
    if (tid < 168) {
        float a = 0.f;
        for (int t = 0; t + tid < 168; t++) a += sd[t] * sd[t + tid];
        sac[tid] = (tid < 2) ? -1e9f : a;
    }
    __syncthreads();
    if (tid == 0) {
        bool used[168];
        for (int t = 0; t < 168; t++) used[t] = false;
        for (int r = 0; r < 4; r++) {
            int bi = 0; float bv = -1e30f;
            for (int t = 0; t < 168; t++)
                if (!used[t] && sac[t] > bv) { bv = sac[t]; bi = t; }
            used[bi] = true;
            g_periods[b*4 + r] = bi;
        }
    }
}

// LayerNorm2: fp32 in -> fp16 out
__global__ void __launch_bounds__(256) ln_kernel(const float* __restrict__ x,
                                                 const float* __restrict__ gw,
                                                 const float* __restrict__ bw,
                                                 __half* __restrict__ o16) {
    __shared__ float srow[DD];
    __shared__ float red[8];
    int row = blockIdx.x, tid = threadIdx.x;
    const float* xp = x + (size_t)row * DD;
    float s = 0.f;
    for (int o = tid; o < DD; o += 256) { float v = xp[o]; srow[o] = v; s += v; }
    s = blockReduceSum(s, red);
    float mu = s * (1.0f/DD);
    float vs = 0.f;
    for (int o = tid; o < DD; o += 256) { float d = srow[o]-mu; vs += d*d; }
    vs = blockReduceSum(vs, red);
    float rstd = rsqrtf(vs * (1.0f/DD) + 1e-5f);
    __half* op = o16 + (size_t)row * DD;
    for (int o = tid; o < DD; o += 256)
        op[o] = __float2half((srow[o]-mu) * rstd * gw[o] + bw[o]);
}

// ---------------- period-sparse attention, fp16 q/k/v ----------------
__global__ void __launch_bounds__(256) attn_kernel() {
    __shared__ float sq[HDIM];
    __shared__ float sc[168];
    __shared__ float red[8];
    int i = blockIdx.x, h = blockIdx.y, b = blockIdx.z;
    int tid = threadIdx.x;
    int p = g_periods[b*4 + h]; if (p < 1) p = 1;
    int nm = i/p + 1;
    size_t qb = ((size_t)(b*TT + i))*DD + h*HDIM;
    {   // load q row: 4 halves per thread
        uint2 u = *(const uint2*)(g_q16 + qb + (size_t)tid * 4);
        __half2 p0 = *(__half2*)&u.x, p1 = *(__half2*)&u.y;
        float2 f0 = __half22float2(p0), f1 = __half22float2(p1);
        sq[tid*4+0] = f0.x; sq[tid*4+1] = f0.y;
        sq[tid*4+2] = f1.x; sq[tid*4+3] = f1.y;
    }
    __syncthreads();
    int w = tid >> 5, lane = tid & 31;
    for (int m = w; m < nm; m += 8) {
        int j = i - m*p;
        const __half* kp = g_k16 + ((size_t)(b*TT + j))*DD + h*HDIM;
        float s = 0.f;
        #pragma unroll
        for (int t = 0; t < 4; t++) {
            int d0 = (lane + t * 32) * 8;
            uint4 u = *(const uint4*)(kp + d0);
            const __half2* hp = (const __half2*)&u;
            #pragma unroll
            for (int c = 0; c < 4; c++) {
                float2 kf = __half22float2(hp[c]);
                s += sq[d0 + c*2] * kf.x + sq[d0 + c*2 + 1] * kf.y;
            }
        }
        #pragma unroll
        for (int o = 16; o > 0; o >>= 1) s += __shfl_xor_sync(0xffffffffu, s, o);
        if (lane == 0) sc[m] = s * 0.03125f;
    }
    __syncthreads();
    float mx = -1e30f;
    for (int m = tid; m < nm; m += 256) mx = fmaxf(mx, sc[m]);
    #pragma unroll
    for (int o = 16; o > 0; o >>= 1) mx = fmaxf(mx, __shfl_xor_sync(0xffffffffu, mx, o));
    if (lane == 0) red[w] = mx;
    __syncthreads();
    if (tid < 32) {
        float t = (tid < 8) ? red[tid] : -1e30f;
        #pragma unroll
        for (int o = 4; o > 0; o >>= 1) t = fmaxf(t, __shfl_xor_sync(0xffffffffu, t, o));
        if (tid == 0) red[0] = t;
    }
    __syncthreads();
    mx = red[0];
    __syncthreads();
    float sum = 0.f;
    for (int m = tid; m < nm; m += 256) { float e = expf(sc[m]-mx); sc[m] = e; sum += e; }
    sum = blockReduceSum(sum, red);
    float inv = 1.0f/sum;
    float4 av = make_float4(0.f, 0.f, 0.f, 0.f);
    for (int m = 0; m < nm; m++) {
        int j = i - m*p;
        uint2 u = *(const uint2*)(g_v16 + ((size_t)(b*TT + j))*DD + h*HDIM + (size_t)tid * 4);
        __half2 p0 = *(__half2*)&u.x, p1 = *(__half2*)&u.y;
        float2 f0 = __half22float2(p0), f1 = __half22float2(p1);
        float wgt = sc[m];
        av.x += wgt*f0.x; av.y += wgt*f0.y; av.z += wgt*f1.x; av.w += wgt*f1.y;
    }
    av.x *= inv; av.y *= inv; av.z *= inv; av.w *= inv;
    __half h0 = __float2half(av.x), h1 = __float2half(av.y);
    __half h2 = __float2half(av.z), h3 = __float2half(av.w);
    uint2 u2;
    u2.x = ((uint32_t)__half_as_ushort(h1) << 16) | __half_as_ushort(h0);
    u2.y = ((uint32_t)__half_as_ushort(h3) << 16) | __half_as_ushort(h2);
    *(uint2*)(g_ao16 + qb + (size_t)tid * 4) = u2;
}

__global__ void periods_out_kernel(float* dst) {
    int t = threadIdx.x;
    if (t < 16) dst[t] = (float)g_periods[t];
}

// ---------------- launch ----------------
extern "C" void kernel_launch(void* const* d_in, const int* in_sizes, int n_in,
                              void* d_out, int out_size) {
    const float* M     = (const float*)d_in[0];
    const float* L_o   = (const float*)d_in[1];
    const float* L_d   = (const float*)d_in[2];
    const float* theta = (const float*)d_in[3];
    const float* Wop   = (const float*)d_in[4];
    const float* bop   = (const float*)d_in[5];
    const float* Wdp   = (const float*)d_in[6];
    const float* bdp   = (const float*)d_in[7];
    const float* Wos   = (const float*)d_in[8];
    const float* bos   = (const float*)d_in[9];
    const float* Wds   = (const float*)d_in[10];
    const float* bds   = (const float*)d_in[11];
    const float* Wq    = (const float*)d_in[12];
    const float* bq    = (const float*)d_in[13];
    const float* Wk    = (const float*)d_in[14];
    const float* bk    = (const float*)d_in[15];
    const float* Wv    = (const float*)d_in[16];
    const float* bv    = (const float*)d_in[17];
    const float* Wo    = (const float*)d_in[18];
    const float* bo    = (const float*)d_in[19];
    const float* W1    = (const float*)d_in[20];
    const float* b1    = (const float*)d_in[21];
    const float* W2    = (const float*)d_in[22];
    const float* b2    = (const float*)d_in[23];
    const float* g1    = (const float*)d_in[24];
    const float* be1   = (const float*)d_in[25];
    const float* g2    = (const float*)d_in[26];
    const float* be2   = (const float*)d_in[27];
    float* out = (float*)d_out;

    float *p_x;
    __half *p_w16, *p_xn16, *p_ao16, *p_y16, *p_f16, *p_q16, *p_k16, *p_v16;
    cudaGetSymbolAddress((void**)&p_x,   g_x);
    cudaGetSymbolAddress((void**)&p_w16, g_w16);
    cudaGetSymbolAddress((void**)&p_xn16,g_xn16);
    cudaGetSymbolAddress((void**)&p_ao16,g_ao16);
    cudaGetSymbolAddress((void**)&p_y16, g_y16);
    cudaGetSymbolAddress((void**)&p_f16, g_f16);
    cudaGetSymbolAddress((void**)&p_q16, g_q16);
    cudaGetSymbolAddress((void**)&p_k16, g_k16);
    cudaGetSymbolAddress((void**)&p_v16, g_v16);

    cudaFuncSetAttribute(gemm_fp16,     cudaFuncAttributeMaxDynamicSharedMemorySize, H_SMEM);
    cudaFuncSetAttribute(gemm_fp16_qkv, cudaFuncAttributeMaxDynamicSharedMemorySize, H_SMEM);

    convert_all_kernel<<<49152, 256>>>(Wq, Wk, Wv, Wo, W1, W2, 0);               // 1
    convert_all_kernel<<<49152, 256>>>(Wq, Wk, Wv, Wo, W1, W2, 49152);           // 2
    prep_kernel<<<128, 256>>>(L_o, L_d, Wop, bop, Wos, bos, Wdp, bdp, Wds, bds); // 3
    gcnod_kernel<<<BT, 256>>>(M, theta, g1, be1);                                // 4 <- ncu slot
    gemm_fp16_qkv<<<dim3(6, 32, 3), 256, H_SMEM>>>(p_xn16, p_w16,
                                                   bq, bk, bv, p_q16, p_k16, p_v16); // 5
    period_kernel<<<BB, 192>>>();                                                // 6
    dim3 gA(TT, HH, BB);
    attn_kernel<<<gA, 256>>>();                                                  // 7

    gemm_fp16<<<dim3(6, 32), 256, H_SMEM>>>(p_ao16, p_w16 + OFFO, bo, p_x,
                                            p_x, (__half*)0, BT, DD, DD, 1);
    ln_kernel<<<BT, 256>>>(p_x, g2, be2, p_y16);
    gemm_fp16<<<dim3(6, 128), 256, H_SMEM>>>(p_y16, p_w16 + OFFH1, b1, (const float*)0,
                                             (float*)0, p_f16, BT, DFF, DD, 2);
    gemm_fp16<<<dim3(6, 32), 256, H_SMEM>>>(p_f16, p_w16 + OFFH2, b2, p_x,
                                            out, (__half*)0, BT, DD, DFF, 1);

    if (out_size >= BT*DD + 16) {
        periods_out_kernel<<<1, 32>>>(out + (size_t)BT*DD);
    }
}